// round 3
// baseline (speedup 1.0000x reference)
#include <cuda_runtime.h>
#include <math.h>

// Problem constants
#define Bn 16
#define Nn 1024      // 2^10
#define En 16384     // 2^14
#define Dn 256
constexpr int ME = Bn * En;   // 262144 edge rows
constexpr int MN = Bn * Nn;   // 16384 node rows

// ---------------- scratch (device globals: no allocation allowed) ----------
__device__ float g_buf1[(size_t)ME * Dn];  // hidden (edge layer1) / h2 (edge update layer1)
__device__ float g_msg [(size_t)ME * Dn];  // masked messages
__device__ float g_agg [(size_t)MN * Dn];  // segment sums
__device__ float g_hn  [(size_t)MN * Dn];  // node hidden
__device__ float g_node[(size_t)MN * Dn];  // pre-layernorm node
__device__ float g_cnt [MN];
__device__ float g_invc[MN];
__device__ int   g_dstrow[ME];
__device__ float g_maskf [ME];             // edge mask as float
__device__ float g_nmaskf[MN];             // node mask as float
__device__ int   g_mask_dt;                // 0=float32, 1=uint8, 2=int32

__device__ __forceinline__ float silu_f(float x) {
    return x / (1.0f + __expf(-x));
}

__device__ __forceinline__ float read_mask(const void* p, int i, int dt) {
    if (dt == 0) return ((const float*)p)[i];
    if (dt == 1) return ((const unsigned char*)p)[i] ? 1.0f : 0.0f;
    return ((const int*)p)[i] ? 1.0f : 0.0f;
}

// ---------------- mask dtype sniffer ----------------------------------------
// Inspect first 16 words of the edge mask buffer (>=64 bytes valid in all
// candidate dtypes since E >= 64).
__global__ void sniff_mask_dtype(const unsigned int* __restrict__ m) {
    bool big_byte = false;   // any byte >= 2  -> float32
    bool upper    = false;   // any byte 1..3 nonzero -> packed uint8
    for (int i = 0; i < 16; i++) {
        unsigned int w = m[i];
        unsigned char b0 = w & 0xff, b1 = (w >> 8) & 0xff,
                      b2 = (w >> 16) & 0xff, b3 = (w >> 24) & 0xff;
        if (b0 >= 2 || b1 >= 2 || b2 >= 2 || b3 >= 2) big_byte = true;
        if (b1 | b2 | b3) upper = true;
    }
    g_mask_dt = big_byte ? 0 : (upper ? 1 : 2);
}

// ---------------- small prep kernels ---------------------------------------
__global__ void zero_scratch() {
    int i = blockIdx.x * blockDim.x + threadIdx.x;
    if (i < MN * Dn) g_agg[i] = 0.0f;
    if (i < MN)      g_cnt[i] = 0.0f;
}

__global__ void prep_edges(const int* __restrict__ edge_index,
                           const void* __restrict__ edge_mask) {
    int r = blockIdx.x * blockDim.x + threadIdx.x;
    if (r >= ME) return;
    int dt = g_mask_dt;
    int b = r >> 14;            // /E
    int e = r & (En - 1);
    int dst = edge_index[(size_t)b * 2 * En + En + e];
    float m = (read_mask(edge_mask, r, dt) != 0.0f) ? 1.0f : 0.0f;
    g_dstrow[r] = b * Nn + dst;
    g_maskf[r]  = m;
    if (m != 0.0f) atomicAdd(&g_cnt[b * Nn + dst], 1.0f);
}

__global__ void prep_nodes(const void* __restrict__ node_mask) {
    int v = blockIdx.x * blockDim.x + threadIdx.x;
    if (v >= MN) return;
    g_invc[v]   = 1.0f / fmaxf(g_cnt[v], 1.0f);
    g_nmaskf[v] = (read_mask(node_mask, v, g_mask_dt) != 0.0f) ? 1.0f : 0.0f;
}

// ---------------- GEMM 1: gathered triplet, K=768, silu epilogue -----------
// C[r,n] = silu( sum_k [src|edge|dst](r,k) * W[k,n] + bias[n] )
__global__ void gemm_triplet(const float* __restrict__ node_feat,
                             const float* __restrict__ edge_feat,
                             const int*   __restrict__ edge_index,
                             const float* __restrict__ W,
                             const float* __restrict__ bias,
                             float* __restrict__ out) {
    __shared__ __align__(16) float As[16][68];
    __shared__ __align__(16) float Bs[16][68];
    __shared__ int s_src[64], s_dst[64];

    const int tid  = threadIdx.x;                 // 256 threads
    const int row0 = blockIdx.y * 64;
    const int col0 = blockIdx.x * 64;

    if (tid < 64) {
        int r = row0 + tid;
        int b = r >> 14;
        int e = r & (En - 1);
        s_src[tid] = b * Nn + edge_index[(size_t)b * 2 * En + e];
        s_dst[tid] = b * Nn + edge_index[(size_t)b * 2 * En + En + e];
    }
    __syncthreads();

    float acc[4][4] = {};
    const int ty = tid >> 4, tx = tid & 15;

    for (int k0 = 0; k0 < 768; k0 += 16) {
        #pragma unroll
        for (int i = 0; i < 4; i++) {
            int idx = tid + i * 256;
            int ar = idx >> 4, ak = idx & 15;
            int k = k0 + ak;
            float v;
            if (k < 256)      v = node_feat[(size_t)s_src[ar] * Dn + k];
            else if (k < 512) v = edge_feat[(size_t)(row0 + ar) * Dn + (k - 256)];
            else              v = node_feat[(size_t)s_dst[ar] * Dn + (k - 512)];
            As[ak][ar] = v;
        }
        #pragma unroll
        for (int i = 0; i < 4; i++) {
            int idx = tid + i * 256;
            int bk = idx >> 6, bn = idx & 63;
            Bs[bk][bn] = W[(size_t)(k0 + bk) * Dn + col0 + bn];
        }
        __syncthreads();
        #pragma unroll
        for (int kk = 0; kk < 16; kk++) {
            float4 av = *(const float4*)&As[kk][ty * 4];
            float4 bv = *(const float4*)&Bs[kk][tx * 4];
            float a[4] = {av.x, av.y, av.z, av.w};
            float b[4] = {bv.x, bv.y, bv.z, bv.w};
            #pragma unroll
            for (int i = 0; i < 4; i++)
                #pragma unroll
                for (int j = 0; j < 4; j++)
                    acc[i][j] += a[i] * b[j];
        }
        __syncthreads();
    }

    float4 bb = *(const float4*)&bias[col0 + tx * 4];
    #pragma unroll
    for (int i = 0; i < 4; i++) {
        int r = row0 + ty * 4 + i;
        float4 o;
        o.x = silu_f(acc[i][0] + bb.x);
        o.y = silu_f(acc[i][1] + bb.y);
        o.z = silu_f(acc[i][2] + bb.z);
        o.w = silu_f(acc[i][3] + bb.w);
        *(float4*)&out[(size_t)r * Dn + col0 + tx * 4] = o;
    }
}

// ---------------- generic K=256 GEMM with epilogue modes --------------------
// MODE 0: out = silu(A@W+b)                       (optionally row-scaled A)
// MODE 1: v = (A@W+b)*maskf[r]; out=v; atomicAdd into g_agg[dstrow[r]]
// MODE 2: out = residual + (A@W+b)
// MODE 3: out = residual + (A@W+b)*g_nmaskf[r]
template<int MODE, bool SCALE>
__global__ void gemm_k256(const float* __restrict__ A,
                          const float* __restrict__ W,
                          const float* __restrict__ bias,
                          const float* __restrict__ residual,
                          float* __restrict__ out) {
    __shared__ __align__(16) float As[16][68];
    __shared__ __align__(16) float Bs[16][68];
    __shared__ float s_scale[64];

    const int tid  = threadIdx.x;
    const int row0 = blockIdx.y * 64;
    const int col0 = blockIdx.x * 64;

    if (SCALE) {
        if (tid < 64) s_scale[tid] = g_invc[row0 + tid];
        __syncthreads();
    }

    float acc[4][4] = {};
    const int ty = tid >> 4, tx = tid & 15;

    for (int k0 = 0; k0 < 256; k0 += 16) {
        #pragma unroll
        for (int i = 0; i < 4; i++) {
            int idx = tid + i * 256;
            int ar = idx >> 4, ak = idx & 15;
            float v = A[(size_t)(row0 + ar) * Dn + k0 + ak];
            if (SCALE) v *= s_scale[ar];
            As[ak][ar] = v;
        }
        #pragma unroll
        for (int i = 0; i < 4; i++) {
            int idx = tid + i * 256;
            int bk = idx >> 6, bn = idx & 63;
            Bs[bk][bn] = W[(size_t)(k0 + bk) * Dn + col0 + bn];
        }
        __syncthreads();
        #pragma unroll
        for (int kk = 0; kk < 16; kk++) {
            float4 av = *(const float4*)&As[kk][ty * 4];
            float4 bv = *(const float4*)&Bs[kk][tx * 4];
            float a[4] = {av.x, av.y, av.z, av.w};
            float b[4] = {bv.x, bv.y, bv.z, bv.w};
            #pragma unroll
            for (int i = 0; i < 4; i++)
                #pragma unroll
                for (int j = 0; j < 4; j++)
                    acc[i][j] += a[i] * b[j];
        }
        __syncthreads();
    }

    float4 bb = *(const float4*)&bias[col0 + tx * 4];
    #pragma unroll
    for (int i = 0; i < 4; i++) {
        int r = row0 + ty * 4 + i;
        size_t off = (size_t)r * Dn + col0 + tx * 4;
        float v0 = acc[i][0] + bb.x;
        float v1 = acc[i][1] + bb.y;
        float v2 = acc[i][2] + bb.z;
        float v3 = acc[i][3] + bb.w;
        if (MODE == 0) {
            float4 o = {silu_f(v0), silu_f(v1), silu_f(v2), silu_f(v3)};
            *(float4*)&out[off] = o;
        } else if (MODE == 1) {
            float m = g_maskf[r];
            v0 *= m; v1 *= m; v2 *= m; v3 *= m;
            float4 o = {v0, v1, v2, v3};
            *(float4*)&out[off] = o;
            if (m != 0.0f) {
                float* ap = &g_agg[(size_t)g_dstrow[r] * Dn + col0 + tx * 4];
                atomicAdd(ap + 0, v0);
                atomicAdd(ap + 1, v1);
                atomicAdd(ap + 2, v2);
                atomicAdd(ap + 3, v3);
            }
        } else if (MODE == 2) {
            float4 rv = *(const float4*)&residual[off];
            float4 o = {rv.x + v0, rv.y + v1, rv.z + v2, rv.w + v3};
            *(float4*)&out[off] = o;
        } else {
            float m = g_nmaskf[r];
            float4 rv = *(const float4*)&residual[off];
            float4 o = {rv.x + v0 * m, rv.y + v1 * m, rv.z + v2 * m, rv.w + v3 * m};
            *(float4*)&out[off] = o;
        }
    }
}

// ---------------- layernorm over last dim (256) -----------------------------
__global__ void ln_kernel(const float* __restrict__ x,
                          const float* __restrict__ gamma,
                          const float* __restrict__ beta,
                          float* __restrict__ out) {
    int v = blockIdx.x, t = threadIdx.x;   // 256 threads
    float val = x[(size_t)v * Dn + t];
    float s = val, s2 = val * val;
    #pragma unroll
    for (int o = 16; o > 0; o >>= 1) {
        s  += __shfl_xor_sync(0xffffffffu, s,  o);
        s2 += __shfl_xor_sync(0xffffffffu, s2, o);
    }
    __shared__ float ws[8], ws2[8];
    int w = t >> 5;
    if ((t & 31) == 0) { ws[w] = s; ws2[w] = s2; }
    __syncthreads();
    if (t == 0) {
        float a = 0.0f, b = 0.0f;
        #pragma unroll
        for (int i = 0; i < 8; i++) { a += ws[i]; b += ws2[i]; }
        ws[0] = a; ws2[0] = b;
    }
    __syncthreads();
    float mean = ws[0] * (1.0f / 256.0f);
    float var  = ws2[0] * (1.0f / 256.0f) - mean * mean;
    out[(size_t)v * Dn + t] = (val - mean) * rsqrtf(var + 1e-5f) * gamma[t] + beta[t];
}

// ---------------- launch ----------------------------------------------------
extern "C" void kernel_launch(void* const* d_in, const int* in_sizes, int n_in,
                              void* d_out, int out_size) {
    const float* node_feat = (const float*)d_in[0];
    const float* edge_feat = (const float*)d_in[1];
    const int*   edge_index = (const int*)d_in[2];
    const void*  node_mask = d_in[3];
    const void*  edge_mask = d_in[4];
    const float* tw1 = (const float*)d_in[5];
    const float* tb1 = (const float*)d_in[6];
    const float* tw2 = (const float*)d_in[7];
    const float* tb2 = (const float*)d_in[8];
    const float* nw1 = (const float*)d_in[9];
    const float* nb1 = (const float*)d_in[10];
    const float* nw2 = (const float*)d_in[11];
    const float* nb2 = (const float*)d_in[12];
    const float* ew1 = (const float*)d_in[13];
    const float* eb1 = (const float*)d_in[14];
    const float* ew2 = (const float*)d_in[15];
    const float* eb2 = (const float*)d_in[16];
    const float* gamma = (const float*)d_in[17];
    const float* beta  = (const float*)d_in[18];

    float* out = (float*)d_out;

    float *hidden, *msg, *agg, *hn, *node;
    cudaGetSymbolAddress((void**)&hidden, g_buf1);
    cudaGetSymbolAddress((void**)&msg,    g_msg);
    cudaGetSymbolAddress((void**)&agg,    g_agg);
    cudaGetSymbolAddress((void**)&hn,     g_hn);
    cudaGetSymbolAddress((void**)&node,   g_node);

    // 0) detect mask dtype (bool may arrive as f32 / u8 / i32)
    sniff_mask_dtype<<<1, 1>>>((const unsigned int*)edge_mask);
    // 1) zero agg + counts
    zero_scratch<<<(MN * Dn) / 256, 256>>>();
    // 2) edge metadata (dst row, mask float, counts)
    prep_edges<<<ME / 256, 256>>>(edge_index, edge_mask);
    // 3) inverse counts + node mask float
    prep_nodes<<<MN / 256, 256>>>(node_mask);
    // 4) triplet layer1 (gather-GEMM K=768, silu)
    gemm_triplet<<<dim3(4, ME / 64), 256>>>(node_feat, edge_feat, edge_index, tw1, tb1, hidden);
    // 5) msg = layer2 * mask, scatter-add into agg
    gemm_k256<1, false><<<dim3(4, ME / 64), 256>>>(hidden, tw2, tb2, nullptr, msg);
    // 6) edge update layer1 (silu)
    gemm_k256<0, false><<<dim3(4, ME / 64), 256>>>(msg, ew1, eb1, nullptr, hidden);
    // 7) edge_out = edge_feat + layer2   -> second output section
    gemm_k256<2, false><<<dim3(4, ME / 64), 256>>>(hidden, ew2, eb2, edge_feat,
                                                   out + (size_t)MN * Dn);
    // 8) node layer1 on normalized agg (silu)
    gemm_k256<0, true ><<<dim3(4, MN / 64), 256>>>(agg, nw1, nb1, nullptr, hn);
    // 9) node = node_feat + layer2 * node_mask
    gemm_k256<3, false><<<dim3(4, MN / 64), 256>>>(hn, nw2, nb2, node_feat, node);
    // 10) layernorm -> out[0 : MN*Dn]
    ln_kernel<<<MN, 256>>>(node, gamma, beta, out);
}

// round 4
// speedup vs baseline: 1.4990x; 1.4990x over previous
#include <cuda_runtime.h>
#include <math.h>

// Problem constants
#define Bn 16
#define Nn 1024      // 2^10
#define En 16384     // 2^14
#define Dn 256
constexpr int ME = Bn * En;   // 262144 edge rows
constexpr int MN = Bn * Nn;   // 16384 node rows

// ---------------- scratch (device globals: no allocation allowed) ----------
__device__ float g_buf1[(size_t)ME * Dn];  // hidden (edge layer1) / h2 (edge update layer1)
__device__ float g_msg [(size_t)ME * Dn];  // masked messages
__device__ float g_agg [(size_t)MN * Dn];  // segment sums
__device__ float g_hn  [(size_t)MN * Dn];  // node hidden
__device__ float g_node[(size_t)MN * Dn];  // pre-layernorm node
__device__ float g_cnt [MN];
__device__ float g_invc[MN];
__device__ int   g_dstrow[ME];
__device__ float g_maskf [ME];             // edge mask as float
__device__ float g_nmaskf[MN];             // node mask as float
__device__ int   g_mask_dt;                // 0=float32, 1=uint8, 2=int32

__device__ __forceinline__ float silu_f(float x) {
    return x / (1.0f + __expf(-x));
}

__device__ __forceinline__ float read_mask(const void* p, int i, int dt) {
    if (dt == 0) return ((const float*)p)[i];
    if (dt == 1) return ((const unsigned char*)p)[i] ? 1.0f : 0.0f;
    return ((const int*)p)[i] ? 1.0f : 0.0f;
}

// ---------------- mask dtype sniffer ----------------------------------------
__global__ void sniff_mask_dtype(const unsigned int* __restrict__ m) {
    bool big_byte = false;   // any byte >= 2  -> float32
    bool upper    = false;   // any byte 1..3 nonzero -> packed uint8
    for (int i = 0; i < 16; i++) {
        unsigned int w = m[i];
        unsigned char b0 = w & 0xff, b1 = (w >> 8) & 0xff,
                      b2 = (w >> 16) & 0xff, b3 = (w >> 24) & 0xff;
        if (b0 >= 2 || b1 >= 2 || b2 >= 2 || b3 >= 2) big_byte = true;
        if (b1 | b2 | b3) upper = true;
    }
    g_mask_dt = big_byte ? 0 : (upper ? 1 : 2);
}

// ---------------- small prep kernels ---------------------------------------
__global__ void prep_edges(const int* __restrict__ edge_index,
                           const void* __restrict__ edge_mask) {
    int r = blockIdx.x * blockDim.x + threadIdx.x;
    if (r >= ME) return;
    int dt = g_mask_dt;
    int b = r >> 14;            // /E
    int e = r & (En - 1);
    int dst = edge_index[(size_t)b * 2 * En + En + e];
    float m = (read_mask(edge_mask, r, dt) != 0.0f) ? 1.0f : 0.0f;
    g_dstrow[r] = b * Nn + dst;
    g_maskf[r]  = m;
    if (m != 0.0f) atomicAdd(&g_cnt[b * Nn + dst], 1.0f);
}

__global__ void prep_nodes(const void* __restrict__ node_mask) {
    int v = blockIdx.x * blockDim.x + threadIdx.x;
    if (v >= MN) return;
    g_invc[v]   = 1.0f / fmaxf(g_cnt[v], 1.0f);
    g_nmaskf[v] = (read_mask(node_mask, v, g_mask_dt) != 0.0f) ? 1.0f : 0.0f;
}

// ============================================================================
// 128x128 tile GEMM machinery: 256 threads, 8x8 per thread, double-buffered
// smem (one __syncthreads per 16-k tile), register prefetch.
//
// Thread map: ty = tid>>4 (0..15), tx = tid&15.
// Rows covered: {ty*4 .. ty*4+3} and {64+ty*4 .. 64+ty*4+3}
// Cols covered: {tx*4 .. tx*4+3} and {64+tx*4 .. 64+tx*4+3}
// ============================================================================

#define PITCH 132

struct Acc88 {
    float a[8][8];
};

__device__ __forceinline__ void ffma_tile(const float (*As)[PITCH],
                                          const float (*Bs)[PITCH],
                                          int ty, int tx, Acc88& acc) {
    #pragma unroll
    for (int kk = 0; kk < 16; kk++) {
        float4 a0 = *(const float4*)&As[kk][ty * 4];
        float4 a1 = *(const float4*)&As[kk][64 + ty * 4];
        float4 b0 = *(const float4*)&Bs[kk][tx * 4];
        float4 b1 = *(const float4*)&Bs[kk][64 + tx * 4];
        float av[8] = {a0.x, a0.y, a0.z, a0.w, a1.x, a1.y, a1.z, a1.w};
        float bv[8] = {b0.x, b0.y, b0.z, b0.w, b1.x, b1.y, b1.z, b1.w};
        #pragma unroll
        for (int i = 0; i < 8; i++)
            #pragma unroll
            for (int j = 0; j < 8; j++)
                acc.a[i][j] += av[i] * bv[j];
    }
}

__device__ __forceinline__ void sts_a(float (*As)[PITCH], int idx, float4 v) {
    int ar = idx >> 2;              // 0..127
    int ks = (idx & 3) * 4;         // 0,4,8,12
    As[ks + 0][ar] = v.x;
    As[ks + 1][ar] = v.y;
    As[ks + 2][ar] = v.z;
    As[ks + 3][ar] = v.w;
}

__device__ __forceinline__ void sts_b(float (*Bs)[PITCH], int idx, float4 v) {
    int bk = idx >> 5;              // 0..15
    int bn = (idx & 31) * 4;        // 0..124
    *(float4*)&Bs[bk][bn] = v;
}

// ---------------- GEMM 1: gathered triplet, K=768, silu epilogue -----------
__global__ void __launch_bounds__(256, 2)
gemm_triplet(const float* __restrict__ node_feat,
             const float* __restrict__ edge_feat,
             const int*   __restrict__ edge_index,
             const float* __restrict__ W,
             const float* __restrict__ bias,
             float* __restrict__ out) {
    __shared__ __align__(16) float As[2][16][PITCH];
    __shared__ __align__(16) float Bs[2][16][PITCH];
    __shared__ int s_src[128], s_dst[128];

    const int tid  = threadIdx.x;
    const int row0 = blockIdx.y * 128;
    const int col0 = blockIdx.x * 128;
    const int ty = tid >> 4, tx = tid & 15;

    if (tid < 128) {
        int r = row0 + tid;
        int b = r >> 14;
        int e = r & (En - 1);
        s_src[tid] = b * Nn + edge_index[(size_t)b * 2 * En + e];
        s_dst[tid] = b * Nn + edge_index[(size_t)b * 2 * En + En + e];
    }
    __syncthreads();

    float4 pa[2], pb[2];

    auto ldg_tile = [&](int k0) {
        #pragma unroll
        for (int i = 0; i < 2; i++) {
            int idx = tid + i * 256;
            int ar = idx >> 2;
            int k = k0 + (idx & 3) * 4;
            const float* src; size_t off;
            if (k < 256)      { src = node_feat; off = (size_t)s_src[ar] * Dn + k; }
            else if (k < 512) { src = edge_feat; off = (size_t)(row0 + ar) * Dn + (k - 256); }
            else              { src = node_feat; off = (size_t)s_dst[ar] * Dn + (k - 512); }
            pa[i] = *(const float4*)&src[off];
        }
        #pragma unroll
        for (int i = 0; i < 2; i++) {
            int idx = tid + i * 256;
            int bk = idx >> 5, bn = (idx & 31) * 4;
            pb[i] = *(const float4*)&W[(size_t)(k0 + bk) * Dn + col0 + bn];
        }
    };

    Acc88 acc = {};
    const int nT = 768 / 16;

    ldg_tile(0);
    sts_a(As[0], tid, pa[0]); sts_a(As[0], tid + 256, pa[1]);
    sts_b(Bs[0], tid, pb[0]); sts_b(Bs[0], tid + 256, pb[1]);
    __syncthreads();

    int buf = 0;
    for (int t = 0; t < nT; t++) {
        if (t + 1 < nT) ldg_tile((t + 1) * 16);
        ffma_tile(As[buf], Bs[buf], ty, tx, acc);
        if (t + 1 < nT) {
            sts_a(As[buf ^ 1], tid, pa[0]); sts_a(As[buf ^ 1], tid + 256, pa[1]);
            sts_b(Bs[buf ^ 1], tid, pb[0]); sts_b(Bs[buf ^ 1], tid + 256, pb[1]);
            __syncthreads();
            buf ^= 1;
        }
    }

    float4 bb0 = *(const float4*)&bias[col0 + tx * 4];
    float4 bb1 = *(const float4*)&bias[col0 + 64 + tx * 4];
    float bbv[8] = {bb0.x, bb0.y, bb0.z, bb0.w, bb1.x, bb1.y, bb1.z, bb1.w};
    #pragma unroll
    for (int i = 0; i < 8; i++) {
        int r = row0 + ((i < 4) ? (ty * 4 + i) : (64 + ty * 4 + i - 4));
        float4 o0, o1;
        o0.x = silu_f(acc.a[i][0] + bbv[0]);
        o0.y = silu_f(acc.a[i][1] + bbv[1]);
        o0.z = silu_f(acc.a[i][2] + bbv[2]);
        o0.w = silu_f(acc.a[i][3] + bbv[3]);
        o1.x = silu_f(acc.a[i][4] + bbv[4]);
        o1.y = silu_f(acc.a[i][5] + bbv[5]);
        o1.z = silu_f(acc.a[i][6] + bbv[6]);
        o1.w = silu_f(acc.a[i][7] + bbv[7]);
        *(float4*)&out[(size_t)r * Dn + col0 + tx * 4]      = o0;
        *(float4*)&out[(size_t)r * Dn + col0 + 64 + tx * 4] = o1;
    }
}

// ---------------- generic K=256 GEMM with epilogue modes --------------------
// MODE 0: out = silu(A@W+b)               (optionally row-scaled A via g_invc)
// MODE 1: v = (A@W+b)*maskf[r]; out=v; atomicAdd into g_agg[dstrow[r]]
// MODE 2: out = residual + (A@W+b)
// MODE 3: out = residual + (A@W+b)*g_nmaskf[r]
template<int MODE, bool SCALE>
__global__ void __launch_bounds__(256, 2)
gemm_k256(const float* __restrict__ A,
          const float* __restrict__ W,
          const float* __restrict__ bias,
          const float* __restrict__ residual,
          float* __restrict__ out) {
    __shared__ __align__(16) float As[2][16][PITCH];
    __shared__ __align__(16) float Bs[2][16][PITCH];
    __shared__ float s_scale[128];

    const int tid  = threadIdx.x;
    const int row0 = blockIdx.y * 128;
    const int col0 = blockIdx.x * 128;
    const int ty = tid >> 4, tx = tid & 15;

    if (SCALE) {
        if (tid < 128) s_scale[tid] = g_invc[row0 + tid];
        __syncthreads();
    }

    float4 pa[2], pb[2];

    auto ldg_tile = [&](int k0) {
        #pragma unroll
        for (int i = 0; i < 2; i++) {
            int idx = tid + i * 256;
            int ar = idx >> 2;
            int k = k0 + (idx & 3) * 4;
            float4 v = *(const float4*)&A[(size_t)(row0 + ar) * Dn + k];
            if (SCALE) {
                float s = s_scale[ar];
                v.x *= s; v.y *= s; v.z *= s; v.w *= s;
            }
            pa[i] = v;
        }
        #pragma unroll
        for (int i = 0; i < 2; i++) {
            int idx = tid + i * 256;
            int bk = idx >> 5, bn = (idx & 31) * 4;
            pb[i] = *(const float4*)&W[(size_t)(k0 + bk) * Dn + col0 + bn];
        }
    };

    Acc88 acc = {};
    const int nT = 256 / 16;

    ldg_tile(0);
    sts_a(As[0], tid, pa[0]); sts_a(As[0], tid + 256, pa[1]);
    sts_b(Bs[0], tid, pb[0]); sts_b(Bs[0], tid + 256, pb[1]);
    __syncthreads();

    int buf = 0;
    for (int t = 0; t < nT; t++) {
        if (t + 1 < nT) ldg_tile((t + 1) * 16);
        ffma_tile(As[buf], Bs[buf], ty, tx, acc);
        if (t + 1 < nT) {
            sts_a(As[buf ^ 1], tid, pa[0]); sts_a(As[buf ^ 1], tid + 256, pa[1]);
            sts_b(Bs[buf ^ 1], tid, pb[0]); sts_b(Bs[buf ^ 1], tid + 256, pb[1]);
            __syncthreads();
            buf ^= 1;
        }
    }

    float4 bb0 = *(const float4*)&bias[col0 + tx * 4];
    float4 bb1 = *(const float4*)&bias[col0 + 64 + tx * 4];
    float bbv[8] = {bb0.x, bb0.y, bb0.z, bb0.w, bb1.x, bb1.y, bb1.z, bb1.w};
    #pragma unroll
    for (int i = 0; i < 8; i++) {
        int r = row0 + ((i < 4) ? (ty * 4 + i) : (64 + ty * 4 + i - 4));
        size_t off0 = (size_t)r * Dn + col0 + tx * 4;
        size_t off1 = off0 + 64;
        float v[8];
        #pragma unroll
        for (int j = 0; j < 8; j++) v[j] = acc.a[i][j] + bbv[j];

        if (MODE == 0) {
            float4 o0 = {silu_f(v[0]), silu_f(v[1]), silu_f(v[2]), silu_f(v[3])};
            float4 o1 = {silu_f(v[4]), silu_f(v[5]), silu_f(v[6]), silu_f(v[7])};
            *(float4*)&out[off0] = o0;
            *(float4*)&out[off1] = o1;
        } else if (MODE == 1) {
            float m = g_maskf[r];
            #pragma unroll
            for (int j = 0; j < 8; j++) v[j] *= m;
            float4 o0 = {v[0], v[1], v[2], v[3]};
            float4 o1 = {v[4], v[5], v[6], v[7]};
            *(float4*)&out[off0] = o0;
            *(float4*)&out[off1] = o1;
            if (m != 0.0f) {
                float* ap0 = &g_agg[(size_t)g_dstrow[r] * Dn + col0 + tx * 4];
                float* ap1 = ap0 + 64;
                atomicAdd(ap0 + 0, v[0]); atomicAdd(ap0 + 1, v[1]);
                atomicAdd(ap0 + 2, v[2]); atomicAdd(ap0 + 3, v[3]);
                atomicAdd(ap1 + 0, v[4]); atomicAdd(ap1 + 1, v[5]);
                atomicAdd(ap1 + 2, v[6]); atomicAdd(ap1 + 3, v[7]);
            }
        } else if (MODE == 2) {
            float4 r0 = *(const float4*)&residual[off0];
            float4 r1 = *(const float4*)&residual[off1];
            float4 o0 = {r0.x + v[0], r0.y + v[1], r0.z + v[2], r0.w + v[3]};
            float4 o1 = {r1.x + v[4], r1.y + v[5], r1.z + v[6], r1.w + v[7]};
            *(float4*)&out[off0] = o0;
            *(float4*)&out[off1] = o1;
        } else {
            float m = g_nmaskf[r];
            float4 r0 = *(const float4*)&residual[off0];
            float4 r1 = *(const float4*)&residual[off1];
            float4 o0 = {r0.x + v[0] * m, r0.y + v[1] * m, r0.z + v[2] * m, r0.w + v[3] * m};
            float4 o1 = {r1.x + v[4] * m, r1.y + v[5] * m, r1.z + v[6] * m, r1.w + v[7] * m};
            *(float4*)&out[off0] = o0;
            *(float4*)&out[off1] = o1;
        }
    }
}

// ---------------- layernorm over last dim (256) -----------------------------
__global__ void ln_kernel(const float* __restrict__ x,
                          const float* __restrict__ gamma,
                          const float* __restrict__ beta,
                          float* __restrict__ out) {
    int v = blockIdx.x, t = threadIdx.x;   // 256 threads
    float val = x[(size_t)v * Dn + t];
    float s = val, s2 = val * val;
    #pragma unroll
    for (int o = 16; o > 0; o >>= 1) {
        s  += __shfl_xor_sync(0xffffffffu, s,  o);
        s2 += __shfl_xor_sync(0xffffffffu, s2, o);
    }
    __shared__ float ws[8], ws2[8];
    int w = t >> 5;
    if ((t & 31) == 0) { ws[w] = s; ws2[w] = s2; }
    __syncthreads();
    if (t == 0) {
        float a = 0.0f, b = 0.0f;
        #pragma unroll
        for (int i = 0; i < 8; i++) { a += ws[i]; b += ws2[i]; }
        ws[0] = a; ws2[0] = b;
    }
    __syncthreads();
    float mean = ws[0] * (1.0f / 256.0f);
    float var  = ws2[0] * (1.0f / 256.0f) - mean * mean;
    out[(size_t)v * Dn + t] = (val - mean) * rsqrtf(var + 1e-5f) * gamma[t] + beta[t];
}

// ---------------- launch ----------------------------------------------------
extern "C" void kernel_launch(void* const* d_in, const int* in_sizes, int n_in,
                              void* d_out, int out_size) {
    const float* node_feat = (const float*)d_in[0];
    const float* edge_feat = (const float*)d_in[1];
    const int*   edge_index = (const int*)d_in[2];
    const void*  node_mask = d_in[3];
    const void*  edge_mask = d_in[4];
    const float* tw1 = (const float*)d_in[5];
    const float* tb1 = (const float*)d_in[6];
    const float* tw2 = (const float*)d_in[7];
    const float* tb2 = (const float*)d_in[8];
    const float* nw1 = (const float*)d_in[9];
    const float* nb1 = (const float*)d_in[10];
    const float* nw2 = (const float*)d_in[11];
    const float* nb2 = (const float*)d_in[12];
    const float* ew1 = (const float*)d_in[13];
    const float* eb1 = (const float*)d_in[14];
    const float* ew2 = (const float*)d_in[15];
    const float* eb2 = (const float*)d_in[16];
    const float* gamma = (const float*)d_in[17];
    const float* beta  = (const float*)d_in[18];

    float* out = (float*)d_out;

    float *hidden, *msg, *agg, *hn, *node, *cnt;
    cudaGetSymbolAddress((void**)&hidden, g_buf1);
    cudaGetSymbolAddress((void**)&msg,    g_msg);
    cudaGetSymbolAddress((void**)&agg,    g_agg);
    cudaGetSymbolAddress((void**)&hn,     g_hn);
    cudaGetSymbolAddress((void**)&node,   g_node);
    cudaGetSymbolAddress((void**)&cnt,    g_cnt);

    // 0) detect mask dtype (bool may arrive as f32 / u8 / i32)
    sniff_mask_dtype<<<1, 1>>>((const unsigned int*)edge_mask);
    // 1) zero agg + counts (async memset is graph-capturable and alloc-free)
    cudaMemsetAsync(agg, 0, (size_t)MN * Dn * sizeof(float));
    cudaMemsetAsync(cnt, 0, (size_t)MN * sizeof(float));
    // 2) edge metadata (dst row, mask float, counts)
    prep_edges<<<ME / 256, 256>>>(edge_index, edge_mask);
    // 3) inverse counts + node mask float
    prep_nodes<<<MN / 256, 256>>>(node_mask);
    // 4) triplet layer1 (gather-GEMM K=768, silu)
    gemm_triplet<<<dim3(2, ME / 128), 256>>>(node_feat, edge_feat, edge_index, tw1, tb1, hidden);
    // 5) msg = layer2 * mask, scatter-add into agg
    gemm_k256<1, false><<<dim3(2, ME / 128), 256>>>(hidden, tw2, tb2, nullptr, msg);
    // 6) edge update layer1 (silu)
    gemm_k256<0, false><<<dim3(2, ME / 128), 256>>>(msg, ew1, eb1, nullptr, hidden);
    // 7) edge_out = edge_feat + layer2   -> second output section
    gemm_k256<2, false><<<dim3(2, ME / 128), 256>>>(hidden, ew2, eb2, edge_feat,
                                                    out + (size_t)MN * Dn);
    // 8) node layer1 on normalized agg (silu)
    gemm_k256<0, true ><<<dim3(2, MN / 128), 256>>>(agg, nw1, nb1, nullptr, hn);
    // 9) node = node_feat + layer2 * node_mask
    gemm_k256<3, false><<<dim3(2, MN / 128), 256>>>(hn, nw2, nb2, node_feat, node);
    // 10) layernorm -> out[0 : MN*Dn]
    ln_kernel<<<MN, 256>>>(node, gamma, beta, out);
}

// round 6
// speedup vs baseline: 2.6330x; 1.7566x over previous
#include <cuda_runtime.h>
#include <cuda_bf16.h>
#include <cstdint>
#include <math.h>

// Problem constants
#define Bn 16
#define Nn 1024
#define En 16384
#define Dn 256
constexpr int ME = Bn * En;   // 262144 edge rows
constexpr int MN = Bn * Nn;   // 16384 node rows

// ============================ PTX helpers (sm_80-compatible only) ===========
__device__ __forceinline__ uint32_t smem_u32(const void* p) {
    uint32_t a;
    asm("{ .reg .u64 t; cvta.to.shared.u64 t, %1; cvt.u32.u64 %0, t; }"
        : "=r"(a) : "l"(p));
    return a;
}

#define LDSM4(r, addr) \
    asm volatile("ldmatrix.sync.aligned.m8n8.x4.shared.b16 {%0,%1,%2,%3}, [%4];" \
        : "=r"((r)[0]), "=r"((r)[1]), "=r"((r)[2]), "=r"((r)[3]) : "r"(addr))

#define MMA_BF16(d, a, b) \
    asm volatile("mma.sync.aligned.m16n8k16.row.col.f32.bf16.bf16.f32 " \
        "{%0,%1,%2,%3}, {%4,%5,%6,%7}, {%8,%9}, {%0,%1,%2,%3};" \
        : "+f"((d)[0]), "+f"((d)[1]), "+f"((d)[2]), "+f"((d)[3]) \
        : "r"((a)[0]), "r"((a)[1]), "r"((a)[2]), "r"((a)[3]), \
          "r"((b)[0]), "r"((b)[1]))

#define CP_ASYNC16(dst, src) \
    asm volatile("cp.async.cg.shared.global [%0], [%1], 16;" :: "r"(dst), "l"(src))
#define CP_COMMIT asm volatile("cp.async.commit_group;" ::: "memory")
#define CP_WAIT0  asm volatile("cp.async.wait_group 0;" ::: "memory")

#define SW128(x) ((x) ^ (((x) >> 3) & 0x70))

// ============================ scratch globals ================================
__device__ float g_buf1[(size_t)ME * Dn];
__device__ float g_msg [(size_t)ME * Dn];
__device__ float g_agg [(size_t)MN * Dn];
__device__ float g_hn  [(size_t)MN * Dn];
__device__ float g_node[(size_t)MN * Dn];
__device__ float g_cnt [MN];
__device__ float g_invc[MN];
__device__ int   g_dstrow[ME];
__device__ float g_maskf [ME];
__device__ float g_nmaskf[MN];
__device__ int   g_mask_dt;
// pre-transposed + bf16-split weights: [N=256][K] row-major
__device__ __nv_bfloat16 g_wth[524288];
__device__ __nv_bfloat16 g_wtl[524288];
constexpr size_t OW_TW1 = 0, OW_TW2 = 196608, OW_EW1 = 262144,
                 OW_EW2 = 327680, OW_NW1 = 393216, OW_NW2 = 458752;

__device__ __forceinline__ float silu_f(float x) { return x / (1.0f + __expf(-x)); }

__device__ __forceinline__ float read_mask(const void* p, int i, int dt) {
    if (dt == 0) return ((const float*)p)[i];
    if (dt == 1) return ((const unsigned char*)p)[i] ? 1.0f : 0.0f;
    return ((const int*)p)[i] ? 1.0f : 0.0f;
}

// ---------------- small prep kernels ----------------------------------------
__global__ void sniff_mask_dtype(const unsigned int* __restrict__ m) {
    bool big_byte = false, upper = false;
    for (int i = 0; i < 16; i++) {
        unsigned int w = m[i];
        unsigned char b0 = w & 0xff, b1 = (w >> 8) & 0xff,
                      b2 = (w >> 16) & 0xff, b3 = (w >> 24) & 0xff;
        if (b0 >= 2 || b1 >= 2 || b2 >= 2 || b3 >= 2) big_byte = true;
        if (b1 | b2 | b3) upper = true;
    }
    g_mask_dt = big_byte ? 0 : (upper ? 1 : 2);
}

__global__ void prep_edges(const int* __restrict__ edge_index,
                           const void* __restrict__ edge_mask) {
    int r = blockIdx.x * blockDim.x + threadIdx.x;
    if (r >= ME) return;
    int dt = g_mask_dt;
    int b = r >> 14;
    int e = r & (En - 1);
    int dst = edge_index[(size_t)b * 2 * En + En + e];
    float m = (read_mask(edge_mask, r, dt) != 0.0f) ? 1.0f : 0.0f;
    g_dstrow[r] = b * Nn + dst;
    g_maskf[r]  = m;
    if (m != 0.0f) atomicAdd(&g_cnt[b * Nn + dst], 1.0f);
}

__global__ void prep_nodes(const void* __restrict__ node_mask) {
    int v = blockIdx.x * blockDim.x + threadIdx.x;
    if (v >= MN) return;
    g_invc[v]   = 1.0f / fmaxf(g_cnt[v], 1.0f);
    g_nmaskf[v] = (read_mask(node_mask, v, g_mask_dt) != 0.0f) ? 1.0f : 0.0f;
}

// transpose + split W[K,256] fp32 -> WT_hi/lo [256,K] bf16
__global__ void prep_weights(const float* __restrict__ W, int K,
                             __nv_bfloat16* __restrict__ wth,
                             __nv_bfloat16* __restrict__ wtl) {
    int i = blockIdx.x * blockDim.x + threadIdx.x;
    if (i >= K * 256) return;
    int k = i >> 8, n = i & 255;
    float v = W[i];
    __nv_bfloat16 h = __float2bfloat16_rn(v);
    wth[(size_t)n * K + k] = h;
    wtl[(size_t)n * K + k] = __float2bfloat16_rn(v - __bfloat162float(h));
}

// ============================ tensor-core GEMM (mma.sync) ====================
// out[M,256] = A[M,KTOT] @ W[KTOT,256] via bf16x3 (AhiBhi + AhiBlo + AloBhi).
// Block tile 128x128, 8 warps (2 M x 4 N), warp tile 64x32 (4x4 m16n8k16).
// Double-buffered smem, SW128 swizzle, ldmatrix fragments, cp.async for B.

constexpr int SM_BIAS  = 0;      // 128 f32
constexpr int SM_SCALE = 512;    // 128 f32
constexpr int SM_SRC   = 1024;   // 128 i32
constexpr int SM_DST   = 1536;   // 128 i32
constexpr int SM_AH    = 2048;   // [2][16384]  A hi bf16, 128 rows x 128B
constexpr int SM_AL    = 34816;  // [2][16384]
constexpr int SM_BH    = 67584;  // [2][16384]  B hi bf16, 128 n-rows x 128B
constexpr int SM_BL    = 100352;
constexpr int SMEM_TOTAL = 133120;

__device__ __forceinline__ void split_bf16x4(float4 v, uint2& hi, uint2& lo) {
    __nv_bfloat162 h01 = __floats2bfloat162_rn(v.x, v.y);
    __nv_bfloat162 h23 = __floats2bfloat162_rn(v.z, v.w);
    float2 f01 = __bfloat1622float2(h01);
    float2 f23 = __bfloat1622float2(h23);
    __nv_bfloat162 l01 = __floats2bfloat162_rn(v.x - f01.x, v.y - f01.y);
    __nv_bfloat162 l23 = __floats2bfloat162_rn(v.z - f23.x, v.w - f23.y);
    hi.x = *(uint32_t*)&h01; hi.y = *(uint32_t*)&h23;
    lo.x = *(uint32_t*)&l01; lo.y = *(uint32_t*)&l23;
}

template<int KTOT, int MODE, bool SCALE, bool GATHER>
__global__ void __launch_bounds__(256, 1)
gemm_tc(const float* __restrict__ A,            // node_feat when GATHER
        const float* __restrict__ edge_feat,
        const int*   __restrict__ edge_index,
        const __nv_bfloat16* __restrict__ WTh,  // [256][KTOT]
        const __nv_bfloat16* __restrict__ WTl,
        const float* __restrict__ bias,
        const float* __restrict__ residual,
        float* __restrict__ out) {
    extern __shared__ __align__(1024) char sm[];
    const uint32_t smb = smem_u32(sm);
    const int tid  = threadIdx.x;
    const int wid  = tid >> 5;
    const int lane = tid & 31;
    const int row0 = blockIdx.y * 128;
    const int col0 = blockIdx.x * 128;
    const int wm = (wid & 1) * 64;     // warp M offset within tile
    const int wn = (wid >> 1) * 32;    // warp N offset within tile

    if (tid < 128) {
        ((float*)(sm + SM_BIAS))[tid] = bias[col0 + tid];
        if (SCALE) ((float*)(sm + SM_SCALE))[tid] = g_invc[row0 + tid];
        if (GATHER) {
            int r = row0 + tid;
            int b = r >> 14;
            int e = r & (En - 1);
            ((int*)(sm + SM_SRC))[tid] = b * Nn + edge_index[(size_t)b * 2 * En + e];
            ((int*)(sm + SM_DST))[tid] = b * Nn + edge_index[(size_t)b * 2 * En + En + e];
        }
    }
    __syncthreads();

    const float* s_scale = (const float*)(sm + SM_SCALE);
    const int* s_src = (const int*)(sm + SM_SRC);
    const int* s_dst = (const int*)(sm + SM_DST);

    // ldmatrix lane addressing (precomputed): grp selects (row-half, k-half)
    const int grp = lane >> 3, lr = lane & 7;
    const uint32_t kadd = (grp >> 1) * 16;      // byte offset for k-half
    uint32_t saA[4], xaA[4], saB[2], xaB[2];
    #pragma unroll
    for (int mi = 0; mi < 4; mi++) {
        int r = wm + mi * 16 + (grp & 1) * 8 + lr;
        saA[mi] = (uint32_t)r * 128;
        xaA[mi] = (uint32_t)(r & 7) << 4;
    }
    #pragma unroll
    for (int nj = 0; nj < 2; nj++) {
        int r = wn + nj * 16 + (grp & 1) * 8 + lr;
        saB[nj] = (uint32_t)r * 128;
        xaB[nj] = (uint32_t)(r & 7) << 4;
    }

    float acc[4][4][4] = {};
    float4 pa[4][2];

    auto ldgA = [&](int k0) {
        #pragma unroll
        for (int i = 0; i < 4; i++) {
            int idx = tid + i * 256;
            int ar = idx >> 3;
            int c8 = (idx & 7) * 8;
            const float* srcp;
            size_t off;
            if (GATHER) {
                int region = k0 >> 8;
                int koff = (k0 & 255) + c8;
                int rowi;
                if (region == 0)      { srcp = A;         rowi = s_src[ar]; }
                else if (region == 1) { srcp = edge_feat; rowi = row0 + ar; }
                else                  { srcp = A;         rowi = s_dst[ar]; }
                off = (size_t)rowi * Dn + koff;
            } else {
                srcp = A;
                off = (size_t)(row0 + ar) * KTOT + k0 + c8;
            }
            pa[i][0] = *(const float4*)&srcp[off];
            pa[i][1] = *(const float4*)&srcp[off + 4];
        }
    };
    auto stsA = [&](int buf) {
        char* ah = sm + SM_AH + buf * 16384;
        char* al = sm + SM_AL + buf * 16384;
        #pragma unroll
        for (int i = 0; i < 4; i++) {
            int idx = tid + i * 256;
            int ar = idx >> 3;
            int c8 = (idx & 7) * 8;
            float4 v0 = pa[i][0], v1 = pa[i][1];
            if (SCALE) {
                float s = s_scale[ar];
                v0.x *= s; v0.y *= s; v0.z *= s; v0.w *= s;
                v1.x *= s; v1.y *= s; v1.z *= s; v1.w *= s;
            }
            uint2 h0, l0, h1, l1;
            split_bf16x4(v0, h0, l0);
            split_bf16x4(v1, h1, l1);
            uint32_t boff = SW128((uint32_t)(ar * 128 + c8 * 2));
            *(uint4*)(ah + boff) = make_uint4(h0.x, h0.y, h1.x, h1.y);
            *(uint4*)(al + boff) = make_uint4(l0.x, l0.y, l1.x, l1.y);
        }
    };
    auto cpB = [&](int k0, int buf) {
        uint32_t bh = smb + SM_BH + buf * 16384;
        uint32_t bl = smb + SM_BL + buf * 16384;
        #pragma unroll
        for (int i = 0; i < 4; i++) {
            int idx = tid + i * 256;
            int n = idx >> 3, j = idx & 7;
            uint32_t boff = SW128((uint32_t)(n * 128 + j * 16));
            size_t go = (size_t)(col0 + n) * KTOT + k0 + j * 8;
            CP_ASYNC16(bh + boff, WTh + go);
            CP_ASYNC16(bl + boff, WTl + go);
        }
        CP_COMMIT;
    };
    auto compute = [&](int buf) {
        uint32_t abh = smb + SM_AH + buf * 16384;
        uint32_t abl = smb + SM_AL + buf * 16384;
        uint32_t bbh = smb + SM_BH + buf * 16384;
        uint32_t bbl = smb + SM_BL + buf * 16384;
        #pragma unroll
        for (int ks = 0; ks < 4; ks++) {
            uint32_t kb = ks * 32;
            uint32_t ahi[4][4], alo[4][4], bhi[4][2], blo[4][2];
            #pragma unroll
            for (int mi = 0; mi < 4; mi++) {
                uint32_t kx = (kb + kadd);
                LDSM4(ahi[mi], abh + saA[mi] + (kx ^ xaA[mi]));
                LDSM4(alo[mi], abl + saA[mi] + (kx ^ xaA[mi]));
            }
            #pragma unroll
            for (int nj = 0; nj < 2; nj++) {
                uint32_t kx = (kb + kadd);
                uint32_t r[4];
                LDSM4(r, bbh + saB[nj] + (kx ^ xaB[nj]));
                bhi[nj * 2][0] = r[0]; bhi[nj * 2 + 1][0] = r[1];
                bhi[nj * 2][1] = r[2]; bhi[nj * 2 + 1][1] = r[3];
                LDSM4(r, bbl + saB[nj] + (kx ^ xaB[nj]));
                blo[nj * 2][0] = r[0]; blo[nj * 2 + 1][0] = r[1];
                blo[nj * 2][1] = r[2]; blo[nj * 2 + 1][1] = r[3];
            }
            #pragma unroll
            for (int mi = 0; mi < 4; mi++)
                #pragma unroll
                for (int ni = 0; ni < 4; ni++)
                    MMA_BF16(acc[mi][ni], ahi[mi], bhi[ni]);
            #pragma unroll
            for (int mi = 0; mi < 4; mi++)
                #pragma unroll
                for (int ni = 0; ni < 4; ni++)
                    MMA_BF16(acc[mi][ni], ahi[mi], blo[ni]);
            #pragma unroll
            for (int mi = 0; mi < 4; mi++)
                #pragma unroll
                for (int ni = 0; ni < 4; ni++)
                    MMA_BF16(acc[mi][ni], alo[mi], bhi[ni]);
        }
    };

    constexpr int nT = KTOT / 64;
    ldgA(0);
    cpB(0, 0);
    stsA(0);
    CP_WAIT0;
    __syncthreads();

    int buf = 0;
    for (int t = 0; t < nT; t++) {
        if (t + 1 < nT) { ldgA((t + 1) * 64); cpB((t + 1) * 64, buf ^ 1); }
        compute(buf);
        if (t + 1 < nT) {
            stsA(buf ^ 1);
            CP_WAIT0;
            __syncthreads();
            buf ^= 1;
        }
    }

    // ---- epilogue: D fragments -> global -------------------------------
    const float* sb = (const float*)(sm + SM_BIAS);
    #pragma unroll
    for (int mi = 0; mi < 4; mi++) {
        int r0g = row0 + wm + mi * 16 + (lane >> 2);
        int r1g = r0g + 8;
        float mk0 = 1.0f, mk1 = 1.0f;
        int dr0 = 0, dr1 = 0;
        if (MODE == 1) {
            mk0 = g_maskf[r0g]; dr0 = g_dstrow[r0g];
            mk1 = g_maskf[r1g]; dr1 = g_dstrow[r1g];
        } else if (MODE == 3) {
            mk0 = g_nmaskf[r0g];
            mk1 = g_nmaskf[r1g];
        }
        #pragma unroll
        for (int ni = 0; ni < 4; ni++) {
            int cl = wn + ni * 8 + (lane & 3) * 2;   // col within 128 tile
            int cg = col0 + cl;
            float b0 = sb[cl], b1 = sb[cl + 1];
            float v00 = acc[mi][ni][0] + b0, v01 = acc[mi][ni][1] + b1;
            float v10 = acc[mi][ni][2] + b0, v11 = acc[mi][ni][3] + b1;
            size_t o0 = (size_t)r0g * Dn + cg;
            size_t o1 = (size_t)r1g * Dn + cg;
            if (MODE == 0) {
                *(float2*)&out[o0] = make_float2(silu_f(v00), silu_f(v01));
                *(float2*)&out[o1] = make_float2(silu_f(v10), silu_f(v11));
            } else if (MODE == 1) {
                v00 *= mk0; v01 *= mk0; v10 *= mk1; v11 *= mk1;
                *(float2*)&out[o0] = make_float2(v00, v01);
                *(float2*)&out[o1] = make_float2(v10, v11);
                if (mk0 != 0.0f) {
                    atomicAdd(&g_agg[(size_t)dr0 * Dn + cg],     v00);
                    atomicAdd(&g_agg[(size_t)dr0 * Dn + cg + 1], v01);
                }
                if (mk1 != 0.0f) {
                    atomicAdd(&g_agg[(size_t)dr1 * Dn + cg],     v10);
                    atomicAdd(&g_agg[(size_t)dr1 * Dn + cg + 1], v11);
                }
            } else if (MODE == 2) {
                float2 q0 = *(const float2*)&residual[o0];
                float2 q1 = *(const float2*)&residual[o1];
                *(float2*)&out[o0] = make_float2(q0.x + v00, q0.y + v01);
                *(float2*)&out[o1] = make_float2(q1.x + v10, q1.y + v11);
            } else {
                float2 q0 = *(const float2*)&residual[o0];
                float2 q1 = *(const float2*)&residual[o1];
                *(float2*)&out[o0] = make_float2(q0.x + v00 * mk0, q0.y + v01 * mk0);
                *(float2*)&out[o1] = make_float2(q1.x + v10 * mk1, q1.y + v11 * mk1);
            }
        }
    }
}

// ---------------- layernorm over last dim (256) ------------------------------
__global__ void ln_kernel(const float* __restrict__ x,
                          const float* __restrict__ gamma,
                          const float* __restrict__ beta,
                          float* __restrict__ out) {
    int v = blockIdx.x, t = threadIdx.x;
    float val = x[(size_t)v * Dn + t];
    float s = val, s2 = val * val;
    #pragma unroll
    for (int o = 16; o > 0; o >>= 1) {
        s  += __shfl_xor_sync(0xffffffffu, s,  o);
        s2 += __shfl_xor_sync(0xffffffffu, s2, o);
    }
    __shared__ float ws[8], ws2[8];
    int w = t >> 5;
    if ((t & 31) == 0) { ws[w] = s; ws2[w] = s2; }
    __syncthreads();
    if (t == 0) {
        float a = 0.0f, b = 0.0f;
        #pragma unroll
        for (int i = 0; i < 8; i++) { a += ws[i]; b += ws2[i]; }
        ws[0] = a; ws2[0] = b;
    }
    __syncthreads();
    float mean = ws[0] * (1.0f / 256.0f);
    float var  = ws2[0] * (1.0f / 256.0f) - mean * mean;
    out[(size_t)v * Dn + t] = (val - mean) * rsqrtf(var + 1e-5f) * gamma[t] + beta[t];
}

// ---------------- launch ------------------------------------------------------
extern "C" void kernel_launch(void* const* d_in, const int* in_sizes, int n_in,
                              void* d_out, int out_size) {
    const float* node_feat = (const float*)d_in[0];
    const float* edge_feat = (const float*)d_in[1];
    const int*   edge_index = (const int*)d_in[2];
    const void*  node_mask = d_in[3];
    const void*  edge_mask = d_in[4];
    const float* tw1 = (const float*)d_in[5];
    const float* tb1 = (const float*)d_in[6];
    const float* tw2 = (const float*)d_in[7];
    const float* tb2 = (const float*)d_in[8];
    const float* nw1 = (const float*)d_in[9];
    const float* nb1 = (const float*)d_in[10];
    const float* nw2 = (const float*)d_in[11];
    const float* nb2 = (const float*)d_in[12];
    const float* ew1 = (const float*)d_in[13];
    const float* eb1 = (const float*)d_in[14];
    const float* ew2 = (const float*)d_in[15];
    const float* eb2 = (const float*)d_in[16];
    const float* gamma = (const float*)d_in[17];
    const float* beta  = (const float*)d_in[18];

    float* out = (float*)d_out;

    float *hidden, *msg, *agg, *hn, *node, *cnt;
    __nv_bfloat16 *wth, *wtl;
    cudaGetSymbolAddress((void**)&hidden, g_buf1);
    cudaGetSymbolAddress((void**)&msg,    g_msg);
    cudaGetSymbolAddress((void**)&agg,    g_agg);
    cudaGetSymbolAddress((void**)&hn,     g_hn);
    cudaGetSymbolAddress((void**)&node,   g_node);
    cudaGetSymbolAddress((void**)&cnt,    g_cnt);
    cudaGetSymbolAddress((void**)&wth,    g_wth);
    cudaGetSymbolAddress((void**)&wtl,    g_wtl);

    cudaFuncSetAttribute(gemm_tc<768, 0, false, true >, cudaFuncAttributeMaxDynamicSharedMemorySize, SMEM_TOTAL);
    cudaFuncSetAttribute(gemm_tc<256, 1, false, false>, cudaFuncAttributeMaxDynamicSharedMemorySize, SMEM_TOTAL);
    cudaFuncSetAttribute(gemm_tc<256, 0, false, false>, cudaFuncAttributeMaxDynamicSharedMemorySize, SMEM_TOTAL);
    cudaFuncSetAttribute(gemm_tc<256, 2, false, false>, cudaFuncAttributeMaxDynamicSharedMemorySize, SMEM_TOTAL);
    cudaFuncSetAttribute(gemm_tc<256, 0, true , false>, cudaFuncAttributeMaxDynamicSharedMemorySize, SMEM_TOTAL);
    cudaFuncSetAttribute(gemm_tc<256, 3, false, false>, cudaFuncAttributeMaxDynamicSharedMemorySize, SMEM_TOTAL);

    // 0) mask dtype + zero scratch
    sniff_mask_dtype<<<1, 1>>>((const unsigned int*)edge_mask);
    cudaMemsetAsync(agg, 0, (size_t)MN * Dn * sizeof(float));
    cudaMemsetAsync(cnt, 0, (size_t)MN * sizeof(float));
    // 1) weight transpose + bf16 hi/lo split
    prep_weights<<<(768 * 256) / 256, 256>>>(tw1, 768, wth + OW_TW1, wtl + OW_TW1);
    prep_weights<<<(256 * 256) / 256, 256>>>(tw2, 256, wth + OW_TW2, wtl + OW_TW2);
    prep_weights<<<(256 * 256) / 256, 256>>>(ew1, 256, wth + OW_EW1, wtl + OW_EW1);
    prep_weights<<<(256 * 256) / 256, 256>>>(ew2, 256, wth + OW_EW2, wtl + OW_EW2);
    prep_weights<<<(256 * 256) / 256, 256>>>(nw1, 256, wth + OW_NW1, wtl + OW_NW1);
    prep_weights<<<(256 * 256) / 256, 256>>>(nw2, 256, wth + OW_NW2, wtl + OW_NW2);
    // 2) edge metadata + node masks
    prep_edges<<<ME / 256, 256>>>(edge_index, edge_mask);
    prep_nodes<<<MN / 256, 256>>>(node_mask);

    dim3 ge(2, ME / 128);   // edge-row GEMMs
    dim3 gn(2, MN / 128);   // node-row GEMMs
    // 3) triplet layer1 (gather K=768, silu)
    gemm_tc<768, 0, false, true ><<<ge, 256, SMEM_TOTAL>>>(
        node_feat, edge_feat, edge_index, wth + OW_TW1, wtl + OW_TW1, tb1, nullptr, hidden);
    // 4) msg = layer2 * edge_mask; scatter-add to agg
    gemm_tc<256, 1, false, false><<<ge, 256, SMEM_TOTAL>>>(
        hidden, nullptr, nullptr, wth + OW_TW2, wtl + OW_TW2, tb2, nullptr, msg);
    // 5) edge update layer1 (silu)
    gemm_tc<256, 0, false, false><<<ge, 256, SMEM_TOTAL>>>(
        msg, nullptr, nullptr, wth + OW_EW1, wtl + OW_EW1, eb1, nullptr, hidden);
    // 6) edge_out = edge_feat + layer2
    gemm_tc<256, 2, false, false><<<ge, 256, SMEM_TOTAL>>>(
        hidden, nullptr, nullptr, wth + OW_EW2, wtl + OW_EW2, eb2, edge_feat,
        out + (size_t)MN * Dn);
    // 7) node layer1 on agg/counts (silu)
    gemm_tc<256, 0, true , false><<<gn, 256, SMEM_TOTAL>>>(
        agg, nullptr, nullptr, wth + OW_NW1, wtl + OW_NW1, nb1, nullptr, hn);
    // 8) node = node_feat + layer2 * node_mask
    gemm_tc<256, 3, false, false><<<gn, 256, SMEM_TOTAL>>>(
        hn, nullptr, nullptr, wth + OW_NW2, wtl + OW_NW2, nb2, node_feat, node);
    // 9) layernorm
    ln_kernel<<<MN, 256>>>(node, gamma, beta, out);
}

// round 7
// speedup vs baseline: 3.1183x; 1.1843x over previous
#include <cuda_runtime.h>
#include <cuda_bf16.h>
#include <cstdint>
#include <math.h>

// Problem constants
#define Bn 16
#define Nn 1024
#define En 16384
#define Dn 256
constexpr int ME = Bn * En;   // 262144 edge rows
constexpr int MN = Bn * Nn;   // 16384 node rows

// ============================ PTX helpers (sm_80-compatible only) ===========
__device__ __forceinline__ uint32_t smem_u32(const void* p) {
    uint32_t a;
    asm("{ .reg .u64 t; cvta.to.shared.u64 t, %1; cvt.u32.u64 %0, t; }"
        : "=r"(a) : "l"(p));
    return a;
}

#define LDSM4(r, addr) \
    asm volatile("ldmatrix.sync.aligned.m8n8.x4.shared.b16 {%0,%1,%2,%3}, [%4];" \
        : "=r"((r)[0]), "=r"((r)[1]), "=r"((r)[2]), "=r"((r)[3]) : "r"(addr))

#define MMA_BF16(d, a, b) \
    asm volatile("mma.sync.aligned.m16n8k16.row.col.f32.bf16.bf16.f32 " \
        "{%0,%1,%2,%3}, {%4,%5,%6,%7}, {%8,%9}, {%0,%1,%2,%3};" \
        : "+f"((d)[0]), "+f"((d)[1]), "+f"((d)[2]), "+f"((d)[3]) \
        : "r"((a)[0]), "r"((a)[1]), "r"((a)[2]), "r"((a)[3]), \
          "r"((b)[0]), "r"((b)[1]))

#define CP_ASYNC16(dst, src) \
    asm volatile("cp.async.cg.shared.global [%0], [%1], 16;" :: "r"(dst), "l"(src))
#define CP_COMMIT asm volatile("cp.async.commit_group;" ::: "memory")
#define CP_WAIT0  asm volatile("cp.async.wait_group 0;" ::: "memory")

#define SW128(x) ((x) ^ (((x) >> 3) & 0x70))

// ============================ scratch globals ================================
__device__ float g_buf1[(size_t)ME * Dn];
__device__ float g_msg [(size_t)ME * Dn];
__device__ float g_agg [(size_t)MN * Dn];
__device__ float g_hn  [(size_t)MN * Dn];
__device__ float g_node[(size_t)MN * Dn];
__device__ float g_p1  [(size_t)MN * Dn];   // node_feat @ W1a
__device__ float g_p3  [(size_t)MN * Dn];   // node_feat @ W1c
__device__ float g_cnt [MN];
__device__ float g_invc[MN];
__device__ int   g_srcrow[ME];
__device__ int   g_dstrow[ME];
__device__ float g_maskf [ME];
__device__ float g_nmaskf[MN];
__device__ int   g_mask_dt;
__device__ float g_zero256[256];            // statically zero (never written)
// pre-transposed + bf16-split weights, 8 matrices of [256][256]
__device__ __nv_bfloat16 g_wth[524288];
__device__ __nv_bfloat16 g_wtl[524288];
constexpr size_t OW_T1A = 0,      OW_T1B = 65536,  OW_T1C = 131072,
                 OW_TW2 = 196608, OW_EW1 = 262144, OW_EW2 = 327680,
                 OW_NW1 = 393216, OW_NW2 = 458752;

__device__ __forceinline__ float silu_f(float x) { return x / (1.0f + __expf(-x)); }

__device__ __forceinline__ float read_mask(const void* p, int i, int dt) {
    if (dt == 0) return ((const float*)p)[i];
    if (dt == 1) return ((const unsigned char*)p)[i] ? 1.0f : 0.0f;
    return ((const int*)p)[i] ? 1.0f : 0.0f;
}

// ---------------- small prep kernels ----------------------------------------
__global__ void sniff_mask_dtype(const unsigned int* __restrict__ m) {
    bool big_byte = false, upper = false;
    for (int i = 0; i < 16; i++) {
        unsigned int w = m[i];
        unsigned char b0 = w & 0xff, b1 = (w >> 8) & 0xff,
                      b2 = (w >> 16) & 0xff, b3 = (w >> 24) & 0xff;
        if (b0 >= 2 || b1 >= 2 || b2 >= 2 || b3 >= 2) big_byte = true;
        if (b1 | b2 | b3) upper = true;
    }
    g_mask_dt = big_byte ? 0 : (upper ? 1 : 2);
}

__global__ void prep_edges(const int* __restrict__ edge_index,
                           const void* __restrict__ edge_mask) {
    int r = blockIdx.x * blockDim.x + threadIdx.x;
    if (r >= ME) return;
    int dt = g_mask_dt;
    int b = r >> 14;
    int e = r & (En - 1);
    int src = edge_index[(size_t)b * 2 * En + e];
    int dst = edge_index[(size_t)b * 2 * En + En + e];
    float m = (read_mask(edge_mask, r, dt) != 0.0f) ? 1.0f : 0.0f;
    g_srcrow[r] = b * Nn + src;
    g_dstrow[r] = b * Nn + dst;
    g_maskf[r]  = m;
    if (m != 0.0f) atomicAdd(&g_cnt[b * Nn + dst], 1.0f);
}

__global__ void prep_nodes(const void* __restrict__ node_mask) {
    int v = blockIdx.x * blockDim.x + threadIdx.x;
    if (v >= MN) return;
    g_invc[v]   = 1.0f / fmaxf(g_cnt[v], 1.0f);
    g_nmaskf[v] = (read_mask(node_mask, v, g_mask_dt) != 0.0f) ? 1.0f : 0.0f;
}

// transpose + split W[256,256] fp32 -> WT_hi/lo [256,256] bf16
__global__ void prep_weights(const float* __restrict__ W,
                             __nv_bfloat16* __restrict__ wth,
                             __nv_bfloat16* __restrict__ wtl) {
    int i = blockIdx.x * blockDim.x + threadIdx.x;
    if (i >= 65536) return;
    int k = i >> 8, n = i & 255;
    float v = W[i];
    __nv_bfloat16 h = __float2bfloat16_rn(v);
    wth[(size_t)n * 256 + k] = h;
    wtl[(size_t)n * 256 + k] = __float2bfloat16_rn(v - __bfloat162float(h));
}

// ============================ tensor-core GEMM (mma.sync) ====================
// out[M,256] = A[M,256] @ W[256,256] via bf16x3 (AhiBhi + AhiBlo + AloBhi).
// Block tile 128x128, 8 warps (2 M x 4 N), warp tile 64x32 (4x4 m16n8k16).
// MODE 0: silu(D+b)                (SCALE: rows of A scaled by g_invc)
// MODE 1: v=(D+b)*maskf; store; atomicAdd to g_agg[dstrow]
// MODE 2: residual + (D+b)
// MODE 3: residual + (D+b)*g_nmaskf
// MODE 4: silu(D + b + g_p1[srcrow] + g_p3[dstrow])   (triplet layer1)
// MODE 5: plain store (bias must be zero array)

constexpr int SM_BIAS  = 0;      // 128 f32
constexpr int SM_SCALE = 512;    // 128 f32
constexpr int SM_AH    = 2048;   // [2][16384]  A hi bf16, 128 rows x 128B
constexpr int SM_AL    = 34816;  // [2][16384]
constexpr int SM_BH    = 67584;  // [2][16384]  B hi bf16, 128 n-rows x 128B
constexpr int SM_BL    = 100352;
constexpr int SMEM_TOTAL = 133120;

__device__ __forceinline__ void split_bf16x4(float4 v, uint2& hi, uint2& lo) {
    __nv_bfloat162 h01 = __floats2bfloat162_rn(v.x, v.y);
    __nv_bfloat162 h23 = __floats2bfloat162_rn(v.z, v.w);
    float2 f01 = __bfloat1622float2(h01);
    float2 f23 = __bfloat1622float2(h23);
    __nv_bfloat162 l01 = __floats2bfloat162_rn(v.x - f01.x, v.y - f01.y);
    __nv_bfloat162 l23 = __floats2bfloat162_rn(v.z - f23.x, v.w - f23.y);
    hi.x = *(uint32_t*)&h01; hi.y = *(uint32_t*)&h23;
    lo.x = *(uint32_t*)&l01; lo.y = *(uint32_t*)&l23;
}

template<int MODE, bool SCALE>
__global__ void __launch_bounds__(256, 1)
gemm_tc(const float* __restrict__ A,
        const __nv_bfloat16* __restrict__ WTh,  // [256][256]
        const __nv_bfloat16* __restrict__ WTl,
        const float* __restrict__ bias,
        const float* __restrict__ residual,
        float* __restrict__ out) {
    extern __shared__ __align__(1024) char sm[];
    const uint32_t smb = smem_u32(sm);
    const int tid  = threadIdx.x;
    const int wid  = tid >> 5;
    const int lane = tid & 31;
    const int row0 = blockIdx.y * 128;
    const int col0 = blockIdx.x * 128;
    const int wm = (wid & 1) * 64;     // warp M offset within tile
    const int wn = (wid >> 1) * 32;    // warp N offset within tile

    if (tid < 128) {
        ((float*)(sm + SM_BIAS))[tid] = bias[col0 + tid];
        if (SCALE) ((float*)(sm + SM_SCALE))[tid] = g_invc[row0 + tid];
    }
    __syncthreads();

    const float* s_scale = (const float*)(sm + SM_SCALE);

    // ldmatrix lane addressing
    const int grp = lane >> 3, lr = lane & 7;
    const uint32_t kadd = (grp >> 1) * 16;      // byte offset for k-half
    uint32_t saA[4], xaA[4], saB[2], xaB[2];
    #pragma unroll
    for (int mi = 0; mi < 4; mi++) {
        int r = wm + mi * 16 + (grp & 1) * 8 + lr;
        saA[mi] = (uint32_t)r * 128;
        xaA[mi] = (uint32_t)(r & 7) << 4;
    }
    #pragma unroll
    for (int nj = 0; nj < 2; nj++) {
        int r = wn + nj * 16 + (grp & 1) * 8 + lr;
        saB[nj] = (uint32_t)r * 128;
        xaB[nj] = (uint32_t)(r & 7) << 4;
    }

    float acc[4][4][4] = {};
    float4 pa[4][2];

    auto ldgA = [&](int k0) {
        #pragma unroll
        for (int i = 0; i < 4; i++) {
            int idx = tid + i * 256;
            int ar = idx >> 3;
            int c8 = (idx & 7) * 8;
            size_t off = (size_t)(row0 + ar) * Dn + k0 + c8;
            pa[i][0] = *(const float4*)&A[off];
            pa[i][1] = *(const float4*)&A[off + 4];
        }
    };
    auto stsA = [&](int buf) {
        char* ah = sm + SM_AH + buf * 16384;
        char* al = sm + SM_AL + buf * 16384;
        #pragma unroll
        for (int i = 0; i < 4; i++) {
            int idx = tid + i * 256;
            int ar = idx >> 3;
            int c8 = (idx & 7) * 8;
            float4 v0 = pa[i][0], v1 = pa[i][1];
            if (SCALE) {
                float s = s_scale[ar];
                v0.x *= s; v0.y *= s; v0.z *= s; v0.w *= s;
                v1.x *= s; v1.y *= s; v1.z *= s; v1.w *= s;
            }
            uint2 h0, l0, h1, l1;
            split_bf16x4(v0, h0, l0);
            split_bf16x4(v1, h1, l1);
            uint32_t boff = SW128((uint32_t)(ar * 128 + c8 * 2));
            *(uint4*)(ah + boff) = make_uint4(h0.x, h0.y, h1.x, h1.y);
            *(uint4*)(al + boff) = make_uint4(l0.x, l0.y, l1.x, l1.y);
        }
    };
    auto cpB = [&](int k0, int buf) {
        uint32_t bh = smb + SM_BH + buf * 16384;
        uint32_t bl = smb + SM_BL + buf * 16384;
        #pragma unroll
        for (int i = 0; i < 4; i++) {
            int idx = tid + i * 256;
            int n = idx >> 3, j = idx & 7;
            uint32_t boff = SW128((uint32_t)(n * 128 + j * 16));
            size_t go = (size_t)(col0 + n) * Dn + k0 + j * 8;
            CP_ASYNC16(bh + boff, WTh + go);
            CP_ASYNC16(bl + boff, WTl + go);
        }
        CP_COMMIT;
    };
    auto compute = [&](int buf) {
        uint32_t abh = smb + SM_AH + buf * 16384;
        uint32_t abl = smb + SM_AL + buf * 16384;
        uint32_t bbh = smb + SM_BH + buf * 16384;
        uint32_t bbl = smb + SM_BL + buf * 16384;
        #pragma unroll
        for (int ks = 0; ks < 4; ks++) {
            uint32_t kb = ks * 32;
            uint32_t ahi[4][4], alo[4][4], bhi[4][2], blo[4][2];
            #pragma unroll
            for (int mi = 0; mi < 4; mi++) {
                uint32_t kx = (kb + kadd);
                LDSM4(ahi[mi], abh + saA[mi] + (kx ^ xaA[mi]));
                LDSM4(alo[mi], abl + saA[mi] + (kx ^ xaA[mi]));
            }
            #pragma unroll
            for (int nj = 0; nj < 2; nj++) {
                uint32_t kx = (kb + kadd);
                uint32_t r[4];
                LDSM4(r, bbh + saB[nj] + (kx ^ xaB[nj]));
                bhi[nj * 2][0] = r[0]; bhi[nj * 2 + 1][0] = r[1];
                bhi[nj * 2][1] = r[2]; bhi[nj * 2 + 1][1] = r[3];
                LDSM4(r, bbl + saB[nj] + (kx ^ xaB[nj]));
                blo[nj * 2][0] = r[0]; blo[nj * 2 + 1][0] = r[1];
                blo[nj * 2][1] = r[2]; blo[nj * 2 + 1][1] = r[3];
            }
            #pragma unroll
            for (int mi = 0; mi < 4; mi++)
                #pragma unroll
                for (int ni = 0; ni < 4; ni++)
                    MMA_BF16(acc[mi][ni], ahi[mi], bhi[ni]);
            #pragma unroll
            for (int mi = 0; mi < 4; mi++)
                #pragma unroll
                for (int ni = 0; ni < 4; ni++)
                    MMA_BF16(acc[mi][ni], ahi[mi], blo[ni]);
            #pragma unroll
            for (int mi = 0; mi < 4; mi++)
                #pragma unroll
                for (int ni = 0; ni < 4; ni++)
                    MMA_BF16(acc[mi][ni], alo[mi], bhi[ni]);
        }
    };

    constexpr int nT = 4;   // K = 256 in chunks of 64
    ldgA(0);
    cpB(0, 0);
    stsA(0);
    CP_WAIT0;
    __syncthreads();

    int buf = 0;
    for (int t = 0; t < nT; t++) {
        if (t + 1 < nT) { ldgA((t + 1) * 64); cpB((t + 1) * 64, buf ^ 1); }
        compute(buf);
        if (t + 1 < nT) {
            stsA(buf ^ 1);
            CP_WAIT0;
            __syncthreads();
            buf ^= 1;
        }
    }

    // ---- epilogue: D fragments -> global -------------------------------
    const float* sb = (const float*)(sm + SM_BIAS);
    #pragma unroll
    for (int mi = 0; mi < 4; mi++) {
        int r0g = row0 + wm + mi * 16 + (lane >> 2);
        int r1g = r0g + 8;
        float mk0 = 1.0f, mk1 = 1.0f;
        int dr0 = 0, dr1 = 0, sr0 = 0, sr1 = 0;
        if (MODE == 1) {
            mk0 = g_maskf[r0g]; dr0 = g_dstrow[r0g];
            mk1 = g_maskf[r1g]; dr1 = g_dstrow[r1g];
        } else if (MODE == 3) {
            mk0 = g_nmaskf[r0g];
            mk1 = g_nmaskf[r1g];
        } else if (MODE == 4) {
            sr0 = g_srcrow[r0g]; dr0 = g_dstrow[r0g];
            sr1 = g_srcrow[r1g]; dr1 = g_dstrow[r1g];
        }
        #pragma unroll
        for (int ni = 0; ni < 4; ni++) {
            int cl = wn + ni * 8 + (lane & 3) * 2;   // col within 128 tile
            int cg = col0 + cl;
            float b0 = sb[cl], b1 = sb[cl + 1];
            float v00 = acc[mi][ni][0] + b0, v01 = acc[mi][ni][1] + b1;
            float v10 = acc[mi][ni][2] + b0, v11 = acc[mi][ni][3] + b1;
            size_t o0 = (size_t)r0g * Dn + cg;
            size_t o1 = (size_t)r1g * Dn + cg;
            if (MODE == 0) {
                *(float2*)&out[o0] = make_float2(silu_f(v00), silu_f(v01));
                *(float2*)&out[o1] = make_float2(silu_f(v10), silu_f(v11));
            } else if (MODE == 1) {
                v00 *= mk0; v01 *= mk0; v10 *= mk1; v11 *= mk1;
                *(float2*)&out[o0] = make_float2(v00, v01);
                *(float2*)&out[o1] = make_float2(v10, v11);
                if (mk0 != 0.0f) {
                    atomicAdd(&g_agg[(size_t)dr0 * Dn + cg],     v00);
                    atomicAdd(&g_agg[(size_t)dr0 * Dn + cg + 1], v01);
                }
                if (mk1 != 0.0f) {
                    atomicAdd(&g_agg[(size_t)dr1 * Dn + cg],     v10);
                    atomicAdd(&g_agg[(size_t)dr1 * Dn + cg + 1], v11);
                }
            } else if (MODE == 2) {
                float2 q0 = *(const float2*)&residual[o0];
                float2 q1 = *(const float2*)&residual[o1];
                *(float2*)&out[o0] = make_float2(q0.x + v00, q0.y + v01);
                *(float2*)&out[o1] = make_float2(q1.x + v10, q1.y + v11);
            } else if (MODE == 3) {
                float2 q0 = *(const float2*)&residual[o0];
                float2 q1 = *(const float2*)&residual[o1];
                *(float2*)&out[o0] = make_float2(q0.x + v00 * mk0, q0.y + v01 * mk0);
                *(float2*)&out[o1] = make_float2(q1.x + v10 * mk1, q1.y + v11 * mk1);
            } else if (MODE == 4) {
                float2 p0 = *(const float2*)&g_p1[(size_t)sr0 * Dn + cg];
                float2 p1 = *(const float2*)&g_p1[(size_t)sr1 * Dn + cg];
                float2 q0 = *(const float2*)&g_p3[(size_t)dr0 * Dn + cg];
                float2 q1 = *(const float2*)&g_p3[(size_t)dr1 * Dn + cg];
                *(float2*)&out[o0] = make_float2(silu_f(v00 + p0.x + q0.x),
                                                 silu_f(v01 + p0.y + q0.y));
                *(float2*)&out[o1] = make_float2(silu_f(v10 + p1.x + q1.x),
                                                 silu_f(v11 + p1.y + q1.y));
            } else {  // MODE 5: plain store (bias array is zero)
                *(float2*)&out[o0] = make_float2(v00, v01);
                *(float2*)&out[o1] = make_float2(v10, v11);
            }
        }
    }
}

// ---------------- layernorm over last dim (256) ------------------------------
__global__ void ln_kernel(const float* __restrict__ x,
                          const float* __restrict__ gamma,
                          const float* __restrict__ beta,
                          float* __restrict__ out) {
    int v = blockIdx.x, t = threadIdx.x;
    float val = x[(size_t)v * Dn + t];
    float s = val, s2 = val * val;
    #pragma unroll
    for (int o = 16; o > 0; o >>= 1) {
        s  += __shfl_xor_sync(0xffffffffu, s,  o);
        s2 += __shfl_xor_sync(0xffffffffu, s2, o);
    }
    __shared__ float ws[8], ws2[8];
    int w = t >> 5;
    if ((t & 31) == 0) { ws[w] = s; ws2[w] = s2; }
    __syncthreads();
    if (t == 0) {
        float a = 0.0f, b = 0.0f;
        #pragma unroll
        for (int i = 0; i < 8; i++) { a += ws[i]; b += ws2[i]; }
        ws[0] = a; ws2[0] = b;
    }
    __syncthreads();
    float mean = ws[0] * (1.0f / 256.0f);
    float var  = ws2[0] * (1.0f / 256.0f) - mean * mean;
    out[(size_t)v * Dn + t] = (val - mean) * rsqrtf(var + 1e-5f) * gamma[t] + beta[t];
}

// ---------------- launch ------------------------------------------------------
extern "C" void kernel_launch(void* const* d_in, const int* in_sizes, int n_in,
                              void* d_out, int out_size) {
    const float* node_feat = (const float*)d_in[0];
    const float* edge_feat = (const float*)d_in[1];
    const int*   edge_index = (const int*)d_in[2];
    const void*  node_mask = d_in[3];
    const void*  edge_mask = d_in[4];
    const float* tw1 = (const float*)d_in[5];
    const float* tb1 = (const float*)d_in[6];
    const float* tw2 = (const float*)d_in[7];
    const float* tb2 = (const float*)d_in[8];
    const float* nw1 = (const float*)d_in[9];
    const float* nb1 = (const float*)d_in[10];
    const float* nw2 = (const float*)d_in[11];
    const float* nb2 = (const float*)d_in[12];
    const float* ew1 = (const float*)d_in[13];
    const float* eb1 = (const float*)d_in[14];
    const float* ew2 = (const float*)d_in[15];
    const float* eb2 = (const float*)d_in[16];
    const float* gamma = (const float*)d_in[17];
    const float* beta  = (const float*)d_in[18];

    float* out = (float*)d_out;

    float *hidden, *msg, *agg, *hn, *node, *cnt, *p1, *p3, *zb;
    __nv_bfloat16 *wth, *wtl;
    cudaGetSymbolAddress((void**)&hidden, g_buf1);
    cudaGetSymbolAddress((void**)&msg,    g_msg);
    cudaGetSymbolAddress((void**)&agg,    g_agg);
    cudaGetSymbolAddress((void**)&hn,     g_hn);
    cudaGetSymbolAddress((void**)&node,   g_node);
    cudaGetSymbolAddress((void**)&cnt,    g_cnt);
    cudaGetSymbolAddress((void**)&p1,     g_p1);
    cudaGetSymbolAddress((void**)&p3,     g_p3);
    cudaGetSymbolAddress((void**)&zb,     g_zero256);
    cudaGetSymbolAddress((void**)&wth,    g_wth);
    cudaGetSymbolAddress((void**)&wtl,    g_wtl);

    cudaFuncSetAttribute(gemm_tc<0, false>, cudaFuncAttributeMaxDynamicSharedMemorySize, SMEM_TOTAL);
    cudaFuncSetAttribute(gemm_tc<0, true >, cudaFuncAttributeMaxDynamicSharedMemorySize, SMEM_TOTAL);
    cudaFuncSetAttribute(gemm_tc<1, false>, cudaFuncAttributeMaxDynamicSharedMemorySize, SMEM_TOTAL);
    cudaFuncSetAttribute(gemm_tc<2, false>, cudaFuncAttributeMaxDynamicSharedMemorySize, SMEM_TOTAL);
    cudaFuncSetAttribute(gemm_tc<3, false>, cudaFuncAttributeMaxDynamicSharedMemorySize, SMEM_TOTAL);
    cudaFuncSetAttribute(gemm_tc<4, false>, cudaFuncAttributeMaxDynamicSharedMemorySize, SMEM_TOTAL);
    cudaFuncSetAttribute(gemm_tc<5, false>, cudaFuncAttributeMaxDynamicSharedMemorySize, SMEM_TOTAL);

    // 0) mask dtype + zero scratch
    sniff_mask_dtype<<<1, 1>>>((const unsigned int*)edge_mask);
    cudaMemsetAsync(agg, 0, (size_t)MN * Dn * sizeof(float));
    cudaMemsetAsync(cnt, 0, (size_t)MN * sizeof(float));
    // 1) weight transpose + bf16 hi/lo split (tw1 in three K=256 slices)
    prep_weights<<<256, 256>>>(tw1,          wth + OW_T1A, wtl + OW_T1A);
    prep_weights<<<256, 256>>>(tw1 + 65536,  wth + OW_T1B, wtl + OW_T1B);
    prep_weights<<<256, 256>>>(tw1 + 131072, wth + OW_T1C, wtl + OW_T1C);
    prep_weights<<<256, 256>>>(tw2, wth + OW_TW2, wtl + OW_TW2);
    prep_weights<<<256, 256>>>(ew1, wth + OW_EW1, wtl + OW_EW1);
    prep_weights<<<256, 256>>>(ew2, wth + OW_EW2, wtl + OW_EW2);
    prep_weights<<<256, 256>>>(nw1, wth + OW_NW1, wtl + OW_NW1);
    prep_weights<<<256, 256>>>(nw2, wth + OW_NW2, wtl + OW_NW2);
    // 2) edge metadata + node masks
    prep_edges<<<ME / 256, 256>>>(edge_index, edge_mask);
    prep_nodes<<<MN / 256, 256>>>(node_mask);

    dim3 ge(2, ME / 128);   // edge-row GEMMs
    dim3 gn(2, MN / 128);   // node-row GEMMs
    // 3) P1 = node_feat @ W1a, P3 = node_feat @ W1c  (node-level, tiny)
    gemm_tc<5, false><<<gn, 256, SMEM_TOTAL>>>(node_feat, wth + OW_T1A, wtl + OW_T1A, zb, nullptr, p1);
    gemm_tc<5, false><<<gn, 256, SMEM_TOTAL>>>(node_feat, wth + OW_T1C, wtl + OW_T1C, zb, nullptr, p3);
    // 4) triplet layer1: silu(edge@W1b + P1[src] + P3[dst] + tb1)
    gemm_tc<4, false><<<ge, 256, SMEM_TOTAL>>>(edge_feat, wth + OW_T1B, wtl + OW_T1B, tb1, nullptr, hidden);
    // 5) msg = layer2 * edge_mask; scatter-add to agg
    gemm_tc<1, false><<<ge, 256, SMEM_TOTAL>>>(hidden, wth + OW_TW2, wtl + OW_TW2, tb2, nullptr, msg);
    // 6) edge update layer1 (silu)
    gemm_tc<0, false><<<ge, 256, SMEM_TOTAL>>>(msg, wth + OW_EW1, wtl + OW_EW1, eb1, nullptr, hidden);
    // 7) edge_out = edge_feat + layer2
    gemm_tc<2, false><<<ge, 256, SMEM_TOTAL>>>(hidden, wth + OW_EW2, wtl + OW_EW2, eb2, edge_feat,
                                               out + (size_t)MN * Dn);
    // 8) node layer1 on agg/counts (silu)
    gemm_tc<0, true ><<<gn, 256, SMEM_TOTAL>>>(agg, wth + OW_NW1, wtl + OW_NW1, nb1, nullptr, hn);
    // 9) node = node_feat + layer2 * node_mask
    gemm_tc<3, false><<<gn, 256, SMEM_TOTAL>>>(hn, wth + OW_NW2, wtl + OW_NW2, nb2, node_feat, node);
    // 10) layernorm
    ln_kernel<<<MN, 256>>>(node, gamma, beta, out);
}

// round 8
// speedup vs baseline: 3.1698x; 1.0165x over previous
#include <cuda_runtime.h>
#include <cuda_bf16.h>
#include <cstdint>
#include <math.h>

// Problem constants
#define Bn 16
#define Nn 1024
#define En 16384
#define Dn 256
constexpr int ME = Bn * En;   // 262144 edge rows
constexpr int MN = Bn * Nn;   // 16384 node rows

// ============================ PTX helpers (sm_80-compatible only) ===========
__device__ __forceinline__ uint32_t smem_u32(const void* p) {
    uint32_t a;
    asm("{ .reg .u64 t; cvta.to.shared.u64 t, %1; cvt.u32.u64 %0, t; }"
        : "=r"(a) : "l"(p));
    return a;
}

#define LDSM4(r, addr) \
    asm volatile("ldmatrix.sync.aligned.m8n8.x4.shared.b16 {%0,%1,%2,%3}, [%4];" \
        : "=r"((r)[0]), "=r"((r)[1]), "=r"((r)[2]), "=r"((r)[3]) : "r"(addr))

#define MMA_BF16(d, a, b) \
    asm volatile("mma.sync.aligned.m16n8k16.row.col.f32.bf16.bf16.f32 " \
        "{%0,%1,%2,%3}, {%4,%5,%6,%7}, {%8,%9}, {%0,%1,%2,%3};" \
        : "+f"((d)[0]), "+f"((d)[1]), "+f"((d)[2]), "+f"((d)[3]) \
        : "r"((a)[0]), "r"((a)[1]), "r"((a)[2]), "r"((a)[3]), \
          "r"((b)[0]), "r"((b)[1]))

#define CP_ASYNC16(dst, src) \
    asm volatile("cp.async.cg.shared.global [%0], [%1], 16;" :: "r"(dst), "l"(src))
#define CP_COMMIT asm volatile("cp.async.commit_group;" ::: "memory")
#define CP_WAIT0  asm volatile("cp.async.wait_group 0;" ::: "memory")

#define SW128(x) ((x) ^ (((x) >> 3) & 0x70))

// ============================ scratch globals ================================
// Aliased storage: each fp32 array of X*256 floats can hold a bf16 hi/lo pair
// of the same logical shape (X*256*2B*2 = X*256*4B).
__device__ float g_buf1[(size_t)ME * Dn];   // hidden  (as bf16 hi/lo pair)
__device__ float g_msg [(size_t)ME * Dn];   // msg     (as bf16 hi/lo pair)
__device__ float g_agg [(size_t)MN * Dn];   // fp32 (atomics)
__device__ float g_hn  [(size_t)MN * Dn];   // hn      (as bf16 hi/lo pair)
__device__ float g_node[(size_t)MN * Dn];   // fp32 pre-LN
__device__ float g_p1  [(size_t)MN * Dn];   // node_feat @ W1a (fp32)
__device__ float g_p3  [(size_t)MN * Dn];   // node_feat @ W1c (fp32)
__device__ float g_cnt [MN];
__device__ float g_invc[MN];
__device__ int   g_srcrow[ME];
__device__ int   g_dstrow[ME];
__device__ float g_maskf [ME];
__device__ float g_nmaskf[MN];
__device__ int   g_mask_dt;
__device__ float g_zero256[256];
// pre-transposed + bf16-split weights, 8 matrices of [256][256]
__device__ __nv_bfloat16 g_wth[524288];
__device__ __nv_bfloat16 g_wtl[524288];
constexpr size_t OW_T1A = 0,      OW_T1B = 65536,  OW_T1C = 131072,
                 OW_TW2 = 196608, OW_EW1 = 262144, OW_EW2 = 327680,
                 OW_NW1 = 393216, OW_NW2 = 458752;

__device__ __forceinline__ float silu_f(float x) { return x / (1.0f + __expf(-x)); }

__device__ __forceinline__ float read_mask(const void* p, int i, int dt) {
    if (dt == 0) return ((const float*)p)[i];
    if (dt == 1) return ((const unsigned char*)p)[i] ? 1.0f : 0.0f;
    return ((const int*)p)[i] ? 1.0f : 0.0f;
}

// ---------------- small prep kernels ----------------------------------------
__global__ void sniff_mask_dtype(const unsigned int* __restrict__ m) {
    bool big_byte = false, upper = false;
    for (int i = 0; i < 16; i++) {
        unsigned int w = m[i];
        unsigned char b0 = w & 0xff, b1 = (w >> 8) & 0xff,
                      b2 = (w >> 16) & 0xff, b3 = (w >> 24) & 0xff;
        if (b0 >= 2 || b1 >= 2 || b2 >= 2 || b3 >= 2) big_byte = true;
        if (b1 | b2 | b3) upper = true;
    }
    g_mask_dt = big_byte ? 0 : (upper ? 1 : 2);
}

__global__ void prep_edges(const int* __restrict__ edge_index,
                           const void* __restrict__ edge_mask) {
    int r = blockIdx.x * blockDim.x + threadIdx.x;
    if (r >= ME) return;
    int dt = g_mask_dt;
    int b = r >> 14;
    int e = r & (En - 1);
    int src = edge_index[(size_t)b * 2 * En + e];
    int dst = edge_index[(size_t)b * 2 * En + En + e];
    float m = (read_mask(edge_mask, r, dt) != 0.0f) ? 1.0f : 0.0f;
    g_srcrow[r] = b * Nn + src;
    g_dstrow[r] = b * Nn + dst;
    g_maskf[r]  = m;
    if (m != 0.0f) atomicAdd(&g_cnt[b * Nn + dst], 1.0f);
}

__global__ void prep_nodes(const void* __restrict__ node_mask) {
    int v = blockIdx.x * blockDim.x + threadIdx.x;
    if (v >= MN) return;
    g_invc[v]   = 1.0f / fmaxf(g_cnt[v], 1.0f);
    g_nmaskf[v] = (read_mask(node_mask, v, g_mask_dt) != 0.0f) ? 1.0f : 0.0f;
}

// All 8 weight transposes in one launch; smem-tile coalesced.
// z selects the [256,256] slice; dst block = z*65536 in g_wth/g_wtl.
struct WSrcs { const float* p[8]; };
__global__ void prep_weights_all(WSrcs srcs,
                                 __nv_bfloat16* __restrict__ wth,
                                 __nv_bfloat16* __restrict__ wtl) {
    __shared__ float tile[32][33];
    const float* src = srcs.p[blockIdx.z];
    int kt = blockIdx.x * 32, nt = blockIdx.y * 32;
    #pragma unroll
    for (int i = threadIdx.y; i < 32; i += 8)
        tile[i][threadIdx.x] = src[(size_t)(kt + i) * 256 + nt + threadIdx.x];
    __syncthreads();
    size_t base = (size_t)blockIdx.z * 65536;
    #pragma unroll
    for (int i = threadIdx.y; i < 32; i += 8) {
        int n = nt + i, k = kt + threadIdx.x;
        float v = tile[threadIdx.x][i];
        __nv_bfloat16 h = __float2bfloat16_rn(v);
        wth[base + (size_t)n * 256 + k] = h;
        wtl[base + (size_t)n * 256 + k] = __float2bfloat16_rn(v - __bfloat162float(h));
    }
}

// ============================ tensor-core GEMM (mma.sync) ====================
// out[M,256] = A[M,256] @ W[256,256] via bf16x3 (AhiBhi + AhiBlo + AloBhi).
// Block tile 128x128, 8 warps (2 M x 4 N), warp tile 64x32 (4x4 m16n8k16).
// ABF16: A arrives pre-split as bf16 hi/lo arrays -> pure cp.async fill.
// OBF16: epilogue splits result into bf16 hi/lo pair stores.
// MODE 0: silu(D+b)                (SCALE: rows of fp32 A scaled by g_invc)
// MODE 1: v=(D+b)*maskf; store; atomicAdd fp32 to g_agg[dstrow]
// MODE 2: residual + (D+b)             (fp32 out)
// MODE 3: residual + (D+b)*g_nmaskf    (fp32 out)
// MODE 4: silu(D + b + g_p1[srcrow] + g_p3[dstrow])
// MODE 5: plain store (bias zero array)

constexpr int SM_BIAS  = 0;      // 128 f32
constexpr int SM_SCALE = 512;    // 128 f32
constexpr int SM_AH    = 2048;   // [2][16384]
constexpr int SM_AL    = 34816;  // [2][16384]
constexpr int SM_BH    = 67584;  // [2][16384]
constexpr int SM_BL    = 100352;
constexpr int SMEM_TOTAL = 133120;

__device__ __forceinline__ void split_bf16x4(float4 v, uint2& hi, uint2& lo) {
    __nv_bfloat162 h01 = __floats2bfloat162_rn(v.x, v.y);
    __nv_bfloat162 h23 = __floats2bfloat162_rn(v.z, v.w);
    float2 f01 = __bfloat1622float2(h01);
    float2 f23 = __bfloat1622float2(h23);
    __nv_bfloat162 l01 = __floats2bfloat162_rn(v.x - f01.x, v.y - f01.y);
    __nv_bfloat162 l23 = __floats2bfloat162_rn(v.z - f23.x, v.w - f23.y);
    hi.x = *(uint32_t*)&h01; hi.y = *(uint32_t*)&h23;
    lo.x = *(uint32_t*)&l01; lo.y = *(uint32_t*)&l23;
}

__device__ __forceinline__ void store_pair(__nv_bfloat16* outh, __nv_bfloat16* outl,
                                           size_t o, float a, float b) {
    __nv_bfloat162 h = __floats2bfloat162_rn(a, b);
    float2 hf = __bfloat1622float2(h);
    __nv_bfloat162 l = __floats2bfloat162_rn(a - hf.x, b - hf.y);
    *(__nv_bfloat162*)&outh[o] = h;
    *(__nv_bfloat162*)&outl[o] = l;
}

template<int MODE, bool SCALE, bool ABF16, bool OBF16>
__global__ void __launch_bounds__(256, 1)
gemm_tc(const float* __restrict__ A,                 // fp32 A (when !ABF16)
        const __nv_bfloat16* __restrict__ Ah,        // bf16 A pair (when ABF16)
        const __nv_bfloat16* __restrict__ Al,
        const __nv_bfloat16* __restrict__ WTh,       // [256][256]
        const __nv_bfloat16* __restrict__ WTl,
        const float* __restrict__ bias,
        const float* __restrict__ residual,
        float* __restrict__ out,
        __nv_bfloat16* __restrict__ outh,
        __nv_bfloat16* __restrict__ outl) {
    extern __shared__ __align__(1024) char sm[];
    const uint32_t smb = smem_u32(sm);
    const int tid  = threadIdx.x;
    const int wid  = tid >> 5;
    const int lane = tid & 31;
    const int row0 = blockIdx.y * 128;
    const int col0 = blockIdx.x * 128;
    const int wm = (wid & 1) * 64;
    const int wn = (wid >> 1) * 32;

    if (tid < 128) {
        ((float*)(sm + SM_BIAS))[tid] = bias[col0 + tid];
        if (SCALE) ((float*)(sm + SM_SCALE))[tid] = g_invc[row0 + tid];
    }
    __syncthreads();

    const float* s_scale = (const float*)(sm + SM_SCALE);

    // ldmatrix lane addressing
    const int grp = lane >> 3, lr = lane & 7;
    const uint32_t kadd = (grp >> 1) * 16;
    uint32_t saA[4], xaA[4], saB[2], xaB[2];
    #pragma unroll
    for (int mi = 0; mi < 4; mi++) {
        int r = wm + mi * 16 + (grp & 1) * 8 + lr;
        saA[mi] = (uint32_t)r * 128;
        xaA[mi] = (uint32_t)(r & 7) << 4;
    }
    #pragma unroll
    for (int nj = 0; nj < 2; nj++) {
        int r = wn + nj * 16 + (grp & 1) * 8 + lr;
        saB[nj] = (uint32_t)r * 128;
        xaB[nj] = (uint32_t)(r & 7) << 4;
    }

    float acc[4][4][4] = {};
    float4 pa[4][2];

    auto ldgA = [&](int k0) {
        #pragma unroll
        for (int i = 0; i < 4; i++) {
            int idx = tid + i * 256;
            int ar = idx >> 3;
            int c8 = (idx & 7) * 8;
            size_t off = (size_t)(row0 + ar) * Dn + k0 + c8;
            pa[i][0] = *(const float4*)&A[off];
            pa[i][1] = *(const float4*)&A[off + 4];
        }
    };
    auto stsA = [&](int buf) {
        char* ah = sm + SM_AH + buf * 16384;
        char* al = sm + SM_AL + buf * 16384;
        #pragma unroll
        for (int i = 0; i < 4; i++) {
            int idx = tid + i * 256;
            int ar = idx >> 3;
            int c8 = (idx & 7) * 8;
            float4 v0 = pa[i][0], v1 = pa[i][1];
            if (SCALE) {
                float s = s_scale[ar];
                v0.x *= s; v0.y *= s; v0.z *= s; v0.w *= s;
                v1.x *= s; v1.y *= s; v1.z *= s; v1.w *= s;
            }
            uint2 h0, l0, h1, l1;
            split_bf16x4(v0, h0, l0);
            split_bf16x4(v1, h1, l1);
            uint32_t boff = SW128((uint32_t)(ar * 128 + c8 * 2));
            *(uint4*)(ah + boff) = make_uint4(h0.x, h0.y, h1.x, h1.y);
            *(uint4*)(al + boff) = make_uint4(l0.x, l0.y, l1.x, l1.y);
        }
    };
    auto cpA = [&](int k0, int buf) {
        uint32_t ah = smb + SM_AH + buf * 16384;
        uint32_t al = smb + SM_AL + buf * 16384;
        #pragma unroll
        for (int i = 0; i < 4; i++) {
            int idx = tid + i * 256;
            int r = idx >> 3, j = idx & 7;
            uint32_t boff = SW128((uint32_t)(r * 128 + j * 16));
            size_t go = (size_t)(row0 + r) * Dn + k0 + j * 8;
            CP_ASYNC16(ah + boff, Ah + go);
            CP_ASYNC16(al + boff, Al + go);
        }
    };
    auto cpB = [&](int k0, int buf) {
        uint32_t bh = smb + SM_BH + buf * 16384;
        uint32_t bl = smb + SM_BL + buf * 16384;
        #pragma unroll
        for (int i = 0; i < 4; i++) {
            int idx = tid + i * 256;
            int n = idx >> 3, j = idx & 7;
            uint32_t boff = SW128((uint32_t)(n * 128 + j * 16));
            size_t go = (size_t)(col0 + n) * Dn + k0 + j * 8;
            CP_ASYNC16(bh + boff, WTh + go);
            CP_ASYNC16(bl + boff, WTl + go);
        }
    };
    auto compute = [&](int buf) {
        uint32_t abh = smb + SM_AH + buf * 16384;
        uint32_t abl = smb + SM_AL + buf * 16384;
        uint32_t bbh = smb + SM_BH + buf * 16384;
        uint32_t bbl = smb + SM_BL + buf * 16384;
        #pragma unroll
        for (int ks = 0; ks < 4; ks++) {
            uint32_t kb = ks * 32;
            uint32_t ahi[4][4], alo[4][4], bhi[4][2], blo[4][2];
            #pragma unroll
            for (int mi = 0; mi < 4; mi++) {
                uint32_t kx = (kb + kadd);
                LDSM4(ahi[mi], abh + saA[mi] + (kx ^ xaA[mi]));
                LDSM4(alo[mi], abl + saA[mi] + (kx ^ xaA[mi]));
            }
            #pragma unroll
            for (int nj = 0; nj < 2; nj++) {
                uint32_t kx = (kb + kadd);
                uint32_t r[4];
                LDSM4(r, bbh + saB[nj] + (kx ^ xaB[nj]));
                bhi[nj * 2][0] = r[0]; bhi[nj * 2 + 1][0] = r[1];
                bhi[nj * 2][1] = r[2]; bhi[nj * 2 + 1][1] = r[3];
                LDSM4(r, bbl + saB[nj] + (kx ^ xaB[nj]));
                blo[nj * 2][0] = r[0]; blo[nj * 2 + 1][0] = r[1];
                blo[nj * 2][1] = r[2]; blo[nj * 2 + 1][1] = r[3];
            }
            #pragma unroll
            for (int mi = 0; mi < 4; mi++)
                #pragma unroll
                for (int ni = 0; ni < 4; ni++)
                    MMA_BF16(acc[mi][ni], ahi[mi], bhi[ni]);
            #pragma unroll
            for (int mi = 0; mi < 4; mi++)
                #pragma unroll
                for (int ni = 0; ni < 4; ni++)
                    MMA_BF16(acc[mi][ni], ahi[mi], blo[ni]);
            #pragma unroll
            for (int mi = 0; mi < 4; mi++)
                #pragma unroll
                for (int ni = 0; ni < 4; ni++)
                    MMA_BF16(acc[mi][ni], alo[mi], bhi[ni]);
        }
    };

    constexpr int nT = 4;   // K = 256 in chunks of 64
    if (ABF16) cpA(0, 0); else ldgA(0);
    cpB(0, 0);
    CP_COMMIT;
    if (!ABF16) stsA(0);
    CP_WAIT0;
    __syncthreads();

    int buf = 0;
    for (int t = 0; t < nT; t++) {
        if (t + 1 < nT) {
            if (ABF16) cpA((t + 1) * 64, buf ^ 1); else ldgA((t + 1) * 64);
            cpB((t + 1) * 64, buf ^ 1);
            CP_COMMIT;
        }
        compute(buf);
        if (t + 1 < nT) {
            if (!ABF16) stsA(buf ^ 1);
            CP_WAIT0;
            __syncthreads();
            buf ^= 1;
        }
    }

    // ---- epilogue ---------------------------------------------------------
    const float* sb = (const float*)(sm + SM_BIAS);
    #pragma unroll
    for (int mi = 0; mi < 4; mi++) {
        int r0g = row0 + wm + mi * 16 + (lane >> 2);
        int r1g = r0g + 8;
        float mk0 = 1.0f, mk1 = 1.0f;
        int dr0 = 0, dr1 = 0, sr0 = 0, sr1 = 0;
        if (MODE == 1) {
            mk0 = g_maskf[r0g]; dr0 = g_dstrow[r0g];
            mk1 = g_maskf[r1g]; dr1 = g_dstrow[r1g];
        } else if (MODE == 3) {
            mk0 = g_nmaskf[r0g];
            mk1 = g_nmaskf[r1g];
        } else if (MODE == 4) {
            sr0 = g_srcrow[r0g]; dr0 = g_dstrow[r0g];
            sr1 = g_srcrow[r1g]; dr1 = g_dstrow[r1g];
        }
        #pragma unroll
        for (int ni = 0; ni < 4; ni++) {
            int cl = wn + ni * 8 + (lane & 3) * 2;
            int cg = col0 + cl;
            float b0 = sb[cl], b1 = sb[cl + 1];
            float v00 = acc[mi][ni][0] + b0, v01 = acc[mi][ni][1] + b1;
            float v10 = acc[mi][ni][2] + b0, v11 = acc[mi][ni][3] + b1;
            size_t o0 = (size_t)r0g * Dn + cg;
            size_t o1 = (size_t)r1g * Dn + cg;
            if (MODE == 0) {
                v00 = silu_f(v00); v01 = silu_f(v01);
                v10 = silu_f(v10); v11 = silu_f(v11);
            } else if (MODE == 1) {
                v00 *= mk0; v01 *= mk0; v10 *= mk1; v11 *= mk1;
                if (mk0 != 0.0f) {
                    atomicAdd(&g_agg[(size_t)dr0 * Dn + cg],     v00);
                    atomicAdd(&g_agg[(size_t)dr0 * Dn + cg + 1], v01);
                }
                if (mk1 != 0.0f) {
                    atomicAdd(&g_agg[(size_t)dr1 * Dn + cg],     v10);
                    atomicAdd(&g_agg[(size_t)dr1 * Dn + cg + 1], v11);
                }
            } else if (MODE == 2) {
                float2 q0 = *(const float2*)&residual[o0];
                float2 q1 = *(const float2*)&residual[o1];
                v00 += q0.x; v01 += q0.y; v10 += q1.x; v11 += q1.y;
            } else if (MODE == 3) {
                float2 q0 = *(const float2*)&residual[o0];
                float2 q1 = *(const float2*)&residual[o1];
                v00 = q0.x + v00 * mk0; v01 = q0.y + v01 * mk0;
                v10 = q1.x + v10 * mk1; v11 = q1.y + v11 * mk1;
            } else if (MODE == 4) {
                float2 p0 = *(const float2*)&g_p1[(size_t)sr0 * Dn + cg];
                float2 p1 = *(const float2*)&g_p1[(size_t)sr1 * Dn + cg];
                float2 q0 = *(const float2*)&g_p3[(size_t)dr0 * Dn + cg];
                float2 q1 = *(const float2*)&g_p3[(size_t)dr1 * Dn + cg];
                v00 = silu_f(v00 + p0.x + q0.x); v01 = silu_f(v01 + p0.y + q0.y);
                v10 = silu_f(v10 + p1.x + q1.x); v11 = silu_f(v11 + p1.y + q1.y);
            }
            if (OBF16) {
                store_pair(outh, outl, o0, v00, v01);
                store_pair(outh, outl, o1, v10, v11);
            } else {
                *(float2*)&out[o0] = make_float2(v00, v01);
                *(float2*)&out[o1] = make_float2(v10, v11);
            }
        }
    }
}

// ---------------- layernorm over last dim (256) ------------------------------
__global__ void ln_kernel(const float* __restrict__ x,
                          const float* __restrict__ gamma,
                          const float* __restrict__ beta,
                          float* __restrict__ out) {
    int v = blockIdx.x, t = threadIdx.x;
    float val = x[(size_t)v * Dn + t];
    float s = val, s2 = val * val;
    #pragma unroll
    for (int o = 16; o > 0; o >>= 1) {
        s  += __shfl_xor_sync(0xffffffffu, s,  o);
        s2 += __shfl_xor_sync(0xffffffffu, s2, o);
    }
    __shared__ float ws[8], ws2[8];
    int w = t >> 5;
    if ((t & 31) == 0) { ws[w] = s; ws2[w] = s2; }
    __syncthreads();
    if (t == 0) {
        float a = 0.0f, b = 0.0f;
        #pragma unroll
        for (int i = 0; i < 8; i++) { a += ws[i]; b += ws2[i]; }
        ws[0] = a; ws2[0] = b;
    }
    __syncthreads();
    float mean = ws[0] * (1.0f / 256.0f);
    float var  = ws2[0] * (1.0f / 256.0f) - mean * mean;
    out[(size_t)v * Dn + t] = (val - mean) * rsqrtf(var + 1e-5f) * gamma[t] + beta[t];
}

// ---------------- launch ------------------------------------------------------
extern "C" void kernel_launch(void* const* d_in, const int* in_sizes, int n_in,
                              void* d_out, int out_size) {
    const float* node_feat = (const float*)d_in[0];
    const float* edge_feat = (const float*)d_in[1];
    const int*   edge_index = (const int*)d_in[2];
    const void*  node_mask = d_in[3];
    const void*  edge_mask = d_in[4];
    const float* tw1 = (const float*)d_in[5];
    const float* tb1 = (const float*)d_in[6];
    const float* tw2 = (const float*)d_in[7];
    const float* tb2 = (const float*)d_in[8];
    const float* nw1 = (const float*)d_in[9];
    const float* nb1 = (const float*)d_in[10];
    const float* nw2 = (const float*)d_in[11];
    const float* nb2 = (const float*)d_in[12];
    const float* ew1 = (const float*)d_in[13];
    const float* eb1 = (const float*)d_in[14];
    const float* ew2 = (const float*)d_in[15];
    const float* eb2 = (const float*)d_in[16];
    const float* gamma = (const float*)d_in[17];
    const float* beta  = (const float*)d_in[18];

    float* out = (float*)d_out;

    float *hidden, *msg, *agg, *hn, *node, *cnt, *p1, *p3, *zb;
    __nv_bfloat16 *wth, *wtl;
    cudaGetSymbolAddress((void**)&hidden, g_buf1);
    cudaGetSymbolAddress((void**)&msg,    g_msg);
    cudaGetSymbolAddress((void**)&agg,    g_agg);
    cudaGetSymbolAddress((void**)&hn,     g_hn);
    cudaGetSymbolAddress((void**)&node,   g_node);
    cudaGetSymbolAddress((void**)&cnt,    g_cnt);
    cudaGetSymbolAddress((void**)&p1,     g_p1);
    cudaGetSymbolAddress((void**)&p3,     g_p3);
    cudaGetSymbolAddress((void**)&zb,     g_zero256);
    cudaGetSymbolAddress((void**)&wth,    g_wth);
    cudaGetSymbolAddress((void**)&wtl,    g_wtl);

    // bf16 hi/lo aliases over fp32 scratch
    __nv_bfloat16* hidh = (__nv_bfloat16*)hidden;
    __nv_bfloat16* hidl = hidh + (size_t)ME * Dn;
    __nv_bfloat16* msgh = (__nv_bfloat16*)msg;
    __nv_bfloat16* msgl = msgh + (size_t)ME * Dn;
    __nv_bfloat16* hnh  = (__nv_bfloat16*)hn;
    __nv_bfloat16* hnl  = hnh + (size_t)MN * Dn;

    cudaFuncSetAttribute(gemm_tc<5, false, false, false>, cudaFuncAttributeMaxDynamicSharedMemorySize, SMEM_TOTAL);
    cudaFuncSetAttribute(gemm_tc<4, false, false, true >, cudaFuncAttributeMaxDynamicSharedMemorySize, SMEM_TOTAL);
    cudaFuncSetAttribute(gemm_tc<1, false, true , true >, cudaFuncAttributeMaxDynamicSharedMemorySize, SMEM_TOTAL);
    cudaFuncSetAttribute(gemm_tc<0, false, true , true >, cudaFuncAttributeMaxDynamicSharedMemorySize, SMEM_TOTAL);
    cudaFuncSetAttribute(gemm_tc<2, false, true , false>, cudaFuncAttributeMaxDynamicSharedMemorySize, SMEM_TOTAL);
    cudaFuncSetAttribute(gemm_tc<0, true , false, true >, cudaFuncAttributeMaxDynamicSharedMemorySize, SMEM_TOTAL);
    cudaFuncSetAttribute(gemm_tc<3, false, true , false>, cudaFuncAttributeMaxDynamicSharedMemorySize, SMEM_TOTAL);

    // 0) mask dtype + zero scratch
    sniff_mask_dtype<<<1, 1>>>((const unsigned int*)edge_mask);
    cudaMemsetAsync(agg, 0, (size_t)MN * Dn * sizeof(float));
    cudaMemsetAsync(cnt, 0, (size_t)MN * sizeof(float));
    // 1) all weight transposes + bf16 hi/lo splits in one launch
    WSrcs ws;
    ws.p[0] = tw1;          ws.p[1] = tw1 + 65536;  ws.p[2] = tw1 + 131072;
    ws.p[3] = tw2;          ws.p[4] = ew1;          ws.p[5] = ew2;
    ws.p[6] = nw1;          ws.p[7] = nw2;
    prep_weights_all<<<dim3(8, 8, 8), dim3(32, 8)>>>(ws, wth, wtl);
    // 2) edge metadata + node masks
    prep_edges<<<ME / 256, 256>>>(edge_index, edge_mask);
    prep_nodes<<<MN / 256, 256>>>(node_mask);

    dim3 ge(2, ME / 128);
    dim3 gn(2, MN / 128);
    // 3) P1 = node_feat @ W1a, P3 = node_feat @ W1c  (fp32 out)
    gemm_tc<5, false, false, false><<<gn, 256, SMEM_TOTAL>>>(
        node_feat, nullptr, nullptr, wth + OW_T1A, wtl + OW_T1A, zb, nullptr, p1, nullptr, nullptr);
    gemm_tc<5, false, false, false><<<gn, 256, SMEM_TOTAL>>>(
        node_feat, nullptr, nullptr, wth + OW_T1C, wtl + OW_T1C, zb, nullptr, p3, nullptr, nullptr);
    // 4) triplet layer1: silu(edge@W1b + P1[src] + P3[dst] + tb1) -> hidden (bf16 pair)
    gemm_tc<4, false, false, true ><<<ge, 256, SMEM_TOTAL>>>(
        edge_feat, nullptr, nullptr, wth + OW_T1B, wtl + OW_T1B, tb1, nullptr, nullptr, hidh, hidl);
    // 5) msg = (hidden@tw2+tb2)*mask -> bf16 pair + fp32 atomics to agg
    gemm_tc<1, false, true , true ><<<ge, 256, SMEM_TOTAL>>>(
        nullptr, hidh, hidl, wth + OW_TW2, wtl + OW_TW2, tb2, nullptr, nullptr, msgh, msgl);
    // 6) edge update layer1 (silu) -> hidden (bf16 pair)
    gemm_tc<0, false, true , true ><<<ge, 256, SMEM_TOTAL>>>(
        nullptr, msgh, msgl, wth + OW_EW1, wtl + OW_EW1, eb1, nullptr, nullptr, hidh, hidl);
    // 7) edge_out = edge_feat + layer2  (fp32 out)
    gemm_tc<2, false, true , false><<<ge, 256, SMEM_TOTAL>>>(
        nullptr, hidh, hidl, wth + OW_EW2, wtl + OW_EW2, eb2, edge_feat,
        out + (size_t)MN * Dn, nullptr, nullptr);
    // 8) node layer1 on agg*invc (silu) -> hn (bf16 pair)
    gemm_tc<0, true , false, true ><<<gn, 256, SMEM_TOTAL>>>(
        agg, nullptr, nullptr, wth + OW_NW1, wtl + OW_NW1, nb1, nullptr, nullptr, hnh, hnl);
    // 9) node = node_feat + layer2 * node_mask (fp32)
    gemm_tc<3, false, true , false><<<gn, 256, SMEM_TOTAL>>>(
        nullptr, hnh, hnl, wth + OW_NW2, wtl + OW_NW2, nb2, node_feat, node, nullptr, nullptr);
    // 10) layernorm
    ln_kernel<<<MN, 256>>>(node, gamma, beta, out);
}

// round 9
// speedup vs baseline: 3.9843x; 1.2570x over previous
#include <cuda_runtime.h>
#include <cuda_bf16.h>
#include <cstdint>
#include <math.h>

// Problem constants
#define Bn 16
#define Nn 1024
#define En 16384
#define Dn 256
constexpr int ME = Bn * En;   // 262144 edge rows
constexpr int MN = Bn * Nn;   // 16384 node rows

// ============================ PTX helpers (sm_80-compatible only) ===========
__device__ __forceinline__ uint32_t smem_u32(const void* p) {
    uint32_t a;
    asm("{ .reg .u64 t; cvta.to.shared.u64 t, %1; cvt.u32.u64 %0, t; }"
        : "=r"(a) : "l"(p));
    return a;
}

#define LDSM4(r, addr) \
    asm volatile("ldmatrix.sync.aligned.m8n8.x4.shared.b16 {%0,%1,%2,%3}, [%4];" \
        : "=r"((r)[0]), "=r"((r)[1]), "=r"((r)[2]), "=r"((r)[3]) : "r"(addr))

#define MMA_BF16(d, a, b) \
    asm volatile("mma.sync.aligned.m16n8k16.row.col.f32.bf16.bf16.f32 " \
        "{%0,%1,%2,%3}, {%4,%5,%6,%7}, {%8,%9}, {%0,%1,%2,%3};" \
        : "+f"((d)[0]), "+f"((d)[1]), "+f"((d)[2]), "+f"((d)[3]) \
        : "r"((a)[0]), "r"((a)[1]), "r"((a)[2]), "r"((a)[3]), \
          "r"((b)[0]), "r"((b)[1]))

#define CP_ASYNC16(dst, src) \
    asm volatile("cp.async.cg.shared.global [%0], [%1], 16;" :: "r"(dst), "l"(src))
#define CP_COMMIT asm volatile("cp.async.commit_group;" ::: "memory")
#define CP_WAIT0  asm volatile("cp.async.wait_group 0;" ::: "memory")

#define RED_ADD_V2(p, a, b) \
    asm volatile("red.global.add.v2.f32 [%0], {%1,%2};" :: "l"(p), "f"(a), "f"(b) : "memory")

#define SW128(x) ((x) ^ (((x) >> 3) & 0x70))

// ============================ scratch globals ================================
__device__ float g_buf1[(size_t)ME * Dn];   // hidden (bf16 hi/lo pair alias)
__device__ float g_msg [(size_t)ME * Dn];   // msg    (bf16 hi/lo pair alias)
__device__ float g_efs [(size_t)ME * Dn];   // edge_feat pre-split (bf16 pair)
__device__ float g_agg [(size_t)MN * Dn];   // fp32 (atomics)
__device__ float g_hn  [(size_t)MN * Dn];   // hn     (bf16 hi/lo pair alias)
__device__ float g_node[(size_t)MN * Dn];   // fp32 pre-LN
__device__ float g_p1  [(size_t)MN * Dn];   // node_feat @ W1a (fp32)
__device__ float g_p3  [(size_t)MN * Dn];   // node_feat @ W1c (fp32)
__device__ float g_cnt [MN];
__device__ float g_invc[MN];
__device__ int   g_srcrow[ME];
__device__ int   g_dstrow[ME];
__device__ float g_maskf [ME];
__device__ float g_nmaskf[MN];
__device__ int   g_mask_dt;
__device__ float g_zero256[256];
// pre-transposed + bf16-split weights, 8 matrices of [256][256]
__device__ __nv_bfloat16 g_wth[524288];
__device__ __nv_bfloat16 g_wtl[524288];
constexpr size_t OW_T1A = 0,      OW_T1B = 65536,  OW_T1C = 131072,
                 OW_TW2 = 196608, OW_EW1 = 262144, OW_EW2 = 327680,
                 OW_NW1 = 393216, OW_NW2 = 458752;

__device__ __forceinline__ float silu_f(float x) { return x / (1.0f + __expf(-x)); }

__device__ __forceinline__ float read_mask(const void* p, int i, int dt) {
    if (dt == 0) return ((const float*)p)[i];
    if (dt == 1) return ((const unsigned char*)p)[i] ? 1.0f : 0.0f;
    return ((const int*)p)[i] ? 1.0f : 0.0f;
}

__device__ __forceinline__ void split_bf16x4(float4 v, uint2& hi, uint2& lo) {
    __nv_bfloat162 h01 = __floats2bfloat162_rn(v.x, v.y);
    __nv_bfloat162 h23 = __floats2bfloat162_rn(v.z, v.w);
    float2 f01 = __bfloat1622float2(h01);
    float2 f23 = __bfloat1622float2(h23);
    __nv_bfloat162 l01 = __floats2bfloat162_rn(v.x - f01.x, v.y - f01.y);
    __nv_bfloat162 l23 = __floats2bfloat162_rn(v.z - f23.x, v.w - f23.y);
    hi.x = *(uint32_t*)&h01; hi.y = *(uint32_t*)&h23;
    lo.x = *(uint32_t*)&l01; lo.y = *(uint32_t*)&l23;
}

// ---------------- small prep kernels ----------------------------------------
__global__ void sniff_mask_dtype(const unsigned int* __restrict__ m) {
    bool big_byte = false, upper = false;
    for (int i = 0; i < 16; i++) {
        unsigned int w = m[i];
        unsigned char b0 = w & 0xff, b1 = (w >> 8) & 0xff,
                      b2 = (w >> 16) & 0xff, b3 = (w >> 24) & 0xff;
        if (b0 >= 2 || b1 >= 2 || b2 >= 2 || b3 >= 2) big_byte = true;
        if (b1 | b2 | b3) upper = true;
    }
    g_mask_dt = big_byte ? 0 : (upper ? 1 : 2);
}

__global__ void prep_edges(const int* __restrict__ edge_index,
                           const void* __restrict__ edge_mask) {
    int r = blockIdx.x * blockDim.x + threadIdx.x;
    if (r >= ME) return;
    int dt = g_mask_dt;
    int b = r >> 14;
    int e = r & (En - 1);
    int src = edge_index[(size_t)b * 2 * En + e];
    int dst = edge_index[(size_t)b * 2 * En + En + e];
    float m = (read_mask(edge_mask, r, dt) != 0.0f) ? 1.0f : 0.0f;
    g_srcrow[r] = b * Nn + src;
    g_dstrow[r] = b * Nn + dst;
    g_maskf[r]  = m;
    if (m != 0.0f) atomicAdd(&g_cnt[b * Nn + dst], 1.0f);
}

__global__ void prep_nodes(const void* __restrict__ node_mask) {
    int v = blockIdx.x * blockDim.x + threadIdx.x;
    if (v >= MN) return;
    g_invc[v]   = 1.0f / fmaxf(g_cnt[v], 1.0f);
    g_nmaskf[v] = (read_mask(node_mask, v, g_mask_dt) != 0.0f) ? 1.0f : 0.0f;
}

// elementwise fp32 -> bf16 hi/lo pair split (for edge_feat)
__global__ void split_pair(const float4* __restrict__ src,
                           uint2* __restrict__ dsth, uint2* __restrict__ dstl) {
    int i = blockIdx.x * blockDim.x + threadIdx.x;
    uint2 hi, lo;
    split_bf16x4(src[i], hi, lo);
    dsth[i] = hi;
    dstl[i] = lo;
}

// All 8 weight transposes in one launch; smem-tile coalesced.
struct WSrcs { const float* p[8]; };
__global__ void prep_weights_all(WSrcs srcs,
                                 __nv_bfloat16* __restrict__ wth,
                                 __nv_bfloat16* __restrict__ wtl) {
    __shared__ float tile[32][33];
    const float* src = srcs.p[blockIdx.z];
    int kt = blockIdx.x * 32, nt = blockIdx.y * 32;
    #pragma unroll
    for (int i = threadIdx.y; i < 32; i += 8)
        tile[i][threadIdx.x] = src[(size_t)(kt + i) * 256 + nt + threadIdx.x];
    __syncthreads();
    size_t base = (size_t)blockIdx.z * 65536;
    #pragma unroll
    for (int i = threadIdx.y; i < 32; i += 8) {
        int n = nt + i, k = kt + threadIdx.x;
        float v = tile[threadIdx.x][i];
        __nv_bfloat16 h = __float2bfloat16_rn(v);
        wth[base + (size_t)n * 256 + k] = h;
        wtl[base + (size_t)n * 256 + k] = __float2bfloat16_rn(v - __bfloat162float(h));
    }
}

// ============================ tensor-core GEMM (mma.sync) ====================
// out[M,256] = A[M,256] @ W[256,256] via bf16x3 (AhiBhi + AloBhi + AhiBlo).
// Block tile 128x128, 8 warps (2M x 4N), warp tile 64x32 (4x4 m16n8k16).
// A double-buffered (cp.async or LDG+split), B single-buffered (L2-resident).
// occupancy 2 (97KB smem, 128-reg cap).
// MODE 0: silu(D+b)                (SCALE: rows of fp32 A scaled by g_invc)
// MODE 1: v=(D+b)*maskf; store pair; red.v2 fp32 to g_agg[dstrow]
// MODE 2: residual + (D+b)             (fp32 out)
// MODE 3: residual + (D+b)*g_nmaskf    (fp32 out)
// MODE 4: silu(D + b + g_p1[srcrow] + g_p3[dstrow])
// MODE 5: plain store (bias zero). DUAL: blockIdx.z picks (W,out) set 1/2.

constexpr int SM_BIAS  = 0;      // 128 f32
constexpr int SM_SCALE = 512;    // 128 f32
constexpr int SM_AH    = 1024;   // [2][16384]
constexpr int SM_AL    = 33792;  // [2][16384]
constexpr int SM_BH    = 66560;  // [16384]
constexpr int SM_BL    = 82944;  // [16384]
constexpr int SMEM_TOTAL = 99328;

__device__ __forceinline__ void store_pair(__nv_bfloat16* outh, __nv_bfloat16* outl,
                                           size_t o, float a, float b) {
    __nv_bfloat162 h = __floats2bfloat162_rn(a, b);
    float2 hf = __bfloat1622float2(h);
    __nv_bfloat162 l = __floats2bfloat162_rn(a - hf.x, b - hf.y);
    *(__nv_bfloat162*)&outh[o] = h;
    *(__nv_bfloat162*)&outl[o] = l;
}

template<int MODE, bool SCALE, bool ABF16, bool OBF16, bool DUAL>
__global__ void __launch_bounds__(256, 2)
gemm_tc(const float* __restrict__ A,                 // fp32 A (when !ABF16)
        const __nv_bfloat16* __restrict__ Ah,        // bf16 A pair (when ABF16)
        const __nv_bfloat16* __restrict__ Al,
        const __nv_bfloat16* WTh,                    // [256][256]
        const __nv_bfloat16* WTl,
        const __nv_bfloat16* WTh2,                   // DUAL second set
        const __nv_bfloat16* WTl2,
        const float* __restrict__ bias,
        const float* __restrict__ residual,
        float* out,
        float* out2,
        __nv_bfloat16* __restrict__ outh,
        __nv_bfloat16* __restrict__ outl) {
    extern __shared__ __align__(1024) char sm[];
    const uint32_t smb = smem_u32(sm);
    const int tid  = threadIdx.x;
    const int wid  = tid >> 5;
    const int lane = tid & 31;
    const int row0 = blockIdx.y * 128;
    const int col0 = blockIdx.x * 128;
    const int wm = (wid & 1) * 64;
    const int wn = (wid >> 1) * 32;

    if (DUAL && blockIdx.z == 1) { WTh = WTh2; WTl = WTl2; out = out2; }

    if (tid < 128) {
        ((float*)(sm + SM_BIAS))[tid] = bias[col0 + tid];
        if (SCALE) ((float*)(sm + SM_SCALE))[tid] = g_invc[row0 + tid];
    }
    __syncthreads();

    const float* s_scale = (const float*)(sm + SM_SCALE);

    // ldmatrix lane addressing
    const int grp = lane >> 3, lr = lane & 7;
    const uint32_t kadd = (grp >> 1) * 16;
    uint32_t saA[4], xaA[4], saB[2], xaB[2];
    #pragma unroll
    for (int mi = 0; mi < 4; mi++) {
        int r = wm + mi * 16 + (grp & 1) * 8 + lr;
        saA[mi] = (uint32_t)r * 128;
        xaA[mi] = (uint32_t)(r & 7) << 4;
    }
    #pragma unroll
    for (int nj = 0; nj < 2; nj++) {
        int r = wn + nj * 16 + (grp & 1) * 8 + lr;
        saB[nj] = (uint32_t)r * 128;
        xaB[nj] = (uint32_t)(r & 7) << 4;
    }

    float acc[4][4][4] = {};
    float4 pa[4][2];

    auto ldgA = [&](int k0) {
        #pragma unroll
        for (int i = 0; i < 4; i++) {
            int idx = tid + i * 256;
            int ar = idx >> 3;
            int c8 = (idx & 7) * 8;
            size_t off = (size_t)(row0 + ar) * Dn + k0 + c8;
            pa[i][0] = *(const float4*)&A[off];
            pa[i][1] = *(const float4*)&A[off + 4];
        }
    };
    auto stsA = [&](int buf) {
        char* ah = sm + SM_AH + buf * 16384;
        char* al = sm + SM_AL + buf * 16384;
        #pragma unroll
        for (int i = 0; i < 4; i++) {
            int idx = tid + i * 256;
            int ar = idx >> 3;
            int c8 = (idx & 7) * 8;
            float4 v0 = pa[i][0], v1 = pa[i][1];
            if (SCALE) {
                float s = s_scale[ar];
                v0.x *= s; v0.y *= s; v0.z *= s; v0.w *= s;
                v1.x *= s; v1.y *= s; v1.z *= s; v1.w *= s;
            }
            uint2 h0, l0, h1, l1;
            split_bf16x4(v0, h0, l0);
            split_bf16x4(v1, h1, l1);
            uint32_t boff = SW128((uint32_t)(ar * 128 + c8 * 2));
            *(uint4*)(ah + boff) = make_uint4(h0.x, h0.y, h1.x, h1.y);
            *(uint4*)(al + boff) = make_uint4(l0.x, l0.y, l1.x, l1.y);
        }
    };
    auto cpA = [&](int k0, int buf) {
        uint32_t ah = smb + SM_AH + buf * 16384;
        uint32_t al = smb + SM_AL + buf * 16384;
        #pragma unroll
        for (int i = 0; i < 4; i++) {
            int idx = tid + i * 256;
            int r = idx >> 3, j = idx & 7;
            uint32_t boff = SW128((uint32_t)(r * 128 + j * 16));
            size_t go = (size_t)(row0 + r) * Dn + k0 + j * 8;
            CP_ASYNC16(ah + boff, Ah + go);
            CP_ASYNC16(al + boff, Al + go);
        }
    };
    auto cpB = [&](int k0) {
        uint32_t bh = smb + SM_BH;
        uint32_t bl = smb + SM_BL;
        #pragma unroll
        for (int i = 0; i < 4; i++) {
            int idx = tid + i * 256;
            int n = idx >> 3, j = idx & 7;
            uint32_t boff = SW128((uint32_t)(n * 128 + j * 16));
            size_t go = (size_t)(col0 + n) * Dn + k0 + j * 8;
            CP_ASYNC16(bh + boff, WTh + go);
            CP_ASYNC16(bl + boff, WTl + go);
        }
    };
    auto compute = [&](int buf) {
        uint32_t abh = smb + SM_AH + buf * 16384;
        uint32_t abl = smb + SM_AL + buf * 16384;
        uint32_t bbh = smb + SM_BH;
        uint32_t bbl = smb + SM_BL;
        #pragma unroll
        for (int ks = 0; ks < 4; ks++) {
            uint32_t kx = ks * 32 + kadd;
            uint32_t ahi[4][4], alo[4][4], bhi[4][2];
            #pragma unroll
            for (int mi = 0; mi < 4; mi++) {
                LDSM4(ahi[mi], abh + saA[mi] + (kx ^ xaA[mi]));
                LDSM4(alo[mi], abl + saA[mi] + (kx ^ xaA[mi]));
            }
            #pragma unroll
            for (int nj = 0; nj < 2; nj++) {
                uint32_t r[4];
                LDSM4(r, bbh + saB[nj] + (kx ^ xaB[nj]));
                bhi[nj * 2][0] = r[0]; bhi[nj * 2 + 1][0] = r[1];
                bhi[nj * 2][1] = r[2]; bhi[nj * 2 + 1][1] = r[3];
            }
            #pragma unroll
            for (int mi = 0; mi < 4; mi++)
                #pragma unroll
                for (int ni = 0; ni < 4; ni++)
                    MMA_BF16(acc[mi][ni], ahi[mi], bhi[ni]);
            #pragma unroll
            for (int mi = 0; mi < 4; mi++)
                #pragma unroll
                for (int ni = 0; ni < 4; ni++)
                    MMA_BF16(acc[mi][ni], alo[mi], bhi[ni]);
            uint32_t blo[4][2];
            #pragma unroll
            for (int nj = 0; nj < 2; nj++) {
                uint32_t r[4];
                LDSM4(r, bbl + saB[nj] + (kx ^ xaB[nj]));
                blo[nj * 2][0] = r[0]; blo[nj * 2 + 1][0] = r[1];
                blo[nj * 2][1] = r[2]; blo[nj * 2 + 1][1] = r[3];
            }
            #pragma unroll
            for (int mi = 0; mi < 4; mi++)
                #pragma unroll
                for (int ni = 0; ni < 4; ni++)
                    MMA_BF16(acc[mi][ni], ahi[mi], blo[ni]);
        }
    };

    constexpr int nT = 4;   // K = 256 in chunks of 64
    if (ABF16) cpA(0, 0); else ldgA(0);
    cpB(0);
    CP_COMMIT;
    if (!ABF16) stsA(0);
    CP_WAIT0;
    __syncthreads();

    int buf = 0;
    for (int t = 0; t < nT; t++) {
        if (t + 1 < nT) {
            if (ABF16) { cpA((t + 1) * 64, buf ^ 1); CP_COMMIT; }
            else ldgA((t + 1) * 64);
        }
        compute(buf);
        if (t + 1 < nT) {
            if (!ABF16) stsA(buf ^ 1);
            __syncthreads();             // all warps done reading B(t)
            cpB((t + 1) * 64);
            CP_COMMIT;
            CP_WAIT0;                    // A(t+1) + B(t+1) arrived
            __syncthreads();
            buf ^= 1;
        }
    }

    // ---- epilogue ---------------------------------------------------------
    const float* sb = (const float*)(sm + SM_BIAS);
    #pragma unroll
    for (int mi = 0; mi < 4; mi++) {
        int r0g = row0 + wm + mi * 16 + (lane >> 2);
        int r1g = r0g + 8;
        float mk0 = 1.0f, mk1 = 1.0f;
        int dr0 = 0, dr1 = 0, sr0 = 0, sr1 = 0;
        if (MODE == 1) {
            mk0 = g_maskf[r0g]; dr0 = g_dstrow[r0g];
            mk1 = g_maskf[r1g]; dr1 = g_dstrow[r1g];
        } else if (MODE == 3) {
            mk0 = g_nmaskf[r0g];
            mk1 = g_nmaskf[r1g];
        } else if (MODE == 4) {
            sr0 = g_srcrow[r0g]; dr0 = g_dstrow[r0g];
            sr1 = g_srcrow[r1g]; dr1 = g_dstrow[r1g];
        }
        #pragma unroll
        for (int ni = 0; ni < 4; ni++) {
            int cl = wn + ni * 8 + (lane & 3) * 2;
            int cg = col0 + cl;
            float b0 = sb[cl], b1 = sb[cl + 1];
            float v00 = acc[mi][ni][0] + b0, v01 = acc[mi][ni][1] + b1;
            float v10 = acc[mi][ni][2] + b0, v11 = acc[mi][ni][3] + b1;
            size_t o0 = (size_t)r0g * Dn + cg;
            size_t o1 = (size_t)r1g * Dn + cg;
            if (MODE == 0) {
                v00 = silu_f(v00); v01 = silu_f(v01);
                v10 = silu_f(v10); v11 = silu_f(v11);
            } else if (MODE == 1) {
                v00 *= mk0; v01 *= mk0; v10 *= mk1; v11 *= mk1;
                if (mk0 != 0.0f) RED_ADD_V2(&g_agg[(size_t)dr0 * Dn + cg], v00, v01);
                if (mk1 != 0.0f) RED_ADD_V2(&g_agg[(size_t)dr1 * Dn + cg], v10, v11);
            } else if (MODE == 2) {
                float2 q0 = *(const float2*)&residual[o0];
                float2 q1 = *(const float2*)&residual[o1];
                v00 += q0.x; v01 += q0.y; v10 += q1.x; v11 += q1.y;
            } else if (MODE == 3) {
                float2 q0 = *(const float2*)&residual[o0];
                float2 q1 = *(const float2*)&residual[o1];
                v00 = q0.x + v00 * mk0; v01 = q0.y + v01 * mk0;
                v10 = q1.x + v10 * mk1; v11 = q1.y + v11 * mk1;
            } else if (MODE == 4) {
                float2 p0 = *(const float2*)&g_p1[(size_t)sr0 * Dn + cg];
                float2 p1 = *(const float2*)&g_p1[(size_t)sr1 * Dn + cg];
                float2 q0 = *(const float2*)&g_p3[(size_t)dr0 * Dn + cg];
                float2 q1 = *(const float2*)&g_p3[(size_t)dr1 * Dn + cg];
                v00 = silu_f(v00 + p0.x + q0.x); v01 = silu_f(v01 + p0.y + q0.y);
                v10 = silu_f(v10 + p1.x + q1.x); v11 = silu_f(v11 + p1.y + q1.y);
            }
            if (OBF16) {
                store_pair(outh, outl, o0, v00, v01);
                store_pair(outh, outl, o1, v10, v11);
            } else {
                *(float2*)&out[o0] = make_float2(v00, v01);
                *(float2*)&out[o1] = make_float2(v10, v11);
            }
        }
    }
}

// ---------------- layernorm over last dim (256) ------------------------------
__global__ void ln_kernel(const float* __restrict__ x,
                          const float* __restrict__ gamma,
                          const float* __restrict__ beta,
                          float* __restrict__ out) {
    int v = blockIdx.x, t = threadIdx.x;
    float val = x[(size_t)v * Dn + t];
    float s = val, s2 = val * val;
    #pragma unroll
    for (int o = 16; o > 0; o >>= 1) {
        s  += __shfl_xor_sync(0xffffffffu, s,  o);
        s2 += __shfl_xor_sync(0xffffffffu, s2, o);
    }
    __shared__ float ws[8], ws2[8];
    int w = t >> 5;
    if ((t & 31) == 0) { ws[w] = s; ws2[w] = s2; }
    __syncthreads();
    if (t == 0) {
        float a = 0.0f, b = 0.0f;
        #pragma unroll
        for (int i = 0; i < 8; i++) { a += ws[i]; b += ws2[i]; }
        ws[0] = a; ws2[0] = b;
    }
    __syncthreads();
    float mean = ws[0] * (1.0f / 256.0f);
    float var  = ws2[0] * (1.0f / 256.0f) - mean * mean;
    out[(size_t)v * Dn + t] = (val - mean) * rsqrtf(var + 1e-5f) * gamma[t] + beta[t];
}

// ---------------- launch ------------------------------------------------------
extern "C" void kernel_launch(void* const* d_in, const int* in_sizes, int n_in,
                              void* d_out, int out_size) {
    const float* node_feat = (const float*)d_in[0];
    const float* edge_feat = (const float*)d_in[1];
    const int*   edge_index = (const int*)d_in[2];
    const void*  node_mask = d_in[3];
    const void*  edge_mask = d_in[4];
    const float* tw1 = (const float*)d_in[5];
    const float* tb1 = (const float*)d_in[6];
    const float* tw2 = (const float*)d_in[7];
    const float* tb2 = (const float*)d_in[8];
    const float* nw1 = (const float*)d_in[9];
    const float* nb1 = (const float*)d_in[10];
    const float* nw2 = (const float*)d_in[11];
    const float* nb2 = (const float*)d_in[12];
    const float* ew1 = (const float*)d_in[13];
    const float* eb1 = (const float*)d_in[14];
    const float* ew2 = (const float*)d_in[15];
    const float* eb2 = (const float*)d_in[16];
    const float* gamma = (const float*)d_in[17];
    const float* beta  = (const float*)d_in[18];

    float* out = (float*)d_out;

    float *hidden, *msg, *efs, *agg, *hn, *node, *cnt, *p1, *p3, *zb;
    __nv_bfloat16 *wth, *wtl;
    cudaGetSymbolAddress((void**)&hidden, g_buf1);
    cudaGetSymbolAddress((void**)&msg,    g_msg);
    cudaGetSymbolAddress((void**)&efs,    g_efs);
    cudaGetSymbolAddress((void**)&agg,    g_agg);
    cudaGetSymbolAddress((void**)&hn,     g_hn);
    cudaGetSymbolAddress((void**)&node,   g_node);
    cudaGetSymbolAddress((void**)&cnt,    g_cnt);
    cudaGetSymbolAddress((void**)&p1,     g_p1);
    cudaGetSymbolAddress((void**)&p3,     g_p3);
    cudaGetSymbolAddress((void**)&zb,     g_zero256);
    cudaGetSymbolAddress((void**)&wth,    g_wth);
    cudaGetSymbolAddress((void**)&wtl,    g_wtl);

    __nv_bfloat16* hidh = (__nv_bfloat16*)hidden;
    __nv_bfloat16* hidl = hidh + (size_t)ME * Dn;
    __nv_bfloat16* msgh = (__nv_bfloat16*)msg;
    __nv_bfloat16* msgl = msgh + (size_t)ME * Dn;
    __nv_bfloat16* efsh = (__nv_bfloat16*)efs;
    __nv_bfloat16* efsl = efsh + (size_t)ME * Dn;
    __nv_bfloat16* hnh  = (__nv_bfloat16*)hn;
    __nv_bfloat16* hnl  = hnh + (size_t)MN * Dn;

    cudaFuncSetAttribute(gemm_tc<5, false, false, false, true >, cudaFuncAttributeMaxDynamicSharedMemorySize, SMEM_TOTAL);
    cudaFuncSetAttribute(gemm_tc<4, false, true , true , false>, cudaFuncAttributeMaxDynamicSharedMemorySize, SMEM_TOTAL);
    cudaFuncSetAttribute(gemm_tc<1, false, true , true , false>, cudaFuncAttributeMaxDynamicSharedMemorySize, SMEM_TOTAL);
    cudaFuncSetAttribute(gemm_tc<0, false, true , true , false>, cudaFuncAttributeMaxDynamicSharedMemorySize, SMEM_TOTAL);
    cudaFuncSetAttribute(gemm_tc<2, false, true , false, false>, cudaFuncAttributeMaxDynamicSharedMemorySize, SMEM_TOTAL);
    cudaFuncSetAttribute(gemm_tc<0, true , false, true , false>, cudaFuncAttributeMaxDynamicSharedMemorySize, SMEM_TOTAL);
    cudaFuncSetAttribute(gemm_tc<3, false, true , false, false>, cudaFuncAttributeMaxDynamicSharedMemorySize, SMEM_TOTAL);

    // zero scratch first (memset nodes, not kernels)
    cudaMemsetAsync(agg, 0, (size_t)MN * Dn * sizeof(float));
    cudaMemsetAsync(cnt, 0, (size_t)MN * sizeof(float));

    // kernels (ordered so ncu -s 5 -c 1 captures the triplet edge GEMM)
    sniff_mask_dtype<<<1, 1>>>((const unsigned int*)edge_mask);           // 1
    WSrcs ws;
    ws.p[0] = tw1;          ws.p[1] = tw1 + 65536;  ws.p[2] = tw1 + 131072;
    ws.p[3] = tw2;          ws.p[4] = ew1;          ws.p[5] = ew2;
    ws.p[6] = nw1;          ws.p[7] = nw2;
    prep_weights_all<<<dim3(8, 8, 8), dim3(32, 8)>>>(ws, wth, wtl);       // 2
    split_pair<<<(ME * Dn / 4) / 256, 256>>>((const float4*)edge_feat,
                                             (uint2*)efsh, (uint2*)efsl); // 3
    prep_edges<<<ME / 256, 256>>>(edge_index, edge_mask);                 // 4

    dim3 ge(2, ME / 128);
    dim3 gn(2, MN / 128);
    dim3 gn2(2, MN / 128, 2);
    // 5: P1 = nf @ W1a (z=0), P3 = nf @ W1c (z=1)
    gemm_tc<5, false, false, false, true ><<<gn2, 256, SMEM_TOTAL>>>(
        node_feat, nullptr, nullptr, wth + OW_T1A, wtl + OW_T1A,
        wth + OW_T1C, wtl + OW_T1C, zb, nullptr, p1, p3, nullptr, nullptr);
    // 6: triplet layer1: silu(ef@W1b + P1[src] + P3[dst] + tb1) -> hidden pair
    gemm_tc<4, false, true , true , false><<<ge, 256, SMEM_TOTAL>>>(
        nullptr, efsh, efsl, wth + OW_T1B, wtl + OW_T1B, nullptr, nullptr,
        tb1, nullptr, nullptr, nullptr, hidh, hidl);
    // 7: msg = (hidden@tw2+tb2)*mask -> pair + red.v2 to agg
    gemm_tc<1, false, true , true , false><<<ge, 256, SMEM_TOTAL>>>(
        nullptr, hidh, hidl, wth + OW_TW2, wtl + OW_TW2, nullptr, nullptr,
        tb2, nullptr, nullptr, nullptr, msgh, msgl);
    // 8: invc + node mask (needs cnt complete)
    prep_nodes<<<MN / 256, 256>>>(node_mask);
    // 9: edge update layer1 (silu) -> hidden pair
    gemm_tc<0, false, true , true , false><<<ge, 256, SMEM_TOTAL>>>(
        nullptr, msgh, msgl, wth + OW_EW1, wtl + OW_EW1, nullptr, nullptr,
        eb1, nullptr, nullptr, nullptr, hidh, hidl);
    // 10: edge_out = edge_feat + layer2 (fp32)
    gemm_tc<2, false, true , false, false><<<ge, 256, SMEM_TOTAL>>>(
        nullptr, hidh, hidl, wth + OW_EW2, wtl + OW_EW2, nullptr, nullptr,
        eb2, edge_feat, out + (size_t)MN * Dn, nullptr, nullptr, nullptr);
    // 11: node layer1 on agg*invc (silu) -> hn pair
    gemm_tc<0, true , false, true , false><<<gn, 256, SMEM_TOTAL>>>(
        agg, nullptr, nullptr, wth + OW_NW1, wtl + OW_NW1, nullptr, nullptr,
        nb1, nullptr, nullptr, nullptr, hnh, hnl);
    // 12: node = node_feat + layer2 * node_mask (fp32)
    gemm_tc<3, false, true , false, false><<<gn, 256, SMEM_TOTAL>>>(
        nullptr, hnh, hnl, wth + OW_NW2, wtl + OW_NW2, nullptr, nullptr,
        nb2, node_feat, node, nullptr, nullptr, nullptr);
    // 13: layernorm
    ln_kernel<<<MN, 256>>>(node, gamma, beta, out);
}

// round 10
// speedup vs baseline: 4.0734x; 1.0224x over previous
#include <cuda_runtime.h>
#include <cuda_bf16.h>
#include <cstdint>
#include <math.h>

// Problem constants
#define Bn 16
#define Nn 1024
#define En 16384
#define Dn 256
constexpr int ME = Bn * En;   // 262144 edge rows
constexpr int MN = Bn * Nn;   // 16384 node rows

// ============================ PTX helpers (sm_80-compatible only) ===========
__device__ __forceinline__ uint32_t smem_u32(const void* p) {
    uint32_t a;
    asm("{ .reg .u64 t; cvta.to.shared.u64 t, %1; cvt.u32.u64 %0, t; }"
        : "=r"(a) : "l"(p));
    return a;
}

#define LDSM4(r, addr) \
    asm volatile("ldmatrix.sync.aligned.m8n8.x4.shared.b16 {%0,%1,%2,%3}, [%4];" \
        : "=r"((r)[0]), "=r"((r)[1]), "=r"((r)[2]), "=r"((r)[3]) : "r"(addr))

#define MMA_BF16(d, a, b) \
    asm volatile("mma.sync.aligned.m16n8k16.row.col.f32.bf16.bf16.f32 " \
        "{%0,%1,%2,%3}, {%4,%5,%6,%7}, {%8,%9}, {%0,%1,%2,%3};" \
        : "+f"((d)[0]), "+f"((d)[1]), "+f"((d)[2]), "+f"((d)[3]) \
        : "r"((a)[0]), "r"((a)[1]), "r"((a)[2]), "r"((a)[3]), \
          "r"((b)[0]), "r"((b)[1]))

#define CP_ASYNC16(dst, src) \
    asm volatile("cp.async.cg.shared.global [%0], [%1], 16;" :: "r"(dst), "l"(src))
#define CP_COMMIT asm volatile("cp.async.commit_group;" ::: "memory")
#define CP_WAIT0  asm volatile("cp.async.wait_group 0;" ::: "memory")

#define RED_ADD_V2(p, a, b) \
    asm volatile("red.global.add.v2.f32 [%0], {%1,%2};" :: "l"(p), "f"(a), "f"(b) : "memory")

#define SW128(x) ((x) ^ (((x) >> 3) & 0x70))

// ============================ scratch globals ================================
__device__ float g_buf1[(size_t)ME * Dn];   // hidden (bf16 hi/lo pair alias)
__device__ float g_msg [(size_t)ME * Dn];   // msg    (bf16 hi/lo pair alias)
__device__ float g_agg [(size_t)MN * Dn];   // fp32 (atomics)
__device__ float g_hn  [(size_t)MN * Dn];   // hn     (bf16 hi/lo pair alias)
__device__ float g_node[(size_t)MN * Dn];   // fp32 pre-LN
__device__ float g_p1  [(size_t)MN * Dn];   // node_feat @ W1a (fp32)
__device__ float g_p3  [(size_t)MN * Dn];   // node_feat @ W1c (fp32)
__device__ float g_cnt [MN];
__device__ float g_invc[MN];
__device__ int   g_srcrow[ME];
__device__ int   g_dstrow[ME];
__device__ float g_maskf [ME];
__device__ float g_nmaskf[MN];
__device__ int   g_mask_dt;
__device__ float g_zero256[256];
// pre-transposed + bf16-split weights, 8 matrices of [256][256]
__device__ __nv_bfloat16 g_wth[524288];
__device__ __nv_bfloat16 g_wtl[524288];
constexpr size_t OW_T1A = 0,      OW_T1B = 65536,  OW_T1C = 131072,
                 OW_TW2 = 196608, OW_EW1 = 262144, OW_EW2 = 327680,
                 OW_NW1 = 393216, OW_NW2 = 458752;

__device__ __forceinline__ float silu_f(float x) { return x / (1.0f + __expf(-x)); }

__device__ __forceinline__ float read_mask(const void* p, int i, int dt) {
    if (dt == 0) return ((const float*)p)[i];
    if (dt == 1) return ((const unsigned char*)p)[i] ? 1.0f : 0.0f;
    return ((const int*)p)[i] ? 1.0f : 0.0f;
}

__device__ __forceinline__ void split_bf16x4(float4 v, uint2& hi, uint2& lo) {
    __nv_bfloat162 h01 = __floats2bfloat162_rn(v.x, v.y);
    __nv_bfloat162 h23 = __floats2bfloat162_rn(v.z, v.w);
    float2 f01 = __bfloat1622float2(h01);
    float2 f23 = __bfloat1622float2(h23);
    __nv_bfloat162 l01 = __floats2bfloat162_rn(v.x - f01.x, v.y - f01.y);
    __nv_bfloat162 l23 = __floats2bfloat162_rn(v.z - f23.x, v.w - f23.y);
    hi.x = *(uint32_t*)&h01; hi.y = *(uint32_t*)&h23;
    lo.x = *(uint32_t*)&l01; lo.y = *(uint32_t*)&l23;
}

// ---------------- small prep kernels ----------------------------------------
__global__ void sniff_mask_dtype(const unsigned int* __restrict__ m) {
    bool big_byte = false, upper = false;
    for (int i = 0; i < 16; i++) {
        unsigned int w = m[i];
        unsigned char b0 = w & 0xff, b1 = (w >> 8) & 0xff,
                      b2 = (w >> 16) & 0xff, b3 = (w >> 24) & 0xff;
        if (b0 >= 2 || b1 >= 2 || b2 >= 2 || b3 >= 2) big_byte = true;
        if (b1 | b2 | b3) upper = true;
    }
    g_mask_dt = big_byte ? 0 : (upper ? 1 : 2);
}

__global__ void prep_edges(const int* __restrict__ edge_index,
                           const void* __restrict__ edge_mask) {
    int r = blockIdx.x * blockDim.x + threadIdx.x;
    if (r >= ME) return;
    int dt = g_mask_dt;
    int b = r >> 14;
    int e = r & (En - 1);
    int src = edge_index[(size_t)b * 2 * En + e];
    int dst = edge_index[(size_t)b * 2 * En + En + e];
    float m = (read_mask(edge_mask, r, dt) != 0.0f) ? 1.0f : 0.0f;
    g_srcrow[r] = b * Nn + src;
    g_dstrow[r] = b * Nn + dst;
    g_maskf[r]  = m;
    if (m != 0.0f) atomicAdd(&g_cnt[b * Nn + dst], 1.0f);
}

__global__ void prep_nodes(const void* __restrict__ node_mask) {
    int v = blockIdx.x * blockDim.x + threadIdx.x;
    if (v >= MN) return;
    g_invc[v]   = 1.0f / fmaxf(g_cnt[v], 1.0f);
    g_nmaskf[v] = (read_mask(node_mask, v, g_mask_dt) != 0.0f) ? 1.0f : 0.0f;
}

// All 8 weight transposes in one launch; smem-tile coalesced.
struct WSrcs { const float* p[8]; };
__global__ void prep_weights_all(WSrcs srcs,
                                 __nv_bfloat16* __restrict__ wth,
                                 __nv_bfloat16* __restrict__ wtl) {
    __shared__ float tile[32][33];
    const float* src = srcs.p[blockIdx.z];
    int kt = blockIdx.x * 32, nt = blockIdx.y * 32;
    #pragma unroll
    for (int i = threadIdx.y; i < 32; i += 8)
        tile[i][threadIdx.x] = src[(size_t)(kt + i) * 256 + nt + threadIdx.x];
    __syncthreads();
    size_t base = (size_t)blockIdx.z * 65536;
    #pragma unroll
    for (int i = threadIdx.y; i < 32; i += 8) {
        int n = nt + i, k = kt + threadIdx.x;
        float v = tile[threadIdx.x][i];
        __nv_bfloat16 h = __float2bfloat16_rn(v);
        wth[base + (size_t)n * 256 + k] = h;
        wtl[base + (size_t)n * 256 + k] = __float2bfloat16_rn(v - __bfloat162float(h));
    }
}

// ============================ tensor-core GEMM (mma.sync) ====================
// out[M,256] = A[M,256] @ W[256,256] via bf16x3 (AhiBhi + AloBhi + AhiBlo).
// Block tile 128x128, 8 warps (2M x 4N), warp tile 64x32 (4x4 m16n8k16).
// A double-buffered (cp.async or LDG+split-early), B single-buffered.
// occupancy 2 (97KB smem, 128-reg cap).
// MODE 0: silu(D+b)                (SCALE: rows of fp32 A scaled by g_invc)
// MODE 1: v=(D+b)*maskf; store pair; red.v2 fp32 to g_agg[dstrow]
// MODE 2: residual + (D+b)             (fp32 out)
// MODE 3: residual + (D+b)*g_nmaskf    (fp32 out)
// MODE 4: silu(D + b + g_p1[srcrow] + g_p3[dstrow])
// MODE 5: plain store (bias zero). DUAL: blockIdx.z picks (W,out) set 1/2.

constexpr int SM_BIAS  = 0;      // 128 f32
constexpr int SM_SCALE = 512;    // 128 f32
constexpr int SM_AH    = 1024;   // [2][16384]
constexpr int SM_AL    = 33792;  // [2][16384]
constexpr int SM_BH    = 66560;  // [16384]
constexpr int SM_BL    = 82944;  // [16384]
constexpr int SMEM_TOTAL = 99328;

__device__ __forceinline__ void store_pair(__nv_bfloat16* outh, __nv_bfloat16* outl,
                                           size_t o, float a, float b) {
    __nv_bfloat162 h = __floats2bfloat162_rn(a, b);
    float2 hf = __bfloat1622float2(h);
    __nv_bfloat162 l = __floats2bfloat162_rn(a - hf.x, b - hf.y);
    *(__nv_bfloat162*)&outh[o] = h;
    *(__nv_bfloat162*)&outl[o] = l;
}

template<int MODE, bool SCALE, bool ABF16, bool OBF16, bool DUAL>
__global__ void __launch_bounds__(256, 2)
gemm_tc(const float* __restrict__ A,                 // fp32 A (when !ABF16)
        const __nv_bfloat16* __restrict__ Ah,        // bf16 A pair (when ABF16)
        const __nv_bfloat16* __restrict__ Al,
        const __nv_bfloat16* WTh,                    // [256][256]
        const __nv_bfloat16* WTl,
        const __nv_bfloat16* WTh2,                   // DUAL second set
        const __nv_bfloat16* WTl2,
        const float* __restrict__ bias,
        const float* __restrict__ residual,
        float* out,
        float* out2,
        __nv_bfloat16* __restrict__ outh,
        __nv_bfloat16* __restrict__ outl) {
    extern __shared__ __align__(1024) char sm[];
    const uint32_t smb = smem_u32(sm);
    const int tid  = threadIdx.x;
    const int wid  = tid >> 5;
    const int lane = tid & 31;
    const int row0 = blockIdx.y * 128;
    const int col0 = blockIdx.x * 128;
    const int wm = (wid & 1) * 64;
    const int wn = (wid >> 1) * 32;

    if (DUAL && blockIdx.z == 1) { WTh = WTh2; WTl = WTl2; out = out2; }

    if (tid < 128) {
        ((float*)(sm + SM_BIAS))[tid] = bias[col0 + tid];
        if (SCALE) ((float*)(sm + SM_SCALE))[tid] = g_invc[row0 + tid];
    }
    __syncthreads();

    const float* s_scale = (const float*)(sm + SM_SCALE);

    // ldmatrix lane addressing
    const int grp = lane >> 3, lr = lane & 7;
    const uint32_t kadd = (grp >> 1) * 16;
    uint32_t saA[4], xaA[4], saB[2], xaB[2];
    #pragma unroll
    for (int mi = 0; mi < 4; mi++) {
        int r = wm + mi * 16 + (grp & 1) * 8 + lr;
        saA[mi] = (uint32_t)r * 128;
        xaA[mi] = (uint32_t)(r & 7) << 4;
    }
    #pragma unroll
    for (int nj = 0; nj < 2; nj++) {
        int r = wn + nj * 16 + (grp & 1) * 8 + lr;
        saB[nj] = (uint32_t)r * 128;
        xaB[nj] = (uint32_t)(r & 7) << 4;
    }

    float acc[4][4][4] = {};

    // LDG fp32 A chunk + split + STS (pa registers are function-local: dead
    // before compute, so peak register pressure stays under the 128 cap).
    auto ldsplitA = [&](int k0, int buf) {
        char* ah = sm + SM_AH + buf * 16384;
        char* al = sm + SM_AL + buf * 16384;
        float4 pa[4][2];
        #pragma unroll
        for (int i = 0; i < 4; i++) {
            int idx = tid + i * 256;
            int ar = idx >> 3;
            int c8 = (idx & 7) * 8;
            size_t off = (size_t)(row0 + ar) * Dn + k0 + c8;
            pa[i][0] = *(const float4*)&A[off];
            pa[i][1] = *(const float4*)&A[off + 4];
        }
        #pragma unroll
        for (int i = 0; i < 4; i++) {
            int idx = tid + i * 256;
            int ar = idx >> 3;
            int c8 = (idx & 7) * 8;
            float4 v0 = pa[i][0], v1 = pa[i][1];
            if (SCALE) {
                float s = s_scale[ar];
                v0.x *= s; v0.y *= s; v0.z *= s; v0.w *= s;
                v1.x *= s; v1.y *= s; v1.z *= s; v1.w *= s;
            }
            uint2 h0, l0, h1, l1;
            split_bf16x4(v0, h0, l0);
            split_bf16x4(v1, h1, l1);
            uint32_t boff = SW128((uint32_t)(ar * 128 + c8 * 2));
            *(uint4*)(ah + boff) = make_uint4(h0.x, h0.y, h1.x, h1.y);
            *(uint4*)(al + boff) = make_uint4(l0.x, l0.y, l1.x, l1.y);
        }
    };
    auto cpA = [&](int k0, int buf) {
        uint32_t ah = smb + SM_AH + buf * 16384;
        uint32_t al = smb + SM_AL + buf * 16384;
        #pragma unroll
        for (int i = 0; i < 4; i++) {
            int idx = tid + i * 256;
            int r = idx >> 3, j = idx & 7;
            uint32_t boff = SW128((uint32_t)(r * 128 + j * 16));
            size_t go = (size_t)(row0 + r) * Dn + k0 + j * 8;
            CP_ASYNC16(ah + boff, Ah + go);
            CP_ASYNC16(al + boff, Al + go);
        }
    };
    auto cpB = [&](int k0) {
        uint32_t bh = smb + SM_BH;
        uint32_t bl = smb + SM_BL;
        #pragma unroll
        for (int i = 0; i < 4; i++) {
            int idx = tid + i * 256;
            int n = idx >> 3, j = idx & 7;
            uint32_t boff = SW128((uint32_t)(n * 128 + j * 16));
            size_t go = (size_t)(col0 + n) * Dn + k0 + j * 8;
            CP_ASYNC16(bh + boff, WTh + go);
            CP_ASYNC16(bl + boff, WTl + go);
        }
    };
    auto compute = [&](int buf) {
        uint32_t abh = smb + SM_AH + buf * 16384;
        uint32_t abl = smb + SM_AL + buf * 16384;
        uint32_t bbh = smb + SM_BH;
        uint32_t bbl = smb + SM_BL;
        #pragma unroll
        for (int ks = 0; ks < 4; ks++) {
            uint32_t kx = ks * 32 + kadd;
            uint32_t ahi[4][4], alo[4][4], bhi[4][2];
            #pragma unroll
            for (int mi = 0; mi < 4; mi++) {
                LDSM4(ahi[mi], abh + saA[mi] + (kx ^ xaA[mi]));
                LDSM4(alo[mi], abl + saA[mi] + (kx ^ xaA[mi]));
            }
            #pragma unroll
            for (int nj = 0; nj < 2; nj++) {
                uint32_t r[4];
                LDSM4(r, bbh + saB[nj] + (kx ^ xaB[nj]));
                bhi[nj * 2][0] = r[0]; bhi[nj * 2 + 1][0] = r[1];
                bhi[nj * 2][1] = r[2]; bhi[nj * 2 + 1][1] = r[3];
            }
            #pragma unroll
            for (int mi = 0; mi < 4; mi++)
                #pragma unroll
                for (int ni = 0; ni < 4; ni++)
                    MMA_BF16(acc[mi][ni], ahi[mi], bhi[ni]);
            #pragma unroll
            for (int mi = 0; mi < 4; mi++)
                #pragma unroll
                for (int ni = 0; ni < 4; ni++)
                    MMA_BF16(acc[mi][ni], alo[mi], bhi[ni]);
            uint32_t blo[4][2];
            #pragma unroll
            for (int nj = 0; nj < 2; nj++) {
                uint32_t r[4];
                LDSM4(r, bbl + saB[nj] + (kx ^ xaB[nj]));
                blo[nj * 2][0] = r[0]; blo[nj * 2 + 1][0] = r[1];
                blo[nj * 2][1] = r[2]; blo[nj * 2 + 1][1] = r[3];
            }
            #pragma unroll
            for (int mi = 0; mi < 4; mi++)
                #pragma unroll
                for (int ni = 0; ni < 4; ni++)
                    MMA_BF16(acc[mi][ni], ahi[mi], blo[ni]);
        }
    };

    constexpr int nT = 4;   // K = 256 in chunks of 64
    if (ABF16) cpA(0, 0); else ldsplitA(0, 0);
    cpB(0);
    CP_COMMIT;
    CP_WAIT0;
    __syncthreads();

    int buf = 0;
    for (int t = 0; t < nT; t++) {
        if (t + 1 < nT) {
            // fill buf^1 before compute: safe — all warps passed the
            // end-of-previous-iteration sync, so buf^1 reads are complete.
            if (ABF16) { cpA((t + 1) * 64, buf ^ 1); CP_COMMIT; }
            else ldsplitA((t + 1) * 64, buf ^ 1);
        }
        compute(buf);
        if (t + 1 < nT) {
            __syncthreads();             // all warps done reading B(t)
            cpB((t + 1) * 64);
            CP_COMMIT;
            CP_WAIT0;                    // A(t+1) + B(t+1) arrived
            __syncthreads();
            buf ^= 1;
        }
    }

    // ---- epilogue ---------------------------------------------------------
    const float* sb = (const float*)(sm + SM_BIAS);
    #pragma unroll
    for (int mi = 0; mi < 4; mi++) {
        int r0g = row0 + wm + mi * 16 + (lane >> 2);
        int r1g = r0g + 8;
        float mk0 = 1.0f, mk1 = 1.0f;
        int dr0 = 0, dr1 = 0, sr0 = 0, sr1 = 0;
        if (MODE == 1) {
            mk0 = g_maskf[r0g]; dr0 = g_dstrow[r0g];
            mk1 = g_maskf[r1g]; dr1 = g_dstrow[r1g];
        } else if (MODE == 3) {
            mk0 = g_nmaskf[r0g];
            mk1 = g_nmaskf[r1g];
        } else if (MODE == 4) {
            sr0 = g_srcrow[r0g]; dr0 = g_dstrow[r0g];
            sr1 = g_srcrow[r1g]; dr1 = g_dstrow[r1g];
        }
        #pragma unroll
        for (int ni = 0; ni < 4; ni++) {
            int cl = wn + ni * 8 + (lane & 3) * 2;
            int cg = col0 + cl;
            float b0 = sb[cl], b1 = sb[cl + 1];
            float v00 = acc[mi][ni][0] + b0, v01 = acc[mi][ni][1] + b1;
            float v10 = acc[mi][ni][2] + b0, v11 = acc[mi][ni][3] + b1;
            size_t o0 = (size_t)r0g * Dn + cg;
            size_t o1 = (size_t)r1g * Dn + cg;
            if (MODE == 0) {
                v00 = silu_f(v00); v01 = silu_f(v01);
                v10 = silu_f(v10); v11 = silu_f(v11);
            } else if (MODE == 1) {
                v00 *= mk0; v01 *= mk0; v10 *= mk1; v11 *= mk1;
                if (mk0 != 0.0f) RED_ADD_V2(&g_agg[(size_t)dr0 * Dn + cg], v00, v01);
                if (mk1 != 0.0f) RED_ADD_V2(&g_agg[(size_t)dr1 * Dn + cg], v10, v11);
            } else if (MODE == 2) {
                float2 q0 = *(const float2*)&residual[o0];
                float2 q1 = *(const float2*)&residual[o1];
                v00 += q0.x; v01 += q0.y; v10 += q1.x; v11 += q1.y;
            } else if (MODE == 3) {
                float2 q0 = *(const float2*)&residual[o0];
                float2 q1 = *(const float2*)&residual[o1];
                v00 = q0.x + v00 * mk0; v01 = q0.y + v01 * mk0;
                v10 = q1.x + v10 * mk1; v11 = q1.y + v11 * mk1;
            } else if (MODE == 4) {
                float2 p0 = *(const float2*)&g_p1[(size_t)sr0 * Dn + cg];
                float2 p1 = *(const float2*)&g_p1[(size_t)sr1 * Dn + cg];
                float2 q0 = *(const float2*)&g_p3[(size_t)dr0 * Dn + cg];
                float2 q1 = *(const float2*)&g_p3[(size_t)dr1 * Dn + cg];
                v00 = silu_f(v00 + p0.x + q0.x); v01 = silu_f(v01 + p0.y + q0.y);
                v10 = silu_f(v10 + p1.x + q1.x); v11 = silu_f(v11 + p1.y + q1.y);
            }
            if (OBF16) {
                store_pair(outh, outl, o0, v00, v01);
                store_pair(outh, outl, o1, v10, v11);
            } else {
                *(float2*)&out[o0] = make_float2(v00, v01);
                *(float2*)&out[o1] = make_float2(v10, v11);
            }
        }
    }
}

// ---------------- layernorm over last dim (256) ------------------------------
__global__ void ln_kernel(const float* __restrict__ x,
                          const float* __restrict__ gamma,
                          const float* __restrict__ beta,
                          float* __restrict__ out) {
    int v = blockIdx.x, t = threadIdx.x;
    float val = x[(size_t)v * Dn + t];
    float s = val, s2 = val * val;
    #pragma unroll
    for (int o = 16; o > 0; o >>= 1) {
        s  += __shfl_xor_sync(0xffffffffu, s,  o);
        s2 += __shfl_xor_sync(0xffffffffu, s2, o);
    }
    __shared__ float ws[8], ws2[8];
    int w = t >> 5;
    if ((t & 31) == 0) { ws[w] = s; ws2[w] = s2; }
    __syncthreads();
    if (t == 0) {
        float a = 0.0f, b = 0.0f;
        #pragma unroll
        for (int i = 0; i < 8; i++) { a += ws[i]; b += ws2[i]; }
        ws[0] = a; ws2[0] = b;
    }
    __syncthreads();
    float mean = ws[0] * (1.0f / 256.0f);
    float var  = ws2[0] * (1.0f / 256.0f) - mean * mean;
    out[(size_t)v * Dn + t] = (val - mean) * rsqrtf(var + 1e-5f) * gamma[t] + beta[t];
}

// ---------------- launch ------------------------------------------------------
extern "C" void kernel_launch(void* const* d_in, const int* in_sizes, int n_in,
                              void* d_out, int out_size) {
    const float* node_feat = (const float*)d_in[0];
    const float* edge_feat = (const float*)d_in[1];
    const int*   edge_index = (const int*)d_in[2];
    const void*  node_mask = d_in[3];
    const void*  edge_mask = d_in[4];
    const float* tw1 = (const float*)d_in[5];
    const float* tb1 = (const float*)d_in[6];
    const float* tw2 = (const float*)d_in[7];
    const float* tb2 = (const float*)d_in[8];
    const float* nw1 = (const float*)d_in[9];
    const float* nb1 = (const float*)d_in[10];
    const float* nw2 = (const float*)d_in[11];
    const float* nb2 = (const float*)d_in[12];
    const float* ew1 = (const float*)d_in[13];
    const float* eb1 = (const float*)d_in[14];
    const float* ew2 = (const float*)d_in[15];
    const float* eb2 = (const float*)d_in[16];
    const float* gamma = (const float*)d_in[17];
    const float* beta  = (const float*)d_in[18];

    float* out = (float*)d_out;

    float *hidden, *msg, *agg, *hn, *node, *cnt, *p1, *p3, *zb;
    __nv_bfloat16 *wth, *wtl;
    cudaGetSymbolAddress((void**)&hidden, g_buf1);
    cudaGetSymbolAddress((void**)&msg,    g_msg);
    cudaGetSymbolAddress((void**)&agg,    g_agg);
    cudaGetSymbolAddress((void**)&hn,     g_hn);
    cudaGetSymbolAddress((void**)&node,   g_node);
    cudaGetSymbolAddress((void**)&cnt,    g_cnt);
    cudaGetSymbolAddress((void**)&p1,     g_p1);
    cudaGetSymbolAddress((void**)&p3,     g_p3);
    cudaGetSymbolAddress((void**)&zb,     g_zero256);
    cudaGetSymbolAddress((void**)&wth,    g_wth);
    cudaGetSymbolAddress((void**)&wtl,    g_wtl);

    __nv_bfloat16* hidh = (__nv_bfloat16*)hidden;
    __nv_bfloat16* hidl = hidh + (size_t)ME * Dn;
    __nv_bfloat16* msgh = (__nv_bfloat16*)msg;
    __nv_bfloat16* msgl = msgh + (size_t)ME * Dn;
    __nv_bfloat16* hnh  = (__nv_bfloat16*)hn;
    __nv_bfloat16* hnl  = hnh + (size_t)MN * Dn;

    cudaFuncSetAttribute(gemm_tc<5, false, false, false, true >, cudaFuncAttributeMaxDynamicSharedMemorySize, SMEM_TOTAL);
    cudaFuncSetAttribute(gemm_tc<4, false, false, true , false>, cudaFuncAttributeMaxDynamicSharedMemorySize, SMEM_TOTAL);
    cudaFuncSetAttribute(gemm_tc<1, false, true , true , false>, cudaFuncAttributeMaxDynamicSharedMemorySize, SMEM_TOTAL);
    cudaFuncSetAttribute(gemm_tc<0, false, true , true , false>, cudaFuncAttributeMaxDynamicSharedMemorySize, SMEM_TOTAL);
    cudaFuncSetAttribute(gemm_tc<2, false, true , false, false>, cudaFuncAttributeMaxDynamicSharedMemorySize, SMEM_TOTAL);
    cudaFuncSetAttribute(gemm_tc<0, true , false, true , false>, cudaFuncAttributeMaxDynamicSharedMemorySize, SMEM_TOTAL);
    cudaFuncSetAttribute(gemm_tc<3, false, true , false, false>, cudaFuncAttributeMaxDynamicSharedMemorySize, SMEM_TOTAL);

    // zero scratch first (memset nodes, not kernels)
    cudaMemsetAsync(agg, 0, (size_t)MN * Dn * sizeof(float));
    cudaMemsetAsync(cnt, 0, (size_t)MN * sizeof(float));

    // kernels
    sniff_mask_dtype<<<1, 1>>>((const unsigned int*)edge_mask);           // 1
    WSrcs ws;
    ws.p[0] = tw1;          ws.p[1] = tw1 + 65536;  ws.p[2] = tw1 + 131072;
    ws.p[3] = tw2;          ws.p[4] = ew1;          ws.p[5] = ew2;
    ws.p[6] = nw1;          ws.p[7] = nw2;
    prep_weights_all<<<dim3(8, 8, 8), dim3(32, 8)>>>(ws, wth, wtl);       // 2
    prep_edges<<<ME / 256, 256>>>(edge_index, edge_mask);                 // 3

    dim3 ge(2, ME / 128);
    dim3 gn(2, MN / 128);
    dim3 gn2(2, MN / 128, 2);
    // 4: P1 = nf @ W1a (z=0), P3 = nf @ W1c (z=1)
    gemm_tc<5, false, false, false, true ><<<gn2, 256, SMEM_TOTAL>>>(
        node_feat, nullptr, nullptr, wth + OW_T1A, wtl + OW_T1A,
        wth + OW_T1C, wtl + OW_T1C, zb, nullptr, p1, p3, nullptr, nullptr);
    // 5: triplet layer1: silu(ef@W1b + P1[src] + P3[dst] + tb1) -> hidden pair
    //    (fp32 A path: in-kernel split, no pre-split round trip)
    gemm_tc<4, false, false, true , false><<<ge, 256, SMEM_TOTAL>>>(
        edge_feat, nullptr, nullptr, wth + OW_T1B, wtl + OW_T1B, nullptr, nullptr,
        tb1, nullptr, nullptr, nullptr, hidh, hidl);
    // 6: msg = (hidden@tw2+tb2)*mask -> pair + red.v2 to agg
    gemm_tc<1, false, true , true , false><<<ge, 256, SMEM_TOTAL>>>(
        nullptr, hidh, hidl, wth + OW_TW2, wtl + OW_TW2, nullptr, nullptr,
        tb2, nullptr, nullptr, nullptr, msgh, msgl);
    // 7: invc + node mask (needs cnt complete)
    prep_nodes<<<MN / 256, 256>>>(node_mask);
    // 8: edge update layer1 (silu) -> hidden pair
    gemm_tc<0, false, true , true , false><<<ge, 256, SMEM_TOTAL>>>(
        nullptr, msgh, msgl, wth + OW_EW1, wtl + OW_EW1, nullptr, nullptr,
        eb1, nullptr, nullptr, nullptr, hidh, hidl);
    // 9: edge_out = edge_feat + layer2 (fp32)
    gemm_tc<2, false, true , false, false><<<ge, 256, SMEM_TOTAL>>>(
        nullptr, hidh, hidl, wth + OW_EW2, wtl + OW_EW2, nullptr, nullptr,
        eb2, edge_feat, out + (size_t)MN * Dn, nullptr, nullptr, nullptr);
    // 10: node layer1 on agg*invc (silu) -> hn pair
    gemm_tc<0, true , false, true , false><<<gn, 256, SMEM_TOTAL>>>(
        agg, nullptr, nullptr, wth + OW_NW1, wtl + OW_NW1, nullptr, nullptr,
        nb1, nullptr, nullptr, nullptr, hnh, hnl);
    // 11: node = node_feat + layer2 * node_mask (fp32)
    gemm_tc<3, false, true , false, false><<<gn, 256, SMEM_TOTAL>>>(
        nullptr, hnh, hnl, wth + OW_NW2, wtl + OW_NW2, nullptr, nullptr,
        nb2, node_feat, node, nullptr, nullptr, nullptr);
    // 12: layernorm
    ln_kernel<<<MN, 256>>>(node, gamma, beta, out);
}

// round 11
// speedup vs baseline: 4.0963x; 1.0056x over previous
#include <cuda_runtime.h>
#include <cuda_bf16.h>
#include <cstdint>
#include <math.h>

// Problem constants
#define Bn 16
#define Nn 1024
#define En 16384
#define Dn 256
constexpr int ME = Bn * En;   // 262144 edge rows
constexpr int MN = Bn * Nn;   // 16384 node rows

// ============================ PTX helpers (sm_80-compatible only) ===========
__device__ __forceinline__ uint32_t smem_u32(const void* p) {
    uint32_t a;
    asm("{ .reg .u64 t; cvta.to.shared.u64 t, %1; cvt.u32.u64 %0, t; }"
        : "=r"(a) : "l"(p));
    return a;
}

#define LDSM4(r, addr) \
    asm volatile("ldmatrix.sync.aligned.m8n8.x4.shared.b16 {%0,%1,%2,%3}, [%4];" \
        : "=r"((r)[0]), "=r"((r)[1]), "=r"((r)[2]), "=r"((r)[3]) : "r"(addr))

#define MMA_BF16(d, a, b) \
    asm volatile("mma.sync.aligned.m16n8k16.row.col.f32.bf16.bf16.f32 " \
        "{%0,%1,%2,%3}, {%4,%5,%6,%7}, {%8,%9}, {%0,%1,%2,%3};" \
        : "+f"((d)[0]), "+f"((d)[1]), "+f"((d)[2]), "+f"((d)[3]) \
        : "r"((a)[0]), "r"((a)[1]), "r"((a)[2]), "r"((a)[3]), \
          "r"((b)[0]), "r"((b)[1]))

#define CP_ASYNC16(dst, src) \
    asm volatile("cp.async.cg.shared.global [%0], [%1], 16;" :: "r"(dst), "l"(src))
#define CP_COMMIT asm volatile("cp.async.commit_group;" ::: "memory")
#define CP_WAIT0  asm volatile("cp.async.wait_group 0;" ::: "memory")

#define RED_ADD_V2(p, a, b) \
    asm volatile("red.global.add.v2.f32 [%0], {%1,%2};" :: "l"(p), "f"(a), "f"(b) : "memory")

#define SW128(x) ((x) ^ (((x) >> 3) & 0x70))

// ============================ scratch globals ================================
__device__ float g_buf1[(size_t)ME * Dn];   // hidden (bf16 hi/lo pair alias)
__device__ float g_msg [(size_t)ME * Dn];   // msg    (bf16 hi/lo pair alias)
__device__ float g_agg [(size_t)MN * Dn];   // fp32 (atomics)
__device__ float g_hn  [(size_t)MN * Dn];   // hn     (bf16 hi/lo pair alias)
__device__ float g_node[(size_t)MN * Dn];   // fp32 pre-LN
__device__ float g_p1  [(size_t)MN * Dn];   // node_feat @ W1a (fp32)
__device__ float g_p3  [(size_t)MN * Dn];   // node_feat @ W1c (fp32)
__device__ float g_nfs [(size_t)MN * Dn];   // node_feat pre-split (bf16 pair)
__device__ float g_cnt [MN];
__device__ float g_invc[MN];
__device__ int   g_srcrow[ME];
__device__ int   g_dstrow[ME];
__device__ float g_maskf [ME];
__device__ float g_nmaskf[MN];
__device__ int   g_mask_dt;
__device__ float g_zero256[256];
// pre-transposed + bf16-split weights, 8 matrices of [256][256]
__device__ __nv_bfloat16 g_wth[524288];
__device__ __nv_bfloat16 g_wtl[524288];
constexpr size_t OW_T1A = 0,      OW_T1B = 65536,  OW_T1C = 131072,
                 OW_TW2 = 196608, OW_EW1 = 262144, OW_EW2 = 327680,
                 OW_NW1 = 393216, OW_NW2 = 458752;

__device__ __forceinline__ float silu_f(float x) { return x / (1.0f + __expf(-x)); }

__device__ __forceinline__ float read_mask(const void* p, int i, int dt) {
    if (dt == 0) return ((const float*)p)[i];
    if (dt == 1) return ((const unsigned char*)p)[i] ? 1.0f : 0.0f;
    return ((const int*)p)[i] ? 1.0f : 0.0f;
}

__device__ __forceinline__ void split_bf16x4(float4 v, uint2& hi, uint2& lo) {
    __nv_bfloat162 h01 = __floats2bfloat162_rn(v.x, v.y);
    __nv_bfloat162 h23 = __floats2bfloat162_rn(v.z, v.w);
    float2 f01 = __bfloat1622float2(h01);
    float2 f23 = __bfloat1622float2(h23);
    __nv_bfloat162 l01 = __floats2bfloat162_rn(v.x - f01.x, v.y - f01.y);
    __nv_bfloat162 l23 = __floats2bfloat162_rn(v.z - f23.x, v.w - f23.y);
    hi.x = *(uint32_t*)&h01; hi.y = *(uint32_t*)&h23;
    lo.x = *(uint32_t*)&l01; lo.y = *(uint32_t*)&l23;
}

// ---------------- small prep kernels ----------------------------------------
__global__ void sniff_mask_dtype(const unsigned int* __restrict__ m) {
    bool big_byte = false, upper = false;
    for (int i = 0; i < 16; i++) {
        unsigned int w = m[i];
        unsigned char b0 = w & 0xff, b1 = (w >> 8) & 0xff,
                      b2 = (w >> 16) & 0xff, b3 = (w >> 24) & 0xff;
        if (b0 >= 2 || b1 >= 2 || b2 >= 2 || b3 >= 2) big_byte = true;
        if (b1 | b2 | b3) upper = true;
    }
    g_mask_dt = big_byte ? 0 : (upper ? 1 : 2);
}

__global__ void prep_edges(const int* __restrict__ edge_index,
                           const void* __restrict__ edge_mask) {
    int r = blockIdx.x * blockDim.x + threadIdx.x;
    if (r >= ME) return;
    int dt = g_mask_dt;
    int b = r >> 14;
    int e = r & (En - 1);
    int src = edge_index[(size_t)b * 2 * En + e];
    int dst = edge_index[(size_t)b * 2 * En + En + e];
    float m = (read_mask(edge_mask, r, dt) != 0.0f) ? 1.0f : 0.0f;
    g_srcrow[r] = b * Nn + src;
    g_dstrow[r] = b * Nn + dst;
    g_maskf[r]  = m;
    if (m != 0.0f) atomicAdd(&g_cnt[b * Nn + dst], 1.0f);
}

__global__ void prep_nodes(const void* __restrict__ node_mask) {
    int v = blockIdx.x * blockDim.x + threadIdx.x;
    if (v >= MN) return;
    g_invc[v]   = 1.0f / fmaxf(g_cnt[v], 1.0f);
    g_nmaskf[v] = (read_mask(node_mask, v, g_mask_dt) != 0.0f) ? 1.0f : 0.0f;
}

// elementwise fp32 -> bf16 hi/lo pair split
__global__ void split_pair(const float4* __restrict__ src,
                           uint2* __restrict__ dsth, uint2* __restrict__ dstl) {
    int i = blockIdx.x * blockDim.x + threadIdx.x;
    uint2 hi, lo;
    split_bf16x4(src[i], hi, lo);
    dsth[i] = hi;
    dstl[i] = lo;
}

// All 8 weight transposes in one launch; smem-tile coalesced.
struct WSrcs { const float* p[8]; };
__global__ void prep_weights_all(WSrcs srcs,
                                 __nv_bfloat16* __restrict__ wth,
                                 __nv_bfloat16* __restrict__ wtl) {
    __shared__ float tile[32][33];
    const float* src = srcs.p[blockIdx.z];
    int kt = blockIdx.x * 32, nt = blockIdx.y * 32;
    #pragma unroll
    for (int i = threadIdx.y; i < 32; i += 8)
        tile[i][threadIdx.x] = src[(size_t)(kt + i) * 256 + nt + threadIdx.x];
    __syncthreads();
    size_t base = (size_t)blockIdx.z * 65536;
    #pragma unroll
    for (int i = threadIdx.y; i < 32; i += 8) {
        int n = nt + i, k = kt + threadIdx.x;
        float v = tile[threadIdx.x][i];
        __nv_bfloat16 h = __float2bfloat16_rn(v);
        wth[base + (size_t)n * 256 + k] = h;
        wtl[base + (size_t)n * 256 + k] = __float2bfloat16_rn(v - __bfloat162float(h));
    }
}

// ============================ tensor-core GEMM (mma.sync) ====================
// out[M,256] = A[M,256] @ W[256,256] via bf16x3 (AhiBhi + AloBhi + AhiBlo).
// Block tile 128x128, 8 warps (2M x 4N), warp tile 64x32 (4x4 m16n8k16).
// A double-buffered (cp.async or LDG+split-early), B single-buffered.
// occupancy 2 (97KB smem, 128-reg cap).
// MODE 0: silu(D+b)                (SCALE: rows of fp32 A scaled by g_invc)
// MODE 1: v=(D+b)*maskf; store pair; red.v2 fp32 to g_agg[dstrow]
// MODE 2: residual + (D+b)             (fp32 out)
// MODE 3: residual + (D+b)*g_nmaskf    (fp32 out)
// MODE 4: silu(D + b + g_p1[srcrow] + g_p3[dstrow])
// MODE 5: plain store (bias zero). DUAL: blockIdx.z picks (W,out) set 1/2.

constexpr int SM_BIAS  = 0;      // 128 f32
constexpr int SM_SCALE = 512;    // 128 f32
constexpr int SM_AH    = 1024;   // [2][16384]
constexpr int SM_AL    = 33792;  // [2][16384]
constexpr int SM_BH    = 66560;  // [16384]
constexpr int SM_BL    = 82944;  // [16384]
constexpr int SMEM_TOTAL = 99328;

__device__ __forceinline__ void store_pair(__nv_bfloat16* outh, __nv_bfloat16* outl,
                                           size_t o, float a, float b) {
    __nv_bfloat162 h = __floats2bfloat162_rn(a, b);
    float2 hf = __bfloat1622float2(h);
    __nv_bfloat162 l = __floats2bfloat162_rn(a - hf.x, b - hf.y);
    *(__nv_bfloat162*)&outh[o] = h;
    *(__nv_bfloat162*)&outl[o] = l;
}

template<int MODE, bool SCALE, bool ABF16, bool OBF16, bool DUAL>
__global__ void __launch_bounds__(256, 2)
gemm_tc(const float* __restrict__ A,                 // fp32 A (when !ABF16)
        const __nv_bfloat16* __restrict__ Ah,        // bf16 A pair (when ABF16)
        const __nv_bfloat16* __restrict__ Al,
        const __nv_bfloat16* WTh,                    // [256][256]
        const __nv_bfloat16* WTl,
        const __nv_bfloat16* WTh2,                   // DUAL second set
        const __nv_bfloat16* WTl2,
        const float* __restrict__ bias,
        const float* __restrict__ residual,
        float* out,
        float* out2,
        __nv_bfloat16* __restrict__ outh,
        __nv_bfloat16* __restrict__ outl) {
    extern __shared__ __align__(1024) char sm[];
    const uint32_t smb = smem_u32(sm);
    const int tid  = threadIdx.x;
    const int wid  = tid >> 5;
    const int lane = tid & 31;
    const int row0 = blockIdx.y * 128;
    const int col0 = blockIdx.x * 128;
    const int wm = (wid & 1) * 64;
    const int wn = (wid >> 1) * 32;

    if (DUAL && blockIdx.z == 1) { WTh = WTh2; WTl = WTl2; out = out2; }

    if (tid < 128) {
        ((float*)(sm + SM_BIAS))[tid] = bias[col0 + tid];
        if (SCALE) ((float*)(sm + SM_SCALE))[tid] = g_invc[row0 + tid];
    }
    __syncthreads();

    const float* s_scale = (const float*)(sm + SM_SCALE);

    // ldmatrix lane addressing
    const int grp = lane >> 3, lr = lane & 7;
    const uint32_t kadd = (grp >> 1) * 16;
    uint32_t saA[4], xaA[4], saB[2], xaB[2];
    #pragma unroll
    for (int mi = 0; mi < 4; mi++) {
        int r = wm + mi * 16 + (grp & 1) * 8 + lr;
        saA[mi] = (uint32_t)r * 128;
        xaA[mi] = (uint32_t)(r & 7) << 4;
    }
    #pragma unroll
    for (int nj = 0; nj < 2; nj++) {
        int r = wn + nj * 16 + (grp & 1) * 8 + lr;
        saB[nj] = (uint32_t)r * 128;
        xaB[nj] = (uint32_t)(r & 7) << 4;
    }

    float acc[4][4][4] = {};

    auto ldsplitA = [&](int k0, int buf) {
        char* ah = sm + SM_AH + buf * 16384;
        char* al = sm + SM_AL + buf * 16384;
        float4 pa[4][2];
        #pragma unroll
        for (int i = 0; i < 4; i++) {
            int idx = tid + i * 256;
            int ar = idx >> 3;
            int c8 = (idx & 7) * 8;
            size_t off = (size_t)(row0 + ar) * Dn + k0 + c8;
            pa[i][0] = *(const float4*)&A[off];
            pa[i][1] = *(const float4*)&A[off + 4];
        }
        #pragma unroll
        for (int i = 0; i < 4; i++) {
            int idx = tid + i * 256;
            int ar = idx >> 3;
            int c8 = (idx & 7) * 8;
            float4 v0 = pa[i][0], v1 = pa[i][1];
            if (SCALE) {
                float s = s_scale[ar];
                v0.x *= s; v0.y *= s; v0.z *= s; v0.w *= s;
                v1.x *= s; v1.y *= s; v1.z *= s; v1.w *= s;
            }
            uint2 h0, l0, h1, l1;
            split_bf16x4(v0, h0, l0);
            split_bf16x4(v1, h1, l1);
            uint32_t boff = SW128((uint32_t)(ar * 128 + c8 * 2));
            *(uint4*)(ah + boff) = make_uint4(h0.x, h0.y, h1.x, h1.y);
            *(uint4*)(al + boff) = make_uint4(l0.x, l0.y, l1.x, l1.y);
        }
    };
    auto cpA = [&](int k0, int buf) {
        uint32_t ah = smb + SM_AH + buf * 16384;
        uint32_t al = smb + SM_AL + buf * 16384;
        #pragma unroll
        for (int i = 0; i < 4; i++) {
            int idx = tid + i * 256;
            int r = idx >> 3, j = idx & 7;
            uint32_t boff = SW128((uint32_t)(r * 128 + j * 16));
            size_t go = (size_t)(row0 + r) * Dn + k0 + j * 8;
            CP_ASYNC16(ah + boff, Ah + go);
            CP_ASYNC16(al + boff, Al + go);
        }
    };
    auto cpB = [&](int k0) {
        uint32_t bh = smb + SM_BH;
        uint32_t bl = smb + SM_BL;
        #pragma unroll
        for (int i = 0; i < 4; i++) {
            int idx = tid + i * 256;
            int n = idx >> 3, j = idx & 7;
            uint32_t boff = SW128((uint32_t)(n * 128 + j * 16));
            size_t go = (size_t)(col0 + n) * Dn + k0 + j * 8;
            CP_ASYNC16(bh + boff, WTh + go);
            CP_ASYNC16(bl + boff, WTl + go);
        }
    };
    auto compute = [&](int buf) {
        uint32_t abh = smb + SM_AH + buf * 16384;
        uint32_t abl = smb + SM_AL + buf * 16384;
        uint32_t bbh = smb + SM_BH;
        uint32_t bbl = smb + SM_BL;
        #pragma unroll
        for (int ks = 0; ks < 4; ks++) {
            uint32_t kx = ks * 32 + kadd;
            uint32_t ahi[4][4], alo[4][4], bhi[4][2];
            #pragma unroll
            for (int mi = 0; mi < 4; mi++) {
                LDSM4(ahi[mi], abh + saA[mi] + (kx ^ xaA[mi]));
                LDSM4(alo[mi], abl + saA[mi] + (kx ^ xaA[mi]));
            }
            #pragma unroll
            for (int nj = 0; nj < 2; nj++) {
                uint32_t r[4];
                LDSM4(r, bbh + saB[nj] + (kx ^ xaB[nj]));
                bhi[nj * 2][0] = r[0]; bhi[nj * 2 + 1][0] = r[1];
                bhi[nj * 2][1] = r[2]; bhi[nj * 2 + 1][1] = r[3];
            }
            #pragma unroll
            for (int mi = 0; mi < 4; mi++)
                #pragma unroll
                for (int ni = 0; ni < 4; ni++)
                    MMA_BF16(acc[mi][ni], ahi[mi], bhi[ni]);
            #pragma unroll
            for (int mi = 0; mi < 4; mi++)
                #pragma unroll
                for (int ni = 0; ni < 4; ni++)
                    MMA_BF16(acc[mi][ni], alo[mi], bhi[ni]);
            uint32_t blo[4][2];
            #pragma unroll
            for (int nj = 0; nj < 2; nj++) {
                uint32_t r[4];
                LDSM4(r, bbl + saB[nj] + (kx ^ xaB[nj]));
                blo[nj * 2][0] = r[0]; blo[nj * 2 + 1][0] = r[1];
                blo[nj * 2][1] = r[2]; blo[nj * 2 + 1][1] = r[3];
            }
            #pragma unroll
            for (int mi = 0; mi < 4; mi++)
                #pragma unroll
                for (int ni = 0; ni < 4; ni++)
                    MMA_BF16(acc[mi][ni], ahi[mi], blo[ni]);
        }
    };

    constexpr int nT = 4;   // K = 256 in chunks of 64
    if (ABF16) cpA(0, 0); else ldsplitA(0, 0);
    cpB(0);
    CP_COMMIT;
    CP_WAIT0;
    __syncthreads();

    int buf = 0;
    for (int t = 0; t < nT; t++) {
        if (t + 1 < nT) {
            if (ABF16) { cpA((t + 1) * 64, buf ^ 1); CP_COMMIT; }
            else ldsplitA((t + 1) * 64, buf ^ 1);
        }
        compute(buf);
        if (t + 1 < nT) {
            __syncthreads();             // all warps done reading B(t)
            cpB((t + 1) * 64);
            CP_COMMIT;
            CP_WAIT0;                    // A(t+1) + B(t+1) arrived
            __syncthreads();
            buf ^= 1;
        }
    }

    // ---- epilogue ---------------------------------------------------------
    const float* sb = (const float*)(sm + SM_BIAS);
    #pragma unroll
    for (int mi = 0; mi < 4; mi++) {
        int r0g = row0 + wm + mi * 16 + (lane >> 2);
        int r1g = r0g + 8;
        float mk0 = 1.0f, mk1 = 1.0f;
        int dr0 = 0, dr1 = 0, sr0 = 0, sr1 = 0;
        if (MODE == 1) {
            mk0 = g_maskf[r0g]; dr0 = g_dstrow[r0g];
            mk1 = g_maskf[r1g]; dr1 = g_dstrow[r1g];
        } else if (MODE == 3) {
            mk0 = g_nmaskf[r0g];
            mk1 = g_nmaskf[r1g];
        } else if (MODE == 4) {
            sr0 = g_srcrow[r0g]; dr0 = g_dstrow[r0g];
            sr1 = g_srcrow[r1g]; dr1 = g_dstrow[r1g];
        }
        #pragma unroll
        for (int ni = 0; ni < 4; ni++) {
            int cl = wn + ni * 8 + (lane & 3) * 2;
            int cg = col0 + cl;
            float b0 = sb[cl], b1 = sb[cl + 1];
            float v00 = acc[mi][ni][0] + b0, v01 = acc[mi][ni][1] + b1;
            float v10 = acc[mi][ni][2] + b0, v11 = acc[mi][ni][3] + b1;
            size_t o0 = (size_t)r0g * Dn + cg;
            size_t o1 = (size_t)r1g * Dn + cg;
            if (MODE == 0) {
                v00 = silu_f(v00); v01 = silu_f(v01);
                v10 = silu_f(v10); v11 = silu_f(v11);
            } else if (MODE == 1) {
                v00 *= mk0; v01 *= mk0; v10 *= mk1; v11 *= mk1;
                if (mk0 != 0.0f) RED_ADD_V2(&g_agg[(size_t)dr0 * Dn + cg], v00, v01);
                if (mk1 != 0.0f) RED_ADD_V2(&g_agg[(size_t)dr1 * Dn + cg], v10, v11);
            } else if (MODE == 2) {
                float2 q0 = *(const float2*)&residual[o0];
                float2 q1 = *(const float2*)&residual[o1];
                v00 += q0.x; v01 += q0.y; v10 += q1.x; v11 += q1.y;
            } else if (MODE == 3) {
                float2 q0 = *(const float2*)&residual[o0];
                float2 q1 = *(const float2*)&residual[o1];
                v00 = q0.x + v00 * mk0; v01 = q0.y + v01 * mk0;
                v10 = q1.x + v10 * mk1; v11 = q1.y + v11 * mk1;
            } else if (MODE == 4) {
                float2 p0 = *(const float2*)&g_p1[(size_t)sr0 * Dn + cg];
                float2 p1 = *(const float2*)&g_p1[(size_t)sr1 * Dn + cg];
                float2 q0 = *(const float2*)&g_p3[(size_t)dr0 * Dn + cg];
                float2 q1 = *(const float2*)&g_p3[(size_t)dr1 * Dn + cg];
                v00 = silu_f(v00 + p0.x + q0.x); v01 = silu_f(v01 + p0.y + q0.y);
                v10 = silu_f(v10 + p1.x + q1.x); v11 = silu_f(v11 + p1.y + q1.y);
            }
            if (OBF16) {
                store_pair(outh, outl, o0, v00, v01);
                store_pair(outh, outl, o1, v10, v11);
            } else {
                *(float2*)&out[o0] = make_float2(v00, v01);
                *(float2*)&out[o1] = make_float2(v10, v11);
            }
        }
    }
}

// ---------------- layernorm over last dim (256), float4 vectorized ----------
__global__ void ln_kernel(const float* __restrict__ x,
                          const float* __restrict__ gamma,
                          const float* __restrict__ beta,
                          float* __restrict__ out) {
    int v = blockIdx.x, t = threadIdx.x;   // 64 threads, 4 elems each
    float4 val = *(const float4*)&x[(size_t)v * Dn + t * 4];
    float s  = val.x + val.y + val.z + val.w;
    float s2 = val.x * val.x + val.y * val.y + val.z * val.z + val.w * val.w;
    #pragma unroll
    for (int o = 16; o > 0; o >>= 1) {
        s  += __shfl_xor_sync(0xffffffffu, s,  o);
        s2 += __shfl_xor_sync(0xffffffffu, s2, o);
    }
    __shared__ float ws[2], ws2[2];
    int w = t >> 5;
    if ((t & 31) == 0) { ws[w] = s; ws2[w] = s2; }
    __syncthreads();
    float sa  = ws[0] + ws[1];
    float sa2 = ws2[0] + ws2[1];
    float mean = sa * (1.0f / 256.0f);
    float var  = sa2 * (1.0f / 256.0f) - mean * mean;
    float inv  = rsqrtf(var + 1e-5f);
    float4 g = *(const float4*)&gamma[t * 4];
    float4 bb = *(const float4*)&beta[t * 4];
    float4 o;
    o.x = (val.x - mean) * inv * g.x + bb.x;
    o.y = (val.y - mean) * inv * g.y + bb.y;
    o.z = (val.z - mean) * inv * g.z + bb.z;
    o.w = (val.w - mean) * inv * g.w + bb.w;
    *(float4*)&out[(size_t)v * Dn + t * 4] = o;
}

// ---------------- launch ------------------------------------------------------
extern "C" void kernel_launch(void* const* d_in, const int* in_sizes, int n_in,
                              void* d_out, int out_size) {
    const float* node_feat = (const float*)d_in[0];
    const float* edge_feat = (const float*)d_in[1];
    const int*   edge_index = (const int*)d_in[2];
    const void*  node_mask = d_in[3];
    const void*  edge_mask = d_in[4];
    const float* tw1 = (const float*)d_in[5];
    const float* tb1 = (const float*)d_in[6];
    const float* tw2 = (const float*)d_in[7];
    const float* tb2 = (const float*)d_in[8];
    const float* nw1 = (const float*)d_in[9];
    const float* nb1 = (const float*)d_in[10];
    const float* nw2 = (const float*)d_in[11];
    const float* nb2 = (const float*)d_in[12];
    const float* ew1 = (const float*)d_in[13];
    const float* eb1 = (const float*)d_in[14];
    const float* ew2 = (const float*)d_in[15];
    const float* eb2 = (const float*)d_in[16];
    const float* gamma = (const float*)d_in[17];
    const float* beta  = (const float*)d_in[18];

    float* out = (float*)d_out;

    float *hidden, *msg, *agg, *hn, *node, *cnt, *p1, *p3, *nfs, *zb;
    __nv_bfloat16 *wth, *wtl;
    cudaGetSymbolAddress((void**)&hidden, g_buf1);
    cudaGetSymbolAddress((void**)&msg,    g_msg);
    cudaGetSymbolAddress((void**)&agg,    g_agg);
    cudaGetSymbolAddress((void**)&hn,     g_hn);
    cudaGetSymbolAddress((void**)&node,   g_node);
    cudaGetSymbolAddress((void**)&cnt,    g_cnt);
    cudaGetSymbolAddress((void**)&p1,     g_p1);
    cudaGetSymbolAddress((void**)&p3,     g_p3);
    cudaGetSymbolAddress((void**)&nfs,    g_nfs);
    cudaGetSymbolAddress((void**)&zb,     g_zero256);
    cudaGetSymbolAddress((void**)&wth,    g_wth);
    cudaGetSymbolAddress((void**)&wtl,    g_wtl);

    __nv_bfloat16* hidh = (__nv_bfloat16*)hidden;
    __nv_bfloat16* hidl = hidh + (size_t)ME * Dn;
    __nv_bfloat16* msgh = (__nv_bfloat16*)msg;
    __nv_bfloat16* msgl = msgh + (size_t)ME * Dn;
    __nv_bfloat16* hnh  = (__nv_bfloat16*)hn;
    __nv_bfloat16* hnl  = hnh + (size_t)MN * Dn;
    __nv_bfloat16* nfh  = (__nv_bfloat16*)nfs;
    __nv_bfloat16* nfl  = nfh + (size_t)MN * Dn;

    cudaFuncSetAttribute(gemm_tc<5, false, true , false, true >, cudaFuncAttributeMaxDynamicSharedMemorySize, SMEM_TOTAL);
    cudaFuncSetAttribute(gemm_tc<4, false, false, true , false>, cudaFuncAttributeMaxDynamicSharedMemorySize, SMEM_TOTAL);
    cudaFuncSetAttribute(gemm_tc<1, false, true , true , false>, cudaFuncAttributeMaxDynamicSharedMemorySize, SMEM_TOTAL);
    cudaFuncSetAttribute(gemm_tc<0, false, true , true , false>, cudaFuncAttributeMaxDynamicSharedMemorySize, SMEM_TOTAL);
    cudaFuncSetAttribute(gemm_tc<2, false, true , false, false>, cudaFuncAttributeMaxDynamicSharedMemorySize, SMEM_TOTAL);
    cudaFuncSetAttribute(gemm_tc<0, true , false, true , false>, cudaFuncAttributeMaxDynamicSharedMemorySize, SMEM_TOTAL);
    cudaFuncSetAttribute(gemm_tc<3, false, true , false, false>, cudaFuncAttributeMaxDynamicSharedMemorySize, SMEM_TOTAL);

    // zero scratch first (memset nodes, not kernels)
    cudaMemsetAsync(agg, 0, (size_t)MN * Dn * sizeof(float));
    cudaMemsetAsync(cnt, 0, (size_t)MN * sizeof(float));

    // kernels
    sniff_mask_dtype<<<1, 1>>>((const unsigned int*)edge_mask);
    WSrcs ws;
    ws.p[0] = tw1;          ws.p[1] = tw1 + 65536;  ws.p[2] = tw1 + 131072;
    ws.p[3] = tw2;          ws.p[4] = ew1;          ws.p[5] = ew2;
    ws.p[6] = nw1;          ws.p[7] = nw2;
    prep_weights_all<<<dim3(8, 8, 8), dim3(32, 8)>>>(ws, wth, wtl);
    split_pair<<<(MN * Dn / 4) / 256, 256>>>((const float4*)node_feat,
                                             (uint2*)nfh, (uint2*)nfl);
    prep_edges<<<ME / 256, 256>>>(edge_index, edge_mask);

    dim3 ge(2, ME / 128);
    dim3 gn(2, MN / 128);
    dim3 gn2(2, MN / 128, 2);
    // P1 = nf @ W1a (z=0), P3 = nf @ W1c (z=1) — pure cp.async A
    gemm_tc<5, false, true , false, true ><<<gn2, 256, SMEM_TOTAL>>>(
        nullptr, nfh, nfl, wth + OW_T1A, wtl + OW_T1A,
        wth + OW_T1C, wtl + OW_T1C, zb, nullptr, p1, p3, nullptr, nullptr);
    // triplet layer1: silu(ef@W1b + P1[src] + P3[dst] + tb1) -> hidden pair
    gemm_tc<4, false, false, true , false><<<ge, 256, SMEM_TOTAL>>>(
        edge_feat, nullptr, nullptr, wth + OW_T1B, wtl + OW_T1B, nullptr, nullptr,
        tb1, nullptr, nullptr, nullptr, hidh, hidl);
    // msg = (hidden@tw2+tb2)*mask -> pair + red.v2 to agg
    gemm_tc<1, false, true , true , false><<<ge, 256, SMEM_TOTAL>>>(
        nullptr, hidh, hidl, wth + OW_TW2, wtl + OW_TW2, nullptr, nullptr,
        tb2, nullptr, nullptr, nullptr, msgh, msgl);
    // invc + node mask (needs cnt complete)
    prep_nodes<<<MN / 256, 256>>>(node_mask);
    // edge update layer1 (silu) -> hidden pair
    gemm_tc<0, false, true , true , false><<<ge, 256, SMEM_TOTAL>>>(
        nullptr, msgh, msgl, wth + OW_EW1, wtl + OW_EW1, nullptr, nullptr,
        eb1, nullptr, nullptr, nullptr, hidh, hidl);
    // edge_out = edge_feat + layer2 (fp32)
    gemm_tc<2, false, true , false, false><<<ge, 256, SMEM_TOTAL>>>(
        nullptr, hidh, hidl, wth + OW_EW2, wtl + OW_EW2, nullptr, nullptr,
        eb2, edge_feat, out + (size_t)MN * Dn, nullptr, nullptr, nullptr);
    // node layer1 on agg*invc (silu) -> hn pair
    gemm_tc<0, true , false, true , false><<<gn, 256, SMEM_TOTAL>>>(
        agg, nullptr, nullptr, wth + OW_NW1, wtl + OW_NW1, nullptr, nullptr,
        nb1, nullptr, nullptr, nullptr, hnh, hnl);
    // node = node_feat + layer2 * node_mask (fp32)
    gemm_tc<3, false, true , false, false><<<gn, 256, SMEM_TOTAL>>>(
        nullptr, hnh, hnl, wth + OW_NW2, wtl + OW_NW2, nullptr, nullptr,
        nb2, node_feat, node, nullptr, nullptr, nullptr);
    // layernorm (float4, 64 threads/row)
    ln_kernel<<<MN, 64>>>(node, gamma, beta, out);
}